// round 1
// baseline (speedup 1.0000x reference)
#include <cuda_runtime.h>
#include <cuda_bf16.h>
#include <math.h>

// ---------------- problem constants ----------------
#define HID   2048
#define NH    32
#define NKVH  8
#define HD    64
#define FF    8192
#define SEQ   2048
#define NB    2
#define ROWS  (NB * SEQ)          // 4096
#define EPS   1e-6f

// ---------------- scratch (device globals; no allocs allowed) ----------------
__device__ float g_hnorm[(size_t)ROWS * HID];
__device__ float g_q    [(size_t)ROWS * (NH * HD)];
__device__ float g_k    [(size_t)ROWS * (NKVH * HD)];
__device__ float g_v    [(size_t)ROWS * (NKVH * HD)];
__device__ float g_ctx  [(size_t)ROWS * (NH * HD)];
__device__ float g_res2 [(size_t)ROWS * HID];
__device__ float g_h2n  [(size_t)ROWS * HID];
__device__ float g_gate [(size_t)ROWS * FF];
__device__ float g_up   [(size_t)ROWS * FF];

// ---------------- RMSNorm ----------------
__global__ void rmsnorm_kernel(const float* __restrict__ x,
                               const float* __restrict__ w,
                               float* __restrict__ o, int cols)
{
    int row = blockIdx.x;
    const float* xr = x + (size_t)row * cols;
    float* orow = o + (size_t)row * cols;

    float ss = 0.f;
    int nvec = cols / 4;
    const float4* xv = (const float4*)xr;
    for (int c = threadIdx.x; c < nvec; c += blockDim.x) {
        float4 v = xv[c];
        ss += v.x * v.x + v.y * v.y + v.z * v.z + v.w * v.w;
    }
    // block reduce
    __shared__ float red[32];
    for (int off = 16; off > 0; off >>= 1) ss += __shfl_xor_sync(0xffffffffu, ss, off);
    int lane = threadIdx.x & 31, wid = threadIdx.x >> 5;
    if (lane == 0) red[wid] = ss;
    __syncthreads();
    int nwarp = blockDim.x >> 5;
    if (wid == 0) {
        float t = (lane < nwarp) ? red[lane] : 0.f;
        for (int off = 16; off > 0; off >>= 1) t += __shfl_xor_sync(0xffffffffu, t, off);
        if (lane == 0) red[0] = t;
    }
    __syncthreads();
    float inv = rsqrtf(red[0] / (float)cols + EPS);

    const float4* wv = (const float4*)w;
    float4* ov = (float4*)orow;
    for (int c = threadIdx.x; c < nvec; c += blockDim.x) {
        float4 v = xv[c];
        float4 ww = wv[c];
        float4 r;
        r.x = v.x * inv * ww.x; r.y = v.y * inv * ww.y;
        r.z = v.z * inv * ww.z; r.w = v.w * inv * ww.w;
        ov[c] = r;
    }
}

// ---------------- SGEMM: C[M,N] = A[M,K] @ B[K,N] (+ RES) ----------------
#define BM 128
#define BN 128
#define BKK 16
#define TM 8
#define TN 8

template<int EPI>  // 0: plain, 1: C = A@B + RES
__global__ void __launch_bounds__(256)
sgemm_kernel(const float* __restrict__ A, const float* __restrict__ B,
             const float* __restrict__ RES, float* __restrict__ C,
             int M, int N, int K)
{
    __shared__ float As[BKK][BM];
    __shared__ float Bs[BKK][BN];

    int tid = threadIdx.x;
    int bm = blockIdx.y, bn = blockIdx.x;
    int tx = tid & 15, ty = tid >> 4;

    const float* Ab = A + (size_t)bm * BM * K;
    const float* Bb = B + (size_t)bn * BN;

    float acc[TM][TN];
#pragma unroll
    for (int i = 0; i < TM; i++)
#pragma unroll
        for (int j = 0; j < TN; j++) acc[i][j] = 0.f;

    int nk = K / BKK;
    for (int bk = 0; bk < nk; bk++) {
        int kb = bk * BKK;
        // load A tile (128x16) transposed into As
#pragma unroll
        for (int t = 0; t < 2; t++) {
            int v = tid + t * 256;
            int r = v >> 2;
            int cc = (v & 3) * 4;
            float4 a4 = *(const float4*)(Ab + (size_t)r * K + kb + cc);
            As[cc + 0][r] = a4.x;
            As[cc + 1][r] = a4.y;
            As[cc + 2][r] = a4.z;
            As[cc + 3][r] = a4.w;
        }
        // load B tile (16x128)
#pragma unroll
        for (int t = 0; t < 2; t++) {
            int v = tid + t * 256;
            int r = v >> 5;
            int cc = (v & 31) * 4;
            *(float4*)&Bs[r][cc] = *(const float4*)(Bb + (size_t)(kb + r) * N + cc);
        }
        __syncthreads();

#pragma unroll
        for (int k = 0; k < BKK; k++) {
            float a[TM], b[TN];
#pragma unroll
            for (int i = 0; i < TM; i++) a[i] = As[k][ty * TM + i];
#pragma unroll
            for (int j = 0; j < TN; j++) b[j] = Bs[k][tx * TN + j];
#pragma unroll
            for (int i = 0; i < TM; i++)
#pragma unroll
                for (int j = 0; j < TN; j++) acc[i][j] += a[i] * b[j];
        }
        __syncthreads();
    }

    int row0 = bm * BM + ty * TM;
    int col0 = bn * BN + tx * TN;
#pragma unroll
    for (int i = 0; i < TM; i++) {
        size_t base = (size_t)(row0 + i) * N + col0;
#pragma unroll
        for (int j = 0; j < TN; j++) {
            float v = acc[i][j];
            if (EPI == 1) v += RES[base + j];
            C[base + j] = v;
        }
    }
}

// ---------------- RoPE (in-place on [row, h*64+d] layout) ----------------
__global__ void rope_kernel(float* __restrict__ x, int nheads)
{
    int row = blockIdx.x;          // 0..ROWS-1
    int s = row % SEQ;
    int t = threadIdx.x;           // nheads*32 threads
    int h = t >> 5, i = t & 31;
    float inv_freq = powf(10000.0f, -(float)(2 * i) / 64.0f);
    float ang = (float)s * inv_freq;
    float c, sn;
    __sincosf(ang, &sn, &c);
    float* p = x + (size_t)row * (nheads * HD) + h * HD;
    float x1 = p[i], x2 = p[i + 32];
    p[i]      = x1 * c - x2 * sn;
    p[i + 32] = x2 * c + x1 * sn;
}

// ---------------- flash-style causal attention ----------------
// grid: (SEQ/64, NH, NB), block 256. smem: Qs(64x65) Ks(64x65, reused for P) Vs(64x65)
__global__ void __launch_bounds__(256)
attn_kernel(const float* __restrict__ Q, const float* __restrict__ K,
            const float* __restrict__ V, float* __restrict__ O)
{
    extern __shared__ float sm[];
    float* Qs = sm;                 // 64*65
    float* Ks = sm + 64 * 65;       // 64*65 (also P)
    float* Vs = sm + 2 * 64 * 65;   // 64*65

    int qt = blockIdx.x, h = blockIdx.y, b = blockIdx.z;
    int kvh = h >> 2;
    int tid = threadIdx.x;
    int q = tid >> 2;      // 0..63
    int c = tid & 3;       // 0..3
    int d0 = c * 16;

    const float* Qb = Q + (size_t)b * SEQ * (NH * HD) + h * HD;
    const float* Kb = K + (size_t)b * SEQ * (NKVH * HD) + kvh * HD;
    const float* Vb = V + (size_t)b * SEQ * (NKVH * HD) + kvh * HD;
    int q0 = qt * 64;

    // load Q tile
    for (int v4 = tid; v4 < 64 * 16; v4 += 256) {
        int r = v4 >> 4, cc = (v4 & 15) * 4;
        float4 val = *(const float4*)(Qb + (size_t)(q0 + r) * (NH * HD) + cc);
        Qs[r * 65 + cc + 0] = val.x; Qs[r * 65 + cc + 1] = val.y;
        Qs[r * 65 + cc + 2] = val.z; Qs[r * 65 + cc + 3] = val.w;
    }

    float m = -1e30f, l = 0.f;
    float acc[16];
#pragma unroll
    for (int i = 0; i < 16; i++) acc[i] = 0.f;

    for (int kt = 0; kt <= qt; kt++) {
        int k0 = kt * 64;
        __syncthreads();  // protect Ks/Vs (P & V still read last iter)
        for (int v4 = tid; v4 < 64 * 16; v4 += 256) {
            int r = v4 >> 4, cc = (v4 & 15) * 4;
            float4 kv = *(const float4*)(Kb + (size_t)(k0 + r) * (NKVH * HD) + cc);
            Ks[r * 65 + cc + 0] = kv.x; Ks[r * 65 + cc + 1] = kv.y;
            Ks[r * 65 + cc + 2] = kv.z; Ks[r * 65 + cc + 3] = kv.w;
            float4 vv = *(const float4*)(Vb + (size_t)(k0 + r) * (NKVH * HD) + cc);
            Vs[r * 65 + cc + 0] = vv.x; Vs[r * 65 + cc + 1] = vv.y;
            Vs[r * 65 + cc + 2] = vv.z; Vs[r * 65 + cc + 3] = vv.w;
        }
        __syncthreads();

        // scores for this thread's 16 keys
        float sc[16];
#pragma unroll
        for (int kk = 0; kk < 16; kk++) {
            int k = c * 16 + kk;
            float dot = 0.f;
#pragma unroll
            for (int dd = 0; dd < 64; dd++) dot += Qs[q * 65 + dd] * Ks[k * 65 + dd];
            dot *= 0.125f;
            if (k0 + k > q0 + q) dot = -1e30f;
            sc[kk] = dot;
        }
        float tm = sc[0];
#pragma unroll
        for (int kk = 1; kk < 16; kk++) tm = fmaxf(tm, sc[kk]);
        tm = fmaxf(tm, __shfl_xor_sync(0xffffffffu, tm, 1));
        tm = fmaxf(tm, __shfl_xor_sync(0xffffffffu, tm, 2));
        float m_new = fmaxf(m, tm);
        float corr = __expf(m - m_new);
        float psum = 0.f;
#pragma unroll
        for (int kk = 0; kk < 16; kk++) {
            float p = __expf(sc[kk] - m_new);
            psum += p;
            sc[kk] = p;
        }
        psum += __shfl_xor_sync(0xffffffffu, psum, 1);
        psum += __shfl_xor_sync(0xffffffffu, psum, 2);
        l = l * corr + psum;
        m = m_new;
#pragma unroll
        for (int i = 0; i < 16; i++) acc[i] *= corr;

        __syncthreads();  // done reading Ks as K
        // write P into Ks region: P[q][k], pitch 65
#pragma unroll
        for (int kk = 0; kk < 16; kk++) Ks[q * 65 + c * 16 + kk] = sc[kk];
        __syncthreads();

        // acc += P @ V
#pragma unroll 4
        for (int k = 0; k < 64; k++) {
            float p = Ks[q * 65 + k];
#pragma unroll
            for (int i = 0; i < 16; i++) acc[i] += p * Vs[k * 65 + d0 + i];
        }
    }

    float inv = 1.f / l;
    float* orow = O + (size_t)(b * SEQ + q0 + q) * (NH * HD) + h * HD + d0;
#pragma unroll
    for (int i = 0; i < 16; i++) orow[i] = acc[i] * inv;
}

// ---------------- silu(gate) * up (in-place into gate) ----------------
__global__ void silu_mul_kernel(float* __restrict__ g, const float* __restrict__ u, size_t n4)
{
    size_t i = (size_t)blockIdx.x * blockDim.x + threadIdx.x;
    if (i >= n4) return;
    float4 gv = ((const float4*)g)[i];
    float4 uv = ((const float4*)u)[i];
    gv.x = gv.x / (1.f + __expf(-gv.x)) * uv.x;
    gv.y = gv.y / (1.f + __expf(-gv.y)) * uv.y;
    gv.z = gv.z / (1.f + __expf(-gv.z)) * uv.z;
    gv.w = gv.w / (1.f + __expf(-gv.w)) * uv.w;
    ((float4*)g)[i] = gv;
}

// ---------------- host launch ----------------
extern "C" void kernel_launch(void* const* d_in, const int* in_sizes, int n_in,
                              void* d_out, int out_size)
{
    const float* hidden  = (const float*)d_in[0];
    // d_in[1] attention_mask: exact causal -1e9, implemented analytically
    const float* norm1_w = (const float*)d_in[2];
    const float* wq      = (const float*)d_in[3];
    const float* wk      = (const float*)d_in[4];
    const float* wv      = (const float*)d_in[5];
    const float* wo      = (const float*)d_in[6];
    const float* norm2_w = (const float*)d_in[7];
    const float* w_gate  = (const float*)d_in[8];
    const float* w_up    = (const float*)d_in[9];
    const float* w_down  = (const float*)d_in[10];
    float* out = (float*)d_out;

    float *hnorm, *q, *k, *v, *ctx, *res2, *h2n, *gate, *up;
    cudaGetSymbolAddress((void**)&hnorm, g_hnorm);
    cudaGetSymbolAddress((void**)&q,     g_q);
    cudaGetSymbolAddress((void**)&k,     g_k);
    cudaGetSymbolAddress((void**)&v,     g_v);
    cudaGetSymbolAddress((void**)&ctx,   g_ctx);
    cudaGetSymbolAddress((void**)&res2,  g_res2);
    cudaGetSymbolAddress((void**)&h2n,   g_h2n);
    cudaGetSymbolAddress((void**)&gate,  g_gate);
    cudaGetSymbolAddress((void**)&up,    g_up);

    // attention kernel needs ~49.9 KB dynamic smem
    int attn_smem = 3 * 64 * 65 * (int)sizeof(float);
    cudaFuncSetAttribute(attn_kernel, cudaFuncAttributeMaxDynamicSharedMemorySize, attn_smem);

    // 1. rmsnorm1
    rmsnorm_kernel<<<ROWS, 256>>>(hidden, norm1_w, hnorm, HID);

    // 2-4. QKV projections
    {
        dim3 gq((NH * HD) / BN, ROWS / BM);
        sgemm_kernel<0><<<gq, 256>>>(hnorm, wq, nullptr, q, ROWS, NH * HD, HID);
        dim3 gk((NKVH * HD) / BN, ROWS / BM);
        sgemm_kernel<0><<<gk, 256>>>(hnorm, wk, nullptr, k, ROWS, NKVH * HD, HID);
        sgemm_kernel<0><<<gk, 256>>>(hnorm, wv, nullptr, v, ROWS, NKVH * HD, HID);
    }

    // 5. RoPE
    rope_kernel<<<ROWS, NH * 32>>>(q, NH);
    rope_kernel<<<ROWS, NKVH * 32>>>(k, NKVH);

    // 6. attention
    {
        dim3 g(SEQ / 64, NH, NB);
        attn_kernel<<<g, 256, attn_smem>>>(q, k, v, ctx);
    }

    // 7. output projection + residual
    {
        dim3 g(HID / BN, ROWS / BM);
        sgemm_kernel<1><<<g, 256>>>(ctx, wo, hidden, res2, ROWS, HID, NH * HD);
    }

    // 8. rmsnorm2
    rmsnorm_kernel<<<ROWS, 256>>>(res2, norm2_w, h2n, HID);

    // 9-10. gate / up
    {
        dim3 g(FF / BN, ROWS / BM);
        sgemm_kernel<0><<<g, 256>>>(h2n, w_gate, nullptr, gate, ROWS, FF, HID);
        sgemm_kernel<0><<<g, 256>>>(h2n, w_up, nullptr, up, ROWS, FF, HID);
    }

    // 11. silu(gate) * up
    {
        size_t n4 = (size_t)ROWS * FF / 4;
        int thr = 256;
        int blk = (int)((n4 + thr - 1) / thr);
        silu_mul_kernel<<<blk, thr>>>(gate, up, n4);
    }

    // 12. down projection + residual -> out
    {
        dim3 g(HID / BN, ROWS / BM);
        sgemm_kernel<1><<<g, 256>>>(gate, w_down, res2, out, ROWS, HID, FF);
    }
}

// round 3
// speedup vs baseline: 1.7005x; 1.7005x over previous
#include <cuda_runtime.h>
#include <cuda_bf16.h>
#include <math.h>
#include <stdint.h>

// ---------------- problem constants ----------------
#define HID   2048
#define NH    32
#define NKVH  8
#define HD    64
#define FF    8192
#define SEQ   2048
#define NB    2
#define ROWS  4096
#define EPS   1e-6f
#define MEG   (1024*1024)

// ---------------- scratch (device globals; no allocs allowed) ----------------
__device__ float g_q   [(size_t)ROWS * 2048];
__device__ float g_k   [(size_t)ROWS * 512];
__device__ float g_v   [(size_t)ROWS * 512];
__device__ float g_ctx [(size_t)ROWS * 2048];
__device__ float g_res2[(size_t)ROWS * 2048];
__device__ float g_gate[(size_t)ROWS * FF];
__device__ float g_up  [(size_t)ROWS * FF];

// bf16 hi/lo split operands (plain row-major)
__device__ __nv_bfloat16 g_a_hi[(size_t)ROWS * FF];
__device__ __nv_bfloat16 g_a_lo[(size_t)ROWS * FF];
__device__ __nv_bfloat16 g_w_hi[(size_t)58 * MEG];
__device__ __nv_bfloat16 g_w_lo[(size_t)58 * MEG];

// ---------------- helpers ----------------
__device__ __forceinline__ uint32_t smem_u32(const void* p) {
    uint32_t a;
    asm("{ .reg .u64 t; cvta.to.shared.u64 t, %1; cvt.u32.u64 %0, t; }" : "=r"(a) : "l"(p));
    return a;
}

__device__ __forceinline__ void cpa16(uint32_t dst, const void* src) {
    asm volatile("cp.async.cg.shared.global [%0], [%1], 16;" :: "r"(dst), "l"(src));
}
__device__ __forceinline__ void cpa_commit() {
    asm volatile("cp.async.commit_group;" ::: "memory");
}

__device__ __forceinline__ void ldsm4(uint32_t* r, uint32_t addr) {
    asm volatile("ldmatrix.sync.aligned.m8n8.x4.shared.b16 {%0,%1,%2,%3}, [%4];"
        : "=r"(r[0]), "=r"(r[1]), "=r"(r[2]), "=r"(r[3]) : "r"(addr));
}

__device__ __forceinline__ void mma16816(float* c, const uint32_t* a, const uint32_t* b) {
    asm volatile("mma.sync.aligned.m16n8k16.row.col.f32.bf16.bf16.f32 "
        "{%0,%1,%2,%3}, {%4,%5,%6,%7}, {%8,%9}, {%0,%1,%2,%3};"
        : "+f"(c[0]), "+f"(c[1]), "+f"(c[2]), "+f"(c[3])
        : "r"(a[0]), "r"(a[1]), "r"(a[2]), "r"(a[3]), "r"(b[0]), "r"(b[1]));
}

__device__ __forceinline__ void split2(float x0, float x1, __nv_bfloat162* hi, __nv_bfloat162* lo) {
    __nv_bfloat16 h0 = __float2bfloat16(x0);
    __nv_bfloat16 h1 = __float2bfloat16(x1);
    __nv_bfloat16 l0 = __float2bfloat16(x0 - __bfloat162float(h0));
    __nv_bfloat16 l1 = __float2bfloat16(x1 - __bfloat162float(h1));
    hi->x = h0; hi->y = h1; lo->x = l0; lo->y = l1;
}

// ---------------- converters ----------------
// W [K,N] fp32 -> Wt [N,K] bf16 hi/lo
__global__ void convT_kernel(const float* __restrict__ W,
                             __nv_bfloat16* __restrict__ hiT,
                             __nv_bfloat16* __restrict__ loT, int K, int N)
{
    __shared__ float t[32][33];
    int n0 = blockIdx.x * 32, k0 = blockIdx.y * 32;
    int tx = threadIdx.x & 31, ty = threadIdx.x >> 5;
    for (int ky = ty; ky < 32; ky += 8)
        t[ky][tx] = W[(size_t)(k0 + ky) * N + n0 + tx];
    __syncthreads();
    for (int ny = ty; ny < 32; ny += 8) {
        float x = t[tx][ny];
        __nv_bfloat16 h = __float2bfloat16(x);
        __nv_bfloat16 l = __float2bfloat16(x - __bfloat162float(h));
        size_t o = (size_t)(n0 + ny) * K + k0 + tx;
        hiT[o] = h; loT[o] = l;
    }
}

// plain elementwise split (x fp32, pairs)
__global__ void convert_split_kernel(const float* __restrict__ x,
                                     __nv_bfloat16* __restrict__ hi,
                                     __nv_bfloat16* __restrict__ lo, size_t npairs)
{
    size_t i = (size_t)blockIdx.x * blockDim.x + threadIdx.x;
    if (i >= npairs) return;
    float2 xv = ((const float2*)x)[i];
    __nv_bfloat162 h, l;
    split2(xv.x, xv.y, &h, &l);
    ((__nv_bfloat162*)hi)[i] = h;
    ((__nv_bfloat162*)lo)[i] = l;
}

// RMSNorm -> split (plain [row,K])
__global__ void rmsnorm_split_kernel(const float* __restrict__ x,
                                     const float* __restrict__ w,
                                     __nv_bfloat16* __restrict__ hi,
                                     __nv_bfloat16* __restrict__ lo, int K)
{
    int row = blockIdx.x;
    const float* xr = x + (size_t)row * K;
    float ss = 0.f;
    int nvec = K / 4;
    const float4* xv = (const float4*)xr;
    for (int c = threadIdx.x; c < nvec; c += blockDim.x) {
        float4 v = xv[c];
        ss += v.x * v.x + v.y * v.y + v.z * v.z + v.w * v.w;
    }
    __shared__ float red[32];
    for (int off = 16; off > 0; off >>= 1) ss += __shfl_xor_sync(0xffffffffu, ss, off);
    int lane = threadIdx.x & 31, wid = threadIdx.x >> 5;
    if (lane == 0) red[wid] = ss;
    __syncthreads();
    int nwarp = blockDim.x >> 5;
    if (wid == 0) {
        float t = (lane < nwarp) ? red[lane] : 0.f;
        for (int off = 16; off > 0; off >>= 1) t += __shfl_xor_sync(0xffffffffu, t, off);
        if (lane == 0) red[0] = t;
    }
    __syncthreads();
    float inv = rsqrtf(red[0] / (float)K + EPS);

    for (int c = threadIdx.x; c < K / 2; c += blockDim.x) {
        int k = 2 * c;
        float x0 = xr[k] * inv * w[k];
        float x1 = xr[k + 1] * inv * w[k + 1];
        __nv_bfloat162 h, l;
        split2(x0, x1, &h, &l);
        ((__nv_bfloat162*)(hi + (size_t)row * K))[c] = h;
        ((__nv_bfloat162*)(lo + (size_t)row * K))[c] = l;
    }
}

// silu(gate)*up -> split
__global__ void silu_mul_split_kernel(const float* __restrict__ g,
                                      const float* __restrict__ u,
                                      __nv_bfloat16* __restrict__ hi,
                                      __nv_bfloat16* __restrict__ lo, size_t npairs)
{
    size_t i = (size_t)blockIdx.x * blockDim.x + threadIdx.x;
    if (i >= npairs) return;
    float2 gv = ((const float2*)g)[i];
    float2 uv = ((const float2*)u)[i];
    float x0 = gv.x / (1.f + __expf(-gv.x)) * uv.x;
    float x1 = gv.y / (1.f + __expf(-gv.y)) * uv.y;
    __nv_bfloat162 h, l;
    split2(x0, x1, &h, &l);
    ((__nv_bfloat162*)hi)[i] = h;
    ((__nv_bfloat162*)lo)[i] = l;
}

// ---------------- HMMA GEMM: C[M,N] = A@Wt^T (+RES), 3-term bf16 split ----------------
// A [M,K] bf16 (hi/lo), B = Wt [N,K] bf16 (hi/lo). CTA 128x128, BK=32, 3-stage cp.async.
#define BK 32
#define APITCH 80            // bytes per row in smem (40 bf16, padded)
#define MAT_SZ 10240         // 128 rows * 80B
#define STG_SZ 40960         // Ah, Al, Bh, Bl
#define GSMEM  (3 * STG_SZ)  // 122880

template<int EPI>
__global__ void __launch_bounds__(256)
hmma_gemm_kernel(const __nv_bfloat16* __restrict__ Ah, const __nv_bfloat16* __restrict__ Al,
                 const __nv_bfloat16* __restrict__ Bh, const __nv_bfloat16* __restrict__ Bl,
                 const float* __restrict__ RES, float* __restrict__ C, int N, int K)
{
    extern __shared__ char sm[];
    uint32_t smb = smem_u32(sm);
    int tid = threadIdx.x, lane = tid & 31, wid = tid >> 5;
    int wm = wid & 3, wn = wid >> 2;          // warp tile: 32 (M) x 64 (N)
    int bm = blockIdx.y, bn = blockIdx.x;
    int NKT = K / BK;

    const __nv_bfloat16* gAh = Ah + (size_t)bm * 128 * K;
    const __nv_bfloat16* gAl = Al + (size_t)bm * 128 * K;
    const __nv_bfloat16* gBh = Bh + (size_t)bn * 128 * K;
    const __nv_bfloat16* gBl = Bl + (size_t)bn * 128 * K;

    int rbase = tid >> 2;      // 0..63
    int ch = tid & 3;          // 16B chunk within 64B row

    // issue loads for stage st covering k-tile kt
    auto issue = [&](int st, int kt) {
        uint32_t base = smb + st * STG_SZ;
        int koff = kt * BK + ch * 8;
#pragma unroll
        for (int it = 0; it < 8; it++) {
            int mat = it >> 1;
            int r = rbase + (it & 1) * 64;
            const __nv_bfloat16* g = (mat == 0) ? gAh : (mat == 1) ? gAl : (mat == 2) ? gBh : gBl;
            cpa16(base + mat * MAT_SZ + r * APITCH + ch * 16,
                  g + (size_t)r * K + koff);
        }
        cpa_commit();
    };

    float acc[2][8][4];
#pragma unroll
    for (int s = 0; s < 2; s++)
#pragma unroll
        for (int t = 0; t < 8; t++)
#pragma unroll
            for (int j = 0; j < 4; j++) acc[s][t][j] = 0.f;

    issue(0, 0);
    issue(1, 1);

    // ldmatrix address components (fixed per thread)
    int a_row = wm * 32 + (lane & 15);
    int a_kb  = ((lane >> 4) << 3) * 2;             // bytes
    int b_ro  = ((lane >> 4) << 3) + (lane & 7);
    int b_kb  = (((lane >> 3) & 1) << 3) * 2;       // bytes

    for (int kt = 0; kt < NKT; kt++) {
        int st = kt % 3;
        if (kt + 2 < NKT) issue((kt + 2) % 3, kt + 2);
        else cpa_commit();
        asm volatile("cp.async.wait_group 2;" ::: "memory");
        __syncthreads();

        uint32_t sAh = smb + st * STG_SZ;
        uint32_t sAl = sAh + MAT_SZ;
        uint32_t sBh = sAl + MAT_SZ;
        uint32_t sBl = sBh + MAT_SZ;

#pragma unroll
        for (int ks = 0; ks < 2; ks++) {
            int kB = ks * 32;   // 16 bf16 = 32 bytes
            uint32_t ah[2][4], al[2][4];
            ldsm4(ah[0], sAh + (a_row)      * APITCH + kB + a_kb);
            ldsm4(ah[1], sAh + (a_row + 16) * APITCH + kB + a_kb);
            ldsm4(al[0], sAl + (a_row)      * APITCH + kB + a_kb);
            ldsm4(al[1], sAl + (a_row + 16) * APITCH + kB + a_kb);
            uint32_t bh[4][4], bl[4][4];
#pragma unroll
            for (int gi = 0; gi < 4; gi++) {
                int brow = wn * 64 + gi * 16 + b_ro;
                ldsm4(bh[gi], sBh + brow * APITCH + kB + b_kb);
                ldsm4(bl[gi], sBl + brow * APITCH + kB + b_kb);
            }
#pragma unroll
            for (int sub = 0; sub < 2; sub++)
#pragma unroll
                for (int t = 0; t < 8; t++) {
                    const uint32_t* bhp = &bh[t >> 1][(t & 1) * 2];
                    const uint32_t* blp = &bl[t >> 1][(t & 1) * 2];
                    mma16816(acc[sub][t], ah[sub], bhp);
                    mma16816(acc[sub][t], ah[sub], blp);
                    mma16816(acc[sub][t], al[sub], bhp);
                }
        }
        __syncthreads();
    }

    // epilogue
#pragma unroll
    for (int sub = 0; sub < 2; sub++) {
        int row0 = bm * 128 + wm * 32 + sub * 16 + (lane >> 2);
#pragma unroll
        for (int t = 0; t < 8; t++) {
            int col = bn * 128 + wn * 64 + t * 8 + (lane & 3) * 2;
            size_t o0 = (size_t)row0 * N + col;
            size_t o1 = o0 + (size_t)8 * N;
            float2 v0 = make_float2(acc[sub][t][0], acc[sub][t][1]);
            float2 v1 = make_float2(acc[sub][t][2], acc[sub][t][3]);
            if (EPI == 1) {
                float2 r0 = *(const float2*)(RES + o0);
                float2 r1 = *(const float2*)(RES + o1);
                v0.x += r0.x; v0.y += r0.y;
                v1.x += r1.x; v1.y += r1.y;
            }
            *(float2*)(C + o0) = v0;
            *(float2*)(C + o1) = v1;
        }
    }
}

// ---------------- RoPE ----------------
__global__ void rope_kernel(float* __restrict__ x, int nheads)
{
    int row = blockIdx.x;
    int s = row % SEQ;
    int t = threadIdx.x;
    int h = t >> 5, i = t & 31;
    float inv_freq = powf(10000.0f, -(float)(2 * i) / 64.0f);
    float ang = (float)s * inv_freq;
    float c, sn;
    __sincosf(ang, &sn, &c);
    float* p = x + (size_t)row * (nheads * HD) + h * HD;
    float x1 = p[i], x2 = p[i + 32];
    p[i]      = x1 * c - x2 * sn;
    p[i + 32] = x2 * c + x1 * sn;
}

// ---------------- flash-style causal attention (fp32) ----------------
__global__ void __launch_bounds__(256)
attn_kernel(const float* __restrict__ Q, const float* __restrict__ K,
            const float* __restrict__ V, float* __restrict__ O)
{
    extern __shared__ float smf[];
    float* Qs = smf;
    float* Ks = smf + 64 * 65;
    float* Vs = smf + 2 * 64 * 65;

    int qt = blockIdx.x, h = blockIdx.y, b = blockIdx.z;
    int kvh = h >> 2;
    int tid = threadIdx.x;
    int q = tid >> 2;
    int c = tid & 3;
    int d0 = c * 16;

    const float* Qb = Q + (size_t)b * SEQ * (NH * HD) + h * HD;
    const float* Kb = K + (size_t)b * SEQ * (NKVH * HD) + kvh * HD;
    const float* Vb = V + (size_t)b * SEQ * (NKVH * HD) + kvh * HD;
    int q0 = qt * 64;

    for (int v4 = tid; v4 < 64 * 16; v4 += 256) {
        int r = v4 >> 4, cc = (v4 & 15) * 4;
        float4 val = *(const float4*)(Qb + (size_t)(q0 + r) * (NH * HD) + cc);
        Qs[r * 65 + cc + 0] = val.x; Qs[r * 65 + cc + 1] = val.y;
        Qs[r * 65 + cc + 2] = val.z; Qs[r * 65 + cc + 3] = val.w;
    }

    float m = -1e30f, l = 0.f;
    float acc[16];
#pragma unroll
    for (int i = 0; i < 16; i++) acc[i] = 0.f;

    for (int kt = 0; kt <= qt; kt++) {
        int k0 = kt * 64;
        __syncthreads();
        for (int v4 = tid; v4 < 64 * 16; v4 += 256) {
            int r = v4 >> 4, cc = (v4 & 15) * 4;
            float4 kv = *(const float4*)(Kb + (size_t)(k0 + r) * (NKVH * HD) + cc);
            Ks[r * 65 + cc + 0] = kv.x; Ks[r * 65 + cc + 1] = kv.y;
            Ks[r * 65 + cc + 2] = kv.z; Ks[r * 65 + cc + 3] = kv.w;
            float4 vv = *(const float4*)(Vb + (size_t)(k0 + r) * (NKVH * HD) + cc);
            Vs[r * 65 + cc + 0] = vv.x; Vs[r * 65 + cc + 1] = vv.y;
            Vs[r * 65 + cc + 2] = vv.z; Vs[r * 65 + cc + 3] = vv.w;
        }
        __syncthreads();

        float sc[16];
#pragma unroll
        for (int kk = 0; kk < 16; kk++) {
            int k = c * 16 + kk;
            float dot = 0.f;
#pragma unroll
            for (int dd = 0; dd < 64; dd++) dot += Qs[q * 65 + dd] * Ks[k * 65 + dd];
            dot *= 0.125f;
            if (k0 + k > q0 + q) dot = -1e30f;
            sc[kk] = dot;
        }
        float tm = sc[0];
#pragma unroll
        for (int kk = 1; kk < 16; kk++) tm = fmaxf(tm, sc[kk]);
        tm = fmaxf(tm, __shfl_xor_sync(0xffffffffu, tm, 1));
        tm = fmaxf(tm, __shfl_xor_sync(0xffffffffu, tm, 2));
        float m_new = fmaxf(m, tm);
        float corr = __expf(m - m_new);
        float psum = 0.f;
#pragma unroll
        for (int kk = 0; kk < 16; kk++) {
            float p = __expf(sc[kk] - m_new);
            psum += p;
            sc[kk] = p;
        }
        psum += __shfl_xor_sync(0xffffffffu, psum, 1);
        psum += __shfl_xor_sync(0xffffffffu, psum, 2);
        l = l * corr + psum;
        m = m_new;
#pragma unroll
        for (int i = 0; i < 16; i++) acc[i] *= corr;

        __syncthreads();
#pragma unroll
        for (int kk = 0; kk < 16; kk++) Ks[q * 65 + c * 16 + kk] = sc[kk];
        __syncthreads();

#pragma unroll 4
        for (int k = 0; k < 64; k++) {
            float p = Ks[q * 65 + k];
#pragma unroll
            for (int i = 0; i < 16; i++) acc[i] += p * Vs[k * 65 + d0 + i];
        }
    }

    float inv = 1.f / l;
    float* orow = O + (size_t)(b * SEQ + q0 + q) * (NH * HD) + h * HD + d0;
#pragma unroll
    for (int i = 0; i < 16; i++) orow[i] = acc[i] * inv;
}

// ---------------- host launch ----------------
extern "C" void kernel_launch(void* const* d_in, const int* in_sizes, int n_in,
                              void* d_out, int out_size)
{
    const float* hidden  = (const float*)d_in[0];
    const float* norm1_w = (const float*)d_in[2];
    const float* wq      = (const float*)d_in[3];
    const float* wk      = (const float*)d_in[4];
    const float* wv      = (const float*)d_in[5];
    const float* wo      = (const float*)d_in[6];
    const float* norm2_w = (const float*)d_in[7];
    const float* w_gate  = (const float*)d_in[8];
    const float* w_up    = (const float*)d_in[9];
    const float* w_down  = (const float*)d_in[10];
    float* out = (float*)d_out;

    float *q, *k, *v, *ctx, *res2, *gate, *up;
    __nv_bfloat16 *a_hi, *a_lo, *w_hi, *w_lo;
    cudaGetSymbolAddress((void**)&q,    g_q);
    cudaGetSymbolAddress((void**)&k,    g_k);
    cudaGetSymbolAddress((void**)&v,    g_v);
    cudaGetSymbolAddress((void**)&ctx,  g_ctx);
    cudaGetSymbolAddress((void**)&res2, g_res2);
    cudaGetSymbolAddress((void**)&gate, g_gate);
    cudaGetSymbolAddress((void**)&up,   g_up);
    cudaGetSymbolAddress((void**)&a_hi, g_a_hi);
    cudaGetSymbolAddress((void**)&a_lo, g_a_lo);
    cudaGetSymbolAddress((void**)&w_hi, g_w_hi);
    cudaGetSymbolAddress((void**)&w_lo, g_w_lo);

    // weight pool offsets (elements)
    const size_t OWQ = 0;
    const size_t OWK = 4ull * MEG;
    const size_t OWV = 5ull * MEG;
    const size_t OWO = 6ull * MEG;
    const size_t OWG = 10ull * MEG;
    const size_t OWU = 26ull * MEG;
    const size_t OWD = 42ull * MEG;

    cudaFuncSetAttribute(hmma_gemm_kernel<0>, cudaFuncAttributeMaxDynamicSharedMemorySize, GSMEM);
    cudaFuncSetAttribute(hmma_gemm_kernel<1>, cudaFuncAttributeMaxDynamicSharedMemorySize, GSMEM);
    int attn_smem = 3 * 64 * 65 * (int)sizeof(float);
    cudaFuncSetAttribute(attn_kernel, cudaFuncAttributeMaxDynamicSharedMemorySize, attn_smem);

    // ---- weight transpose + split ----
    convT_kernel<<<dim3(2048 / 32, 2048 / 32), 256>>>(wq,     w_hi + OWQ, w_lo + OWQ, 2048, 2048);
    convT_kernel<<<dim3(512  / 32, 2048 / 32), 256>>>(wk,     w_hi + OWK, w_lo + OWK, 2048, 512);
    convT_kernel<<<dim3(512  / 32, 2048 / 32), 256>>>(wv,     w_hi + OWV, w_lo + OWV, 2048, 512);
    convT_kernel<<<dim3(2048 / 32, 2048 / 32), 256>>>(wo,     w_hi + OWO, w_lo + OWO, 2048, 2048);
    convT_kernel<<<dim3(8192 / 32, 2048 / 32), 256>>>(w_gate, w_hi + OWG, w_lo + OWG, 2048, 8192);
    convT_kernel<<<dim3(8192 / 32, 2048 / 32), 256>>>(w_up,   w_hi + OWU, w_lo + OWU, 2048, 8192);
    convT_kernel<<<dim3(2048 / 32, 8192 / 32), 256>>>(w_down, w_hi + OWD, w_lo + OWD, 8192, 2048);

    // ---- 1. rmsnorm1 -> split ----
    rmsnorm_split_kernel<<<ROWS, 256>>>(hidden, norm1_w, a_hi, a_lo, HID);

    // ---- 2-4. QKV ----
    hmma_gemm_kernel<0><<<dim3(2048 / 128, ROWS / 128), 256, GSMEM>>>(
        a_hi, a_lo, w_hi + OWQ, w_lo + OWQ, nullptr, q, 2048, 2048);
    hmma_gemm_kernel<0><<<dim3(512 / 128, ROWS / 128), 256, GSMEM>>>(
        a_hi, a_lo, w_hi + OWK, w_lo + OWK, nullptr, k, 512, 2048);
    hmma_gemm_kernel<0><<<dim3(512 / 128, ROWS / 128), 256, GSMEM>>>(
        a_hi, a_lo, w_hi + OWV, w_lo + OWV, nullptr, v, 512, 2048);

    // ---- 5. RoPE ----
    rope_kernel<<<ROWS, NH * 32>>>(q, NH);
    rope_kernel<<<ROWS, NKVH * 32>>>(k, NKVH);

    // ---- 6. attention ----
    attn_kernel<<<dim3(SEQ / 64, NH, NB), 256, attn_smem>>>(q, k, v, ctx);

    // ---- 7. ctx -> split, output projection + residual ----
    convert_split_kernel<<<(int)(((size_t)ROWS * 2048 / 2 + 255) / 256), 256>>>(
        ctx, a_hi, a_lo, (size_t)ROWS * 2048 / 2);
    hmma_gemm_kernel<1><<<dim3(2048 / 128, ROWS / 128), 256, GSMEM>>>(
        a_hi, a_lo, w_hi + OWO, w_lo + OWO, hidden, res2, 2048, 2048);

    // ---- 8. rmsnorm2 -> split ----
    rmsnorm_split_kernel<<<ROWS, 256>>>(res2, norm2_w, a_hi, a_lo, HID);

    // ---- 9-10. gate / up ----
    hmma_gemm_kernel<0><<<dim3(FF / 128, ROWS / 128), 256, GSMEM>>>(
        a_hi, a_lo, w_hi + OWG, w_lo + OWG, nullptr, gate, FF, 2048);
    hmma_gemm_kernel<0><<<dim3(FF / 128, ROWS / 128), 256, GSMEM>>>(
        a_hi, a_lo, w_hi + OWU, w_lo + OWU, nullptr, up, FF, 2048);

    // ---- 11. silu(gate)*up -> split ----
    {
        size_t npairs = (size_t)ROWS * FF / 2;
        silu_mul_split_kernel<<<(int)((npairs + 255) / 256), 256>>>(gate, up, a_hi, a_lo, npairs);
    }

    // ---- 12. down projection + residual -> out ----
    hmma_gemm_kernel<1><<<dim3(2048 / 128, ROWS / 128), 256, GSMEM>>>(
        a_hi, a_lo, w_hi + OWD, w_lo + OWD, res2, out, 2048, 8192);
}

// round 5
// speedup vs baseline: 2.9145x; 1.7139x over previous
#include <cuda_runtime.h>
#include <cuda_bf16.h>
#include <math.h>
#include <stdint.h>

// ---------------- problem constants ----------------
#define HID   2048
#define NH    32
#define NKVH  8
#define HD    64
#define FF    8192
#define SEQ   2048
#define NB    2
#define ROWS  4096
#define EPS   1e-6f
#define MEG   (1024*1024)
#define L2E   1.4426950408889634f

// ---------------- scratch (device globals; no allocs allowed) ----------------
__device__ float g_q   [(size_t)ROWS * 2048];
__device__ float g_k   [(size_t)ROWS * 512];
__device__ float g_v   [(size_t)ROWS * 512];
__device__ float g_ctx [(size_t)ROWS * 2048];
__device__ float g_res2[(size_t)ROWS * 2048];
__device__ float g_gate[(size_t)ROWS * FF];
__device__ float g_up  [(size_t)ROWS * FF];

// bf16 hi/lo split operands (plain row-major)
__device__ __nv_bfloat16 g_a_hi[(size_t)ROWS * FF];
__device__ __nv_bfloat16 g_a_lo[(size_t)ROWS * FF];
__device__ __nv_bfloat16 g_w_hi[(size_t)58 * MEG];
__device__ __nv_bfloat16 g_w_lo[(size_t)58 * MEG];

// attention bf16 split operands
__device__ __nv_bfloat16 g_qh[(size_t)ROWS * 2048];
__device__ __nv_bfloat16 g_ql[(size_t)ROWS * 2048];
__device__ __nv_bfloat16 g_kh[(size_t)ROWS * 512];
__device__ __nv_bfloat16 g_kl[(size_t)ROWS * 512];
__device__ __nv_bfloat16 g_vth[(size_t)ROWS * 512];
__device__ __nv_bfloat16 g_vtl[(size_t)ROWS * 512];

// ---------------- helpers ----------------
__device__ __forceinline__ uint32_t smem_u32(const void* p) {
    uint32_t a;
    asm("{ .reg .u64 t; cvta.to.shared.u64 t, %1; cvt.u32.u64 %0, t; }" : "=r"(a) : "l"(p));
    return a;
}

__device__ __forceinline__ void cpa16(uint32_t dst, const void* src) {
    asm volatile("cp.async.cg.shared.global [%0], [%1], 16;" :: "r"(dst), "l"(src));
}
__device__ __forceinline__ void cpa_commit() {
    asm volatile("cp.async.commit_group;" ::: "memory");
}

__device__ __forceinline__ void ldsm4(uint32_t* r, uint32_t addr) {
    asm volatile("ldmatrix.sync.aligned.m8n8.x4.shared.b16 {%0,%1,%2,%3}, [%4];"
        : "=r"(r[0]), "=r"(r[1]), "=r"(r[2]), "=r"(r[3]) : "r"(addr));
}

__device__ __forceinline__ void mma16816(float* c, const uint32_t* a, const uint32_t* b) {
    asm volatile("mma.sync.aligned.m16n8k16.row.col.f32.bf16.bf16.f32 "
        "{%0,%1,%2,%3}, {%4,%5,%6,%7}, {%8,%9}, {%0,%1,%2,%3};"
        : "+f"(c[0]), "+f"(c[1]), "+f"(c[2]), "+f"(c[3])
        : "r"(a[0]), "r"(a[1]), "r"(a[2]), "r"(a[3]), "r"(b[0]), "r"(b[1]));
}

__device__ __forceinline__ void split2(float x0, float x1, __nv_bfloat162* hi, __nv_bfloat162* lo) {
    __nv_bfloat16 h0 = __float2bfloat16(x0);
    __nv_bfloat16 h1 = __float2bfloat16(x1);
    __nv_bfloat16 l0 = __float2bfloat16(x0 - __bfloat162float(h0));
    __nv_bfloat16 l1 = __float2bfloat16(x1 - __bfloat162float(h1));
    hi->x = h0; hi->y = h1; lo->x = l0; lo->y = l1;
}

// FMA-only exp2 (z <= 0), |rel err| ~2e-6
__device__ __forceinline__ float fexp2(float z) {
    z = fmaxf(z, -126.f);
    float sh = z + 12582912.f;       // round to nearest int (magic)
    float zi = sh - 12582912.f;
    float f = z - zi;
    float p = 0.0013333558f;
    p = p * f + 0.0096181291f;
    p = p * f + 0.0555041087f;
    p = p * f + 0.2402265070f;
    p = p * f + 0.6931471806f;
    p = p * f + 1.0f;
    int ei = __float_as_int(sh) - 0x4B400000;
    return p * __int_as_float((ei + 127) << 23);
}

// ---------------- converters ----------------
__global__ void convT_kernel(const float* __restrict__ W,
                             __nv_bfloat16* __restrict__ hiT,
                             __nv_bfloat16* __restrict__ loT, int K, int N)
{
    __shared__ float t[32][33];
    int n0 = blockIdx.x * 32, k0 = blockIdx.y * 32;
    int tx = threadIdx.x & 31, ty = threadIdx.x >> 5;
    for (int ky = ty; ky < 32; ky += 8)
        t[ky][tx] = W[(size_t)(k0 + ky) * N + n0 + tx];
    __syncthreads();
    for (int ny = ty; ny < 32; ny += 8) {
        float x = t[tx][ny];
        __nv_bfloat16 h = __float2bfloat16(x);
        __nv_bfloat16 l = __float2bfloat16(x - __bfloat162float(h));
        size_t o = (size_t)(n0 + ny) * K + k0 + tx;
        hiT[o] = h; loT[o] = l;
    }
}

__global__ void convert_split_kernel(const float* __restrict__ x,
                                     __nv_bfloat16* __restrict__ hi,
                                     __nv_bfloat16* __restrict__ lo, size_t npairs)
{
    size_t i = (size_t)blockIdx.x * blockDim.x + threadIdx.x;
    if (i >= npairs) return;
    float2 xv = ((const float2*)x)[i];
    __nv_bfloat162 h, l;
    split2(xv.x, xv.y, &h, &l);
    ((__nv_bfloat162*)hi)[i] = h;
    ((__nv_bfloat162*)lo)[i] = l;
}

__global__ void rmsnorm_split_kernel(const float* __restrict__ x,
                                     const float* __restrict__ w,
                                     __nv_bfloat16* __restrict__ hi,
                                     __nv_bfloat16* __restrict__ lo, int K)
{
    int row = blockIdx.x;
    const float* xr = x + (size_t)row * K;
    float ss = 0.f;
    int nvec = K / 4;
    const float4* xv = (const float4*)xr;
    for (int c = threadIdx.x; c < nvec; c += blockDim.x) {
        float4 v = xv[c];
        ss += v.x * v.x + v.y * v.y + v.z * v.z + v.w * v.w;
    }
    __shared__ float red[32];
    for (int off = 16; off > 0; off >>= 1) ss += __shfl_xor_sync(0xffffffffu, ss, off);
    int lane = threadIdx.x & 31, wid = threadIdx.x >> 5;
    if (lane == 0) red[wid] = ss;
    __syncthreads();
    int nwarp = blockDim.x >> 5;
    if (wid == 0) {
        float t = (lane < nwarp) ? red[lane] : 0.f;
        for (int off = 16; off > 0; off >>= 1) t += __shfl_xor_sync(0xffffffffu, t, off);
        if (lane == 0) red[0] = t;
    }
    __syncthreads();
    float inv = rsqrtf(red[0] / (float)K + EPS);

    for (int c = threadIdx.x; c < K / 2; c += blockDim.x) {
        int k = 2 * c;
        float x0 = xr[k] * inv * w[k];
        float x1 = xr[k + 1] * inv * w[k + 1];
        __nv_bfloat162 h, l;
        split2(x0, x1, &h, &l);
        ((__nv_bfloat162*)(hi + (size_t)row * K))[c] = h;
        ((__nv_bfloat162*)(lo + (size_t)row * K))[c] = l;
    }
}

__global__ void silu_mul_split_kernel(const float* __restrict__ g,
                                      const float* __restrict__ u,
                                      __nv_bfloat16* __restrict__ hi,
                                      __nv_bfloat16* __restrict__ lo, size_t npairs)
{
    size_t i = (size_t)blockIdx.x * blockDim.x + threadIdx.x;
    if (i >= npairs) return;
    float2 gv = ((const float2*)g)[i];
    float2 uv = ((const float2*)u)[i];
    float x0 = gv.x / (1.f + __expf(-gv.x)) * uv.x;
    float x1 = gv.y / (1.f + __expf(-gv.y)) * uv.y;
    __nv_bfloat162 h, l;
    split2(x0, x1, &h, &l);
    ((__nv_bfloat162*)hi)[i] = h;
    ((__nv_bfloat162*)lo)[i] = l;
}

// RoPE + scale + split: q fp32 [row][h*64+d] -> qh/ql [b,h,s,d], scaled by 1/8
template<int NHEADS, int SCALE>
__global__ void rope_split_kernel(const float* __restrict__ x,
                                  __nv_bfloat16* __restrict__ hi,
                                  __nv_bfloat16* __restrict__ lo)
{
    int row = blockIdx.x;
    int b = row >> 11, s = row & 2047;
    int t = threadIdx.x;                 // NHEADS*32 threads
    int h = t >> 5, i = t & 31;
    float inv_freq = powf(10000.0f, -(float)(2 * i) / 64.0f);
    float ang = (float)s * inv_freq;
    float c, sn;
    __sincosf(ang, &sn, &c);
    const float* p = x + (size_t)row * (NHEADS * HD) + h * HD;
    float x1 = p[i], x2 = p[i + 32];
    float o1 = x1 * c - x2 * sn;
    float o2 = x2 * c + x1 * sn;
    if (SCALE) { o1 *= 0.125f; o2 *= 0.125f; }
    size_t dst = ((size_t)(b * NHEADS + h) * SEQ + s) * 64;
    __nv_bfloat16 h1 = __float2bfloat16(o1);
    __nv_bfloat16 h2 = __float2bfloat16(o2);
    hi[dst + i]      = h1;
    hi[dst + i + 32] = h2;
    lo[dst + i]      = __float2bfloat16(o1 - __bfloat162float(h1));
    lo[dst + i + 32] = __float2bfloat16(o2 - __bfloat162float(h2));
}

// V transpose + split: v fp32 [b*2048+s][kvh*64+d] -> vt [b,kvh,d,s] bf16 hi/lo
__global__ void vt_split_kernel(const float* __restrict__ v,
                                __nv_bfloat16* __restrict__ hiT,
                                __nv_bfloat16* __restrict__ loT)
{
    __shared__ float t[32][33];
    int s0 = blockIdx.x * 32, d0 = blockIdx.y * 32;
    int bz = blockIdx.z;                 // b*8+kvh
    int b = bz >> 3, kvh = bz & 7;
    int tx = threadIdx.x, ty = threadIdx.y;  // 32 x 8
    for (int sy = ty; sy < 32; sy += 8)
        t[sy][tx] = v[(size_t)(b * SEQ + s0 + sy) * 512 + kvh * 64 + d0 + tx];
    __syncthreads();
    for (int dy = ty; dy < 32; dy += 8) {
        float x = t[tx][dy];
        __nv_bfloat16 h = __float2bfloat16(x);
        __nv_bfloat16 l = __float2bfloat16(x - __bfloat162float(h));
        size_t o = ((size_t)bz * 64 + d0 + dy) * SEQ + s0 + tx;
        hiT[o] = h; loT[o] = l;
    }
}

// ---------------- HMMA GEMM (unchanged from passing R3) ----------------
#define BK 32
#define APITCH 80
#define MAT_SZ 10240
#define STG_SZ 40960
#define GSMEM  (3 * STG_SZ)

template<int EPI>
__global__ void __launch_bounds__(256)
hmma_gemm_kernel(const __nv_bfloat16* __restrict__ Ah, const __nv_bfloat16* __restrict__ Al,
                 const __nv_bfloat16* __restrict__ Bh, const __nv_bfloat16* __restrict__ Bl,
                 const float* __restrict__ RES, float* __restrict__ C, int N, int K)
{
    extern __shared__ char sm[];
    uint32_t smb = smem_u32(sm);
    int tid = threadIdx.x, lane = tid & 31, wid = tid >> 5;
    int wm = wid & 3, wn = wid >> 2;
    int bm = blockIdx.y, bn = blockIdx.x;
    int NKT = K / BK;

    const __nv_bfloat16* gAh = Ah + (size_t)bm * 128 * K;
    const __nv_bfloat16* gAl = Al + (size_t)bm * 128 * K;
    const __nv_bfloat16* gBh = Bh + (size_t)bn * 128 * K;
    const __nv_bfloat16* gBl = Bl + (size_t)bn * 128 * K;

    int rbase = tid >> 2;
    int ch = tid & 3;

    auto issue = [&](int st, int kt) {
        uint32_t base = smb + st * STG_SZ;
        int koff = kt * BK + ch * 8;
#pragma unroll
        for (int it = 0; it < 8; it++) {
            int mat = it >> 1;
            int r = rbase + (it & 1) * 64;
            const __nv_bfloat16* g = (mat == 0) ? gAh : (mat == 1) ? gAl : (mat == 2) ? gBh : gBl;
            cpa16(base + mat * MAT_SZ + r * APITCH + ch * 16,
                  g + (size_t)r * K + koff);
        }
        cpa_commit();
    };

    float acc[2][8][4];
#pragma unroll
    for (int s = 0; s < 2; s++)
#pragma unroll
        for (int t = 0; t < 8; t++)
#pragma unroll
            for (int j = 0; j < 4; j++) acc[s][t][j] = 0.f;

    issue(0, 0);
    issue(1, 1);

    int a_row = wm * 32 + (lane & 15);
    int a_kb  = (lane >> 4) * 16;
    int b_ro  = ((lane >> 4) << 3) + (lane & 7);
    int b_kb  = ((lane >> 3) & 1) * 16;

    for (int kt = 0; kt < NKT; kt++) {
        int st = kt % 3;
        if (kt + 2 < NKT) issue((kt + 2) % 3, kt + 2);
        else cpa_commit();
        asm volatile("cp.async.wait_group 2;" ::: "memory");
        __syncthreads();

        uint32_t sAh = smb + st * STG_SZ;
        uint32_t sAl = sAh + MAT_SZ;
        uint32_t sBh = sAl + MAT_SZ;
        uint32_t sBl = sBh + MAT_SZ;

#pragma unroll
        for (int ks = 0; ks < 2; ks++) {
            int kB = ks * 32;
            uint32_t ah[2][4], al[2][4];
            ldsm4(ah[0], sAh + (a_row)      * APITCH + kB + a_kb);
            ldsm4(ah[1], sAh + (a_row + 16) * APITCH + kB + a_kb);
            ldsm4(al[0], sAl + (a_row)      * APITCH + kB + a_kb);
            ldsm4(al[1], sAl + (a_row + 16) * APITCH + kB + a_kb);
            uint32_t bh[4][4], bl[4][4];
#pragma unroll
            for (int gi = 0; gi < 4; gi++) {
                int brow = wn * 64 + gi * 16 + b_ro;
                ldsm4(bh[gi], sBh + brow * APITCH + kB + b_kb);
                ldsm4(bl[gi], sBl + brow * APITCH + kB + b_kb);
            }
#pragma unroll
            for (int sub = 0; sub < 2; sub++)
#pragma unroll
                for (int t = 0; t < 8; t++) {
                    const uint32_t* bhp = &bh[t >> 1][(t & 1) * 2];
                    const uint32_t* blp = &bl[t >> 1][(t & 1) * 2];
                    mma16816(acc[sub][t], ah[sub], bhp);
                    mma16816(acc[sub][t], ah[sub], blp);
                    mma16816(acc[sub][t], al[sub], bhp);
                }
        }
        __syncthreads();
    }

#pragma unroll
    for (int sub = 0; sub < 2; sub++) {
        int row0 = bm * 128 + wm * 32 + sub * 16 + (lane >> 2);
#pragma unroll
        for (int t = 0; t < 8; t++) {
            int col = bn * 128 + wn * 64 + t * 8 + (lane & 3) * 2;
            size_t o0 = (size_t)row0 * N + col;
            size_t o1 = o0 + (size_t)8 * N;
            float2 v0 = make_float2(acc[sub][t][0], acc[sub][t][1]);
            float2 v1 = make_float2(acc[sub][t][2], acc[sub][t][3]);
            if (EPI == 1) {
                float2 r0 = *(const float2*)(RES + o0);
                float2 r1 = *(const float2*)(RES + o1);
                v0.x += r0.x; v0.y += r0.y;
                v1.x += r1.x; v1.y += r1.y;
            }
            *(float2*)(C + o0) = v0;
            *(float2*)(C + o1) = v1;
        }
    }
}

// ---------------- tensor-core causal attention ----------------
// 64 queries x 64 keys per tile; 128 threads (4 warps, 16 q-rows each).
// smem: Qh Ql Kh Kl Vh Vl, each 64 rows x 144B pitch.
#define AT_PITCH 144
#define AT_MAT   (64 * AT_PITCH)   // 9216
#define AT_QH 0
#define AT_QL (AT_MAT)
#define AT_KH (2 * AT_MAT)
#define AT_KL (3 * AT_MAT)
#define AT_VH (4 * AT_MAT)
#define AT_VL (5 * AT_MAT)
#define AT_SMEM (6 * AT_MAT)       // 55296

__global__ void __launch_bounds__(128)
attn_mma_kernel(const __nv_bfloat16* __restrict__ qh, const __nv_bfloat16* __restrict__ ql,
                const __nv_bfloat16* __restrict__ kh, const __nv_bfloat16* __restrict__ kl,
                const __nv_bfloat16* __restrict__ vth, const __nv_bfloat16* __restrict__ vtl,
                float* __restrict__ O)
{
    extern __shared__ char sm[];
    uint32_t smb = smem_u32(sm);
    int qt = blockIdx.x, h = blockIdx.y, b = blockIdx.z;
    int kvh = h >> 2;
    int tid = threadIdx.x, lane = tid & 31, w = tid >> 5;
    int q0 = qt * 64;

    const __nv_bfloat16* Qhp = qh + ((size_t)(b * NH + h) * SEQ + q0) * 64;
    const __nv_bfloat16* Qlp = ql + ((size_t)(b * NH + h) * SEQ + q0) * 64;
    const __nv_bfloat16* Khp = kh + ((size_t)(b * NKVH + kvh) * SEQ) * 64;
    const __nv_bfloat16* Klp = kl + ((size_t)(b * NKVH + kvh) * SEQ) * 64;
    const __nv_bfloat16* Vhp = vth + ((size_t)(b * NKVH + kvh) * 64) * SEQ;
    const __nv_bfloat16* Vlp = vtl + ((size_t)(b * NKVH + kvh) * 64) * SEQ;

    // load Q tile once
#pragma unroll
    for (int it = 0; it < 4; it++) {
        int idx = it * 128 + tid;
        int r = idx >> 3, ch = idx & 7;
        cpa16(smb + AT_QH + r * AT_PITCH + ch * 16, Qhp + (size_t)r * 64 + ch * 8);
        cpa16(smb + AT_QL + r * AT_PITCH + ch * 16, Qlp + (size_t)r * 64 + ch * 8);
    }
    cpa_commit();

    float m0 = -1e30f, m1 = -1e30f, l0 = 0.f, l1 = 0.f;
    float ao[8][4];
#pragma unroll
    for (int nt = 0; nt < 8; nt++)
#pragma unroll
        for (int j = 0; j < 4; j++) ao[nt][j] = 0.f;

    int r0 = lane >> 2, cq = lane & 3;
    int a_row = w * 16 + (lane & 15);
    int a_kb  = (lane >> 4) * 16;
    int b_ro  = ((lane >> 4) << 3) + (lane & 7);
    int b_kb  = ((lane >> 3) & 1) * 16;

    for (int kt = 0; kt <= qt; kt++) {
        int k0 = kt * 64;
        // load K and V^T tiles
#pragma unroll
        for (int it = 0; it < 4; it++) {
            int idx = it * 128 + tid;
            int r = idx >> 3, ch = idx & 7;
            cpa16(smb + AT_KH + r * AT_PITCH + ch * 16, Khp + (size_t)(k0 + r) * 64 + ch * 8);
            cpa16(smb + AT_KL + r * AT_PITCH + ch * 16, Klp + (size_t)(k0 + r) * 64 + ch * 8);
            cpa16(smb + AT_VH + r * AT_PITCH + ch * 16, Vhp + (size_t)r * SEQ + k0 + ch * 8);
            cpa16(smb + AT_VL + r * AT_PITCH + ch * 16, Vlp + (size_t)r * SEQ + k0 + ch * 8);
        }
        cpa_commit();
        asm volatile("cp.async.wait_group 0;" ::: "memory");
        __syncthreads();

        // scores = Q K^T (3-term split), fp32 accum
        float sc[8][4];
#pragma unroll
        for (int nt = 0; nt < 8; nt++)
#pragma unroll
            for (int j = 0; j < 4; j++) sc[nt][j] = 0.f;

#pragma unroll
        for (int kc = 0; kc < 4; kc++) {
            uint32_t ah4[4], al4[4];
            ldsm4(ah4, smb + AT_QH + a_row * AT_PITCH + kc * 32 + a_kb);
            ldsm4(al4, smb + AT_QL + a_row * AT_PITCH + kc * 32 + a_kb);
#pragma unroll
            for (int gi = 0; gi < 4; gi++) {
                uint32_t kh4[4], kl4[4];
                ldsm4(kh4, smb + AT_KH + (gi * 16 + b_ro) * AT_PITCH + kc * 32 + b_kb);
                ldsm4(kl4, smb + AT_KL + (gi * 16 + b_ro) * AT_PITCH + kc * 32 + b_kb);
#pragma unroll
                for (int t = 0; t < 2; t++) {
                    mma16816(sc[gi * 2 + t], ah4, &kh4[t * 2]);
                    mma16816(sc[gi * 2 + t], ah4, &kl4[t * 2]);
                    mma16816(sc[gi * 2 + t], al4, &kh4[t * 2]);
                }
            }
        }

        // causal mask on the diagonal tile
        if (kt == qt) {
            int qr0 = w * 16 + r0, qr1 = qr0 + 8;
#pragma unroll
            for (int nt = 0; nt < 8; nt++) {
                int col = nt * 8 + cq * 2;
                if (col     > qr0) sc[nt][0] = -1e30f;
                if (col + 1 > qr0) sc[nt][1] = -1e30f;
                if (col     > qr1) sc[nt][2] = -1e30f;
                if (col + 1 > qr1) sc[nt][3] = -1e30f;
            }
        }

        // online softmax (rows r0 and r0+8)
        float tm0 = -1e30f, tm1 = -1e30f;
#pragma unroll
        for (int nt = 0; nt < 8; nt++) {
            tm0 = fmaxf(tm0, fmaxf(sc[nt][0], sc[nt][1]));
            tm1 = fmaxf(tm1, fmaxf(sc[nt][2], sc[nt][3]));
        }
        tm0 = fmaxf(tm0, __shfl_xor_sync(0xffffffffu, tm0, 1));
        tm0 = fmaxf(tm0, __shfl_xor_sync(0xffffffffu, tm0, 2));
        tm1 = fmaxf(tm1, __shfl_xor_sync(0xffffffffu, tm1, 1));
        tm1 = fmaxf(tm1, __shfl_xor_sync(0xffffffffu, tm1, 2));
        float mn0 = fmaxf(m0, tm0), mn1 = fmaxf(m1, tm1);
        float cr0 = fexp2((m0 - mn0) * L2E);
        float cr1 = fexp2((m1 - mn1) * L2E);
        float rs0 = 0.f, rs1 = 0.f;
#pragma unroll
        for (int nt = 0; nt < 8; nt++) {
            sc[nt][0] = fexp2((sc[nt][0] - mn0) * L2E);
            sc[nt][1] = fexp2((sc[nt][1] - mn0) * L2E);
            sc[nt][2] = fexp2((sc[nt][2] - mn1) * L2E);
            sc[nt][3] = fexp2((sc[nt][3] - mn1) * L2E);
            rs0 += sc[nt][0] + sc[nt][1];
            rs1 += sc[nt][2] + sc[nt][3];
        }
        rs0 += __shfl_xor_sync(0xffffffffu, rs0, 1);
        rs0 += __shfl_xor_sync(0xffffffffu, rs0, 2);
        rs1 += __shfl_xor_sync(0xffffffffu, rs1, 1);
        rs1 += __shfl_xor_sync(0xffffffffu, rs1, 2);
        l0 = l0 * cr0 + rs0;
        l1 = l1 * cr1 + rs1;
        m0 = mn0; m1 = mn1;
#pragma unroll
        for (int nt = 0; nt < 8; nt++) {
            ao[nt][0] *= cr0; ao[nt][1] *= cr0;
            ao[nt][2] *= cr1; ao[nt][3] *= cr1;
        }

        // P (split hi/lo) @ V^T
#pragma unroll
        for (int j = 0; j < 4; j++) {
            uint32_t pah[4], pal[4];
#pragma unroll
            for (int u = 0; u < 2; u++) {
                float p0 = sc[2 * j + u][0], p1 = sc[2 * j + u][1];
                float p2 = sc[2 * j + u][2], p3 = sc[2 * j + u][3];
                __nv_bfloat162 H, L;
                split2(p0, p1, &H, &L);
                pah[2 * u + 0] = *(uint32_t*)&H; pal[2 * u + 0] = *(uint32_t*)&L;
                split2(p2, p3, &H, &L);
                pah[2 * u + 1] = *(uint32_t*)&H; pal[2 * u + 1] = *(uint32_t*)&L;
            }
            // reorder: a[0]=tile2j rows, a[1]=tile2j rows+8, a[2]=tile2j+1 rows, a[3]=tile2j+1 rows+8
            uint32_t A_h[4] = { pah[0], pah[1], pah[2], pah[3] };
            uint32_t A_l[4] = { pal[0], pal[1], pal[2], pal[3] };
#pragma unroll
            for (int gi = 0; gi < 4; gi++) {
                uint32_t vh4[4], vl4[4];
                ldsm4(vh4, smb + AT_VH + (gi * 16 + b_ro) * AT_PITCH + j * 32 + b_kb);
                ldsm4(vl4, smb + AT_VL + (gi * 16 + b_ro) * AT_PITCH + j * 32 + b_kb);
#pragma unroll
                for (int t = 0; t < 2; t++) {
                    mma16816(ao[gi * 2 + t], A_h, &vh4[t * 2]);
                    mma16816(ao[gi * 2 + t], A_h, &vl4[t * 2]);
                    mma16816(ao[gi * 2 + t], A_l, &vh4[t * 2]);
                }
            }
        }
        __syncthreads();
    }

    float i0 = 1.f / l0, i1 = 1.f / l1;
    int rowA = q0 + w * 16 + r0;
    int rowB = rowA + 8;
#pragma unroll
    for (int nt = 0; nt < 8; nt++) {
        int col = h * 64 + nt * 8 + cq * 2;
        float2 vA = make_float2(ao[nt][0] * i0, ao[nt][1] * i0);
        float2 vB = make_float2(ao[nt][2] * i1, ao[nt][3] * i1);
        *(float2*)(O + ((size_t)(b * SEQ) + rowA) * 2048 + col) = vA;
        *(float2*)(O + ((size_t)(b * SEQ) + rowB) * 2048 + col) = vB;
    }
}

// ---------------- host launch ----------------
extern "C" void kernel_launch(void* const* d_in, const int* in_sizes, int n_in,
                              void* d_out, int out_size)
{
    const float* hidden  = (const float*)d_in[0];
    const float* norm1_w = (const float*)d_in[2];
    const float* wq      = (const float*)d_in[3];
    const float* wk      = (const float*)d_in[4];
    const float* wv      = (const float*)d_in[5];
    const float* wo      = (const float*)d_in[6];
    const float* norm2_w = (const float*)d_in[7];
    const float* w_gate  = (const float*)d_in[8];
    const float* w_up    = (const float*)d_in[9];
    const float* w_down  = (const float*)d_in[10];
    float* out = (float*)d_out;

    float *q, *k, *v, *ctx, *res2, *gate, *up;
    __nv_bfloat16 *a_hi, *a_lo, *w_hi, *w_lo;
    __nv_bfloat16 *qh, *ql, *kh, *kl, *vth, *vtl;
    cudaGetSymbolAddress((void**)&q,    g_q);
    cudaGetSymbolAddress((void**)&k,    g_k);
    cudaGetSymbolAddress((void**)&v,    g_v);
    cudaGetSymbolAddress((void**)&ctx,  g_ctx);
    cudaGetSymbolAddress((void**)&res2, g_res2);
    cudaGetSymbolAddress((void**)&gate, g_gate);
    cudaGetSymbolAddress((void**)&up,   g_up);
    cudaGetSymbolAddress((void**)&a_hi, g_a_hi);
    cudaGetSymbolAddress((void**)&a_lo, g_a_lo);
    cudaGetSymbolAddress((void**)&w_hi, g_w_hi);
    cudaGetSymbolAddress((void**)&w_lo, g_w_lo);
    cudaGetSymbolAddress((void**)&qh,   g_qh);
    cudaGetSymbolAddress((void**)&ql,   g_ql);
    cudaGetSymbolAddress((void**)&kh,   g_kh);
    cudaGetSymbolAddress((void**)&kl,   g_kl);
    cudaGetSymbolAddress((void**)&vth,  g_vth);
    cudaGetSymbolAddress((void**)&vtl,  g_vtl);

    const size_t OWQ = 0;
    const size_t OWK = 4ull * MEG;
    const size_t OWV = 5ull * MEG;
    const size_t OWO = 6ull * MEG;
    const size_t OWG = 10ull * MEG;
    const size_t OWU = 26ull * MEG;
    const size_t OWD = 42ull * MEG;

    cudaFuncSetAttribute(hmma_gemm_kernel<0>, cudaFuncAttributeMaxDynamicSharedMemorySize, GSMEM);
    cudaFuncSetAttribute(hmma_gemm_kernel<1>, cudaFuncAttributeMaxDynamicSharedMemorySize, GSMEM);
    cudaFuncSetAttribute(attn_mma_kernel, cudaFuncAttributeMaxDynamicSharedMemorySize, AT_SMEM);

    // ---- weight transpose + split ----
    convT_kernel<<<dim3(2048 / 32, 2048 / 32), 256>>>(wq,     w_hi + OWQ, w_lo + OWQ, 2048, 2048);
    convT_kernel<<<dim3(512  / 32, 2048 / 32), 256>>>(wk,     w_hi + OWK, w_lo + OWK, 2048, 512);
    convT_kernel<<<dim3(512  / 32, 2048 / 32), 256>>>(wv,     w_hi + OWV, w_lo + OWV, 2048, 512);
    convT_kernel<<<dim3(2048 / 32, 2048 / 32), 256>>>(wo,     w_hi + OWO, w_lo + OWO, 2048, 2048);
    convT_kernel<<<dim3(8192 / 32, 2048 / 32), 256>>>(w_gate, w_hi + OWG, w_lo + OWG, 2048, 8192);
    convT_kernel<<<dim3(8192 / 32, 2048 / 32), 256>>>(w_up,   w_hi + OWU, w_lo + OWU, 2048, 8192);
    convT_kernel<<<dim3(2048 / 32, 8192 / 32), 256>>>(w_down, w_hi + OWD, w_lo + OWD, 8192, 2048);

    // ---- 1. rmsnorm1 -> split ----
    rmsnorm_split_kernel<<<ROWS, 256>>>(hidden, norm1_w, a_hi, a_lo, HID);

    // ---- 2-4. QKV ----
    hmma_gemm_kernel<0><<<dim3(2048 / 128, ROWS / 128), 256, GSMEM>>>(
        a_hi, a_lo, w_hi + OWQ, w_lo + OWQ, nullptr, q, 2048, 2048);
    hmma_gemm_kernel<0><<<dim3(512 / 128, ROWS / 128), 256, GSMEM>>>(
        a_hi, a_lo, w_hi + OWK, w_lo + OWK, nullptr, k, 512, 2048);
    hmma_gemm_kernel<0><<<dim3(512 / 128, ROWS / 128), 256, GSMEM>>>(
        a_hi, a_lo, w_hi + OWV, w_lo + OWV, nullptr, v, 512, 2048);

    // ---- 5. RoPE + scale + split; V transpose + split ----
    rope_split_kernel<NH, 1><<<ROWS, NH * 32>>>(q, qh, ql);
    rope_split_kernel<NKVH, 0><<<ROWS, NKVH * 32>>>(k, kh, kl);
    vt_split_kernel<<<dim3(SEQ / 32, 2, NB * NKVH), dim3(32, 8)>>>(v, vth, vtl);

    // ---- 6. attention (tensor cores) ----
    attn_mma_kernel<<<dim3(SEQ / 64, NH, NB), 128, AT_SMEM>>>(qh, ql, kh, kl, vth, vtl, ctx);

    // ---- 7. ctx -> split, output projection + residual ----
    convert_split_kernel<<<(int)(((size_t)ROWS * 2048 / 2 + 255) / 256), 256>>>(
        ctx, a_hi, a_lo, (size_t)ROWS * 2048 / 2);
    hmma_gemm_kernel<1><<<dim3(2048 / 128, ROWS / 128), 256, GSMEM>>>(
        a_hi, a_lo, w_hi + OWO, w_lo + OWO, hidden, res2, 2048, 2048);

    // ---- 8. rmsnorm2 -> split ----
    rmsnorm_split_kernel<<<ROWS, 256>>>(res2, norm2_w, a_hi, a_lo, HID);

    // ---- 9-10. gate / up ----
    hmma_gemm_kernel<0><<<dim3(FF / 128, ROWS / 128), 256, GSMEM>>>(
        a_hi, a_lo, w_hi + OWG, w_lo + OWG, nullptr, gate, FF, 2048);
    hmma_gemm_kernel<0><<<dim3(FF / 128, ROWS / 128), 256, GSMEM>>>(
        a_hi, a_lo, w_hi + OWU, w_lo + OWU, nullptr, up, FF, 2048);

    // ---- 11. silu(gate)*up -> split ----
    {
        size_t npairs = (size_t)ROWS * FF / 2;
        silu_mul_split_kernel<<<(int)((npairs + 255) / 256), 256>>>(gate, up, a_hi, a_lo, npairs);
    }

    // ---- 12. down projection + residual -> out ----
    hmma_gemm_kernel<1><<<dim3(2048 / 128, ROWS / 128), 256, GSMEM>>>(
        a_hi, a_lo, w_hi + OWD, w_lo + OWD, res2, out, 2048, 8192);
}

// round 6
// speedup vs baseline: 3.2466x; 1.1139x over previous
#include <cuda_runtime.h>
#include <cuda_bf16.h>
#include <math.h>
#include <stdint.h>

// ---------------- problem constants ----------------
#define HID   2048
#define NH    32
#define NKVH  8
#define HD    64
#define FF    8192
#define SEQ   2048
#define NB    2
#define ROWS  4096
#define EPS   1e-6f
#define MEG   (1024*1024)
#define L2E   1.4426950408889634f

// ---------------- scratch (device globals; no allocs allowed) ----------------
__device__ float g_res2[(size_t)ROWS * 2048];
__device__ float g_gate[(size_t)ROWS * FF];          // also holds qkv fp32 [ROWS][3072] early
__device__ float g_up  [(size_t)ROWS * FF];          // reused as bf16 m_hi/m_lo halves

// bf16 hi/lo split operands (plain row-major)
__device__ __nv_bfloat16 g_a_hi[(size_t)ROWS * HID];
__device__ __nv_bfloat16 g_a_lo[(size_t)ROWS * HID];
__device__ __nv_bfloat16 g_w_hi[(size_t)58 * MEG];
__device__ __nv_bfloat16 g_w_lo[(size_t)58 * MEG];

// attention bf16 split operands
__device__ __nv_bfloat16 g_qh[(size_t)ROWS * 2048];
__device__ __nv_bfloat16 g_ql[(size_t)ROWS * 2048];
__device__ __nv_bfloat16 g_kh[(size_t)ROWS * 512];
__device__ __nv_bfloat16 g_kl[(size_t)ROWS * 512];
__device__ __nv_bfloat16 g_vth[(size_t)ROWS * 512];
__device__ __nv_bfloat16 g_vtl[(size_t)ROWS * 512];

// ---------------- helpers ----------------
__device__ __forceinline__ uint32_t smem_u32(const void* p) {
    uint32_t a;
    asm("{ .reg .u64 t; cvta.to.shared.u64 t, %1; cvt.u32.u64 %0, t; }" : "=r"(a) : "l"(p));
    return a;
}

__device__ __forceinline__ void cpa16(uint32_t dst, const void* src) {
    asm volatile("cp.async.cg.shared.global [%0], [%1], 16;" :: "r"(dst), "l"(src));
}
__device__ __forceinline__ void cpa_commit() {
    asm volatile("cp.async.commit_group;" ::: "memory");
}

__device__ __forceinline__ void ldsm4(uint32_t* r, uint32_t addr) {
    asm volatile("ldmatrix.sync.aligned.m8n8.x4.shared.b16 {%0,%1,%2,%3}, [%4];"
        : "=r"(r[0]), "=r"(r[1]), "=r"(r[2]), "=r"(r[3]) : "r"(addr));
}

__device__ __forceinline__ void mma16816(float* c, const uint32_t* a, const uint32_t* b) {
    asm volatile("mma.sync.aligned.m16n8k16.row.col.f32.bf16.bf16.f32 "
        "{%0,%1,%2,%3}, {%4,%5,%6,%7}, {%8,%9}, {%0,%1,%2,%3};"
        : "+f"(c[0]), "+f"(c[1]), "+f"(c[2]), "+f"(c[3])
        : "r"(a[0]), "r"(a[1]), "r"(a[2]), "r"(a[3]), "r"(b[0]), "r"(b[1]));
}

__device__ __forceinline__ void split2(float x0, float x1, __nv_bfloat162* hi, __nv_bfloat162* lo) {
    __nv_bfloat16 h0 = __float2bfloat16(x0);
    __nv_bfloat16 h1 = __float2bfloat16(x1);
    __nv_bfloat16 l0 = __float2bfloat16(x0 - __bfloat162float(h0));
    __nv_bfloat16 l1 = __float2bfloat16(x1 - __bfloat162float(h1));
    hi->x = h0; hi->y = h1; lo->x = l0; lo->y = l1;
}

// FMA-only exp2, clamped both sides, |rel err| ~2e-6
__device__ __forceinline__ float fexp2(float z) {
    z = fminf(fmaxf(z, -126.f), 126.f);
    float sh = z + 12582912.f;
    float zi = sh - 12582912.f;
    float f = z - zi;
    float p = 0.0013333558f;
    p = p * f + 0.0096181291f;
    p = p * f + 0.0555041087f;
    p = p * f + 0.2402265070f;
    p = p * f + 0.6931471806f;
    p = p * f + 1.0f;
    int ei = __float_as_int(sh) - 0x4B400000;
    return p * __int_as_float((ei + 127) << 23);
}

__device__ __forceinline__ float fsilu(float x) {
    return x / (1.f + fexp2(-x * L2E));
}

// ---------------- converters ----------------
__global__ void convT_kernel(const float* __restrict__ W,
                             __nv_bfloat16* __restrict__ hiT,
                             __nv_bfloat16* __restrict__ loT, int K, int N)
{
    __shared__ float t[32][33];
    int n0 = blockIdx.x * 32, k0 = blockIdx.y * 32;
    int tx = threadIdx.x & 31, ty = threadIdx.x >> 5;
    for (int ky = ty; ky < 32; ky += 8)
        t[ky][tx] = W[(size_t)(k0 + ky) * N + n0 + tx];
    __syncthreads();
    for (int ny = ty; ny < 32; ny += 8) {
        float x = t[tx][ny];
        __nv_bfloat16 h = __float2bfloat16(x);
        __nv_bfloat16 l = __float2bfloat16(x - __bfloat162float(h));
        size_t o = (size_t)(n0 + ny) * K + k0 + tx;
        hiT[o] = h; loT[o] = l;
    }
}

__global__ void rmsnorm_split_kernel(const float* __restrict__ x,
                                     const float* __restrict__ w,
                                     __nv_bfloat16* __restrict__ hi,
                                     __nv_bfloat16* __restrict__ lo, int K)
{
    int row = blockIdx.x;
    const float* xr = x + (size_t)row * K;
    float ss = 0.f;
    int nvec = K / 4;
    const float4* xv = (const float4*)xr;
    for (int c = threadIdx.x; c < nvec; c += blockDim.x) {
        float4 v = xv[c];
        ss += v.x * v.x + v.y * v.y + v.z * v.z + v.w * v.w;
    }
    __shared__ float red[32];
    for (int off = 16; off > 0; off >>= 1) ss += __shfl_xor_sync(0xffffffffu, ss, off);
    int lane = threadIdx.x & 31, wid = threadIdx.x >> 5;
    if (lane == 0) red[wid] = ss;
    __syncthreads();
    int nwarp = blockDim.x >> 5;
    if (wid == 0) {
        float t = (lane < nwarp) ? red[lane] : 0.f;
        for (int off = 16; off > 0; off >>= 1) t += __shfl_xor_sync(0xffffffffu, t, off);
        if (lane == 0) red[0] = t;
    }
    __syncthreads();
    float inv = rsqrtf(red[0] / (float)K + EPS);

    for (int c = threadIdx.x; c < K / 2; c += blockDim.x) {
        int k = 2 * c;
        float x0 = xr[k] * inv * w[k];
        float x1 = xr[k + 1] * inv * w[k + 1];
        __nv_bfloat162 h, l;
        split2(x0, x1, &h, &l);
        ((__nv_bfloat162*)(hi + (size_t)row * K))[c] = h;
        ((__nv_bfloat162*)(lo + (size_t)row * K))[c] = l;
    }
}

// RoPE + scale + split; reads qkv fp32 [row][3072] at column offset COFF
template<int NHEADS, int SCALE, int COFF>
__global__ void rope_split_kernel(const float* __restrict__ x,
                                  __nv_bfloat16* __restrict__ hi,
                                  __nv_bfloat16* __restrict__ lo)
{
    int row = blockIdx.x;
    int b = row >> 11, s = row & 2047;
    int t = threadIdx.x;
    int h = t >> 5, i = t & 31;
    float inv_freq = powf(10000.0f, -(float)(2 * i) / 64.0f);
    float ang = (float)s * inv_freq;
    float c, sn;
    __sincosf(ang, &sn, &c);
    const float* p = x + (size_t)row * 3072 + COFF + h * HD;
    float x1 = p[i], x2 = p[i + 32];
    float o1 = x1 * c - x2 * sn;
    float o2 = x2 * c + x1 * sn;
    if (SCALE) { o1 *= 0.125f; o2 *= 0.125f; }
    size_t dst = ((size_t)(b * NHEADS + h) * SEQ + s) * 64;
    __nv_bfloat16 h1 = __float2bfloat16(o1);
    __nv_bfloat16 h2 = __float2bfloat16(o2);
    hi[dst + i]      = h1;
    hi[dst + i + 32] = h2;
    lo[dst + i]      = __float2bfloat16(o1 - __bfloat162float(h1));
    lo[dst + i + 32] = __float2bfloat16(o2 - __bfloat162float(h2));
}

// V transpose + split: qkv fp32 [row][3072] col 2560+ -> vt [b,kvh,d,s] bf16 hi/lo
__global__ void vt_split_kernel(const float* __restrict__ v,
                                __nv_bfloat16* __restrict__ hiT,
                                __nv_bfloat16* __restrict__ loT)
{
    __shared__ float t[32][33];
    int s0 = blockIdx.x * 32, d0 = blockIdx.y * 32;
    int bz = blockIdx.z;
    int b = bz >> 3, kvh = bz & 7;
    int tx = threadIdx.x, ty = threadIdx.y;
    for (int sy = ty; sy < 32; sy += 8)
        t[sy][tx] = v[(size_t)(b * SEQ + s0 + sy) * 3072 + 2560 + kvh * 64 + d0 + tx];
    __syncthreads();
    for (int dy = ty; dy < 32; dy += 8) {
        float x = t[tx][dy];
        __nv_bfloat16 h = __float2bfloat16(x);
        __nv_bfloat16 l = __float2bfloat16(x - __bfloat162float(h));
        size_t o = ((size_t)bz * 64 + d0 + dy) * SEQ + s0 + tx;
        hiT[o] = h; loT[o] = l;
    }
}

// ---------------- HMMA GEMM: 128(M) x 256(N) tile, BK=32, 3-stage ----------------
// EPI 0: C = A@B^T (fp32)
// EPI 1: C = A@B^T + RES (fp32)
// EPI 2: OH/OL = split(silu(RES) * (A@B^T))   (RES = gate fp32; C unused)
#define APITCH 80
#define A_MAT  10240          // 128 * 80
#define B_MAT  20480          // 256 * 80
#define STG_SZ (2 * A_MAT + 2 * B_MAT)   // 61440
#define GSMEM  (3 * STG_SZ)               // 184320

template<int EPI>
__global__ void __launch_bounds__(256, 1)
hmma_gemm_kernel(const __nv_bfloat16* __restrict__ Ah, const __nv_bfloat16* __restrict__ Al,
                 const __nv_bfloat16* __restrict__ Bh, const __nv_bfloat16* __restrict__ Bl,
                 const float* __restrict__ RES, float* __restrict__ C,
                 __nv_bfloat16* __restrict__ OH, __nv_bfloat16* __restrict__ OL,
                 int N, int K)
{
    extern __shared__ char sm[];
    uint32_t smb = smem_u32(sm);
    int tid = threadIdx.x, lane = tid & 31, wid = tid >> 5;
    int wm = wid & 3, wn = wid >> 2;          // warp tile 32(M) x 128(N)
    int bm = blockIdx.y, bn = blockIdx.x;
    int NKT = K / 32;

    const __nv_bfloat16* gAh = Ah + (size_t)bm * 128 * K;
    const __nv_bfloat16* gAl = Al + (size_t)bm * 128 * K;
    const __nv_bfloat16* gBh = Bh + (size_t)bn * 256 * K;
    const __nv_bfloat16* gBl = Bl + (size_t)bn * 256 * K;

    int rbase = tid >> 2;      // 0..63
    int ch = tid & 3;          // 16B chunk within 64B row

    auto issue = [&](int st, int kt) {
        uint32_t base = smb + st * STG_SZ;
        int koff = kt * 32 + ch * 8;
        // A hi/lo: rows rbase, rbase+64
#pragma unroll
        for (int u = 0; u < 2; u++) {
            int r = rbase + u * 64;
            cpa16(base + 0 * A_MAT + r * APITCH + ch * 16, gAh + (size_t)r * K + koff);
            cpa16(base + 1 * A_MAT + r * APITCH + ch * 16, gAl + (size_t)r * K + koff);
        }
        // B hi/lo: rows rbase + {0,64,128,192}
        uint32_t bB = base + 2 * A_MAT;
#pragma unroll
        for (int u = 0; u < 4; u++) {
            int r = rbase + u * 64;
            cpa16(bB + r * APITCH + ch * 16,         gBh + (size_t)r * K + koff);
            cpa16(bB + B_MAT + r * APITCH + ch * 16, gBl + (size_t)r * K + koff);
        }
        cpa_commit();
    };

    float acc[2][16][4];
#pragma unroll
    for (int s = 0; s < 2; s++)
#pragma unroll
        for (int t = 0; t < 16; t++)
#pragma unroll
            for (int j = 0; j < 4; j++) acc[s][t][j] = 0.f;

    issue(0, 0);
    issue(1, 1);

    int a_row = wm * 32 + (lane & 15);
    int a_kb  = (lane >> 4) * 16;
    int b_ro  = ((lane >> 4) << 3) + (lane & 7);
    int b_kb  = ((lane >> 3) & 1) * 16;

    for (int kt = 0; kt < NKT; kt++) {
        int st = kt % 3;
        if (kt + 2 < NKT) issue((kt + 2) % 3, kt + 2);
        else cpa_commit();
        asm volatile("cp.async.wait_group 2;" ::: "memory");
        __syncthreads();

        uint32_t sAh = smb + st * STG_SZ;
        uint32_t sAl = sAh + A_MAT;
        uint32_t sBh = sAl + A_MAT;
        uint32_t sBl = sBh + B_MAT;

#pragma unroll
        for (int ks = 0; ks < 2; ks++) {
            int kB = ks * 32;
            uint32_t ah[2][4], al[2][4];
            ldsm4(ah[0], sAh + (a_row)      * APITCH + kB + a_kb);
            ldsm4(ah[1], sAh + (a_row + 16) * APITCH + kB + a_kb);
            ldsm4(al[0], sAl + (a_row)      * APITCH + kB + a_kb);
            ldsm4(al[1], sAl + (a_row + 16) * APITCH + kB + a_kb);
#pragma unroll
            for (int gi = 0; gi < 8; gi++) {
                int brow = wn * 128 + gi * 16 + b_ro;
                uint32_t bh4[4], bl4[4];
                ldsm4(bh4, sBh + brow * APITCH + kB + b_kb);
                ldsm4(bl4, sBl + brow * APITCH + kB + b_kb);
#pragma unroll
                for (int t = 0; t < 2; t++) {
                    const uint32_t* bhp = &bh4[t * 2];
                    const uint32_t* blp = &bl4[t * 2];
#pragma unroll
                    for (int sub = 0; sub < 2; sub++) {
                        mma16816(acc[sub][gi * 2 + t], ah[sub], bhp);
                        mma16816(acc[sub][gi * 2 + t], ah[sub], blp);
                        mma16816(acc[sub][gi * 2 + t], al[sub], bhp);
                    }
                }
            }
        }
        __syncthreads();
    }

    // epilogue
#pragma unroll
    for (int sub = 0; sub < 2; sub++) {
        int row0 = bm * 128 + wm * 32 + sub * 16 + (lane >> 2);
#pragma unroll
        for (int t = 0; t < 16; t++) {
            int col = bn * 256 + wn * 128 + t * 8 + (lane & 3) * 2;
            size_t o0 = (size_t)row0 * N + col;
            size_t o1 = o0 + (size_t)8 * N;
            if (EPI == 2) {
                float2 G0 = *(const float2*)(RES + o0);
                float2 G1 = *(const float2*)(RES + o1);
                float x0 = fsilu(G0.x) * acc[sub][t][0];
                float x1 = fsilu(G0.y) * acc[sub][t][1];
                float x2 = fsilu(G1.x) * acc[sub][t][2];
                float x3 = fsilu(G1.y) * acc[sub][t][3];
                __nv_bfloat162 H, L;
                split2(x0, x1, &H, &L);
                *(__nv_bfloat162*)(OH + o0) = H;
                *(__nv_bfloat162*)(OL + o0) = L;
                split2(x2, x3, &H, &L);
                *(__nv_bfloat162*)(OH + o1) = H;
                *(__nv_bfloat162*)(OL + o1) = L;
            } else {
                float2 v0 = make_float2(acc[sub][t][0], acc[sub][t][1]);
                float2 v1 = make_float2(acc[sub][t][2], acc[sub][t][3]);
                if (EPI == 1) {
                    float2 r0 = *(const float2*)(RES + o0);
                    float2 r1 = *(const float2*)(RES + o1);
                    v0.x += r0.x; v0.y += r0.y;
                    v1.x += r1.x; v1.y += r1.y;
                }
                *(float2*)(C + o0) = v0;
                *(float2*)(C + o1) = v1;
            }
        }
    }
}

// ---------------- tensor-core causal attention (writes ctx split directly) ----------------
#define AT_PITCH 144
#define AT_MAT   (64 * AT_PITCH)
#define AT_QH 0
#define AT_QL (AT_MAT)
#define AT_KH (2 * AT_MAT)
#define AT_KL (3 * AT_MAT)
#define AT_VH (4 * AT_MAT)
#define AT_VL (5 * AT_MAT)
#define AT_SMEM (6 * AT_MAT)

__global__ void __launch_bounds__(128)
attn_mma_kernel(const __nv_bfloat16* __restrict__ qh, const __nv_bfloat16* __restrict__ ql,
                const __nv_bfloat16* __restrict__ kh, const __nv_bfloat16* __restrict__ kl,
                const __nv_bfloat16* __restrict__ vth, const __nv_bfloat16* __restrict__ vtl,
                __nv_bfloat16* __restrict__ OH, __nv_bfloat16* __restrict__ OL)
{
    extern __shared__ char sm[];
    uint32_t smb = smem_u32(sm);
    int qt = blockIdx.x, h = blockIdx.y, b = blockIdx.z;
    int kvh = h >> 2;
    int tid = threadIdx.x, lane = tid & 31, w = tid >> 5;
    int q0 = qt * 64;

    const __nv_bfloat16* Qhp = qh + ((size_t)(b * NH + h) * SEQ + q0) * 64;
    const __nv_bfloat16* Qlp = ql + ((size_t)(b * NH + h) * SEQ + q0) * 64;
    const __nv_bfloat16* Khp = kh + ((size_t)(b * NKVH + kvh) * SEQ) * 64;
    const __nv_bfloat16* Klp = kl + ((size_t)(b * NKVH + kvh) * SEQ) * 64;
    const __nv_bfloat16* Vhp = vth + ((size_t)(b * NKVH + kvh) * 64) * SEQ;
    const __nv_bfloat16* Vlp = vtl + ((size_t)(b * NKVH + kvh) * 64) * SEQ;

#pragma unroll
    for (int it = 0; it < 4; it++) {
        int idx = it * 128 + tid;
        int r = idx >> 3, ch = idx & 7;
        cpa16(smb + AT_QH + r * AT_PITCH + ch * 16, Qhp + (size_t)r * 64 + ch * 8);
        cpa16(smb + AT_QL + r * AT_PITCH + ch * 16, Qlp + (size_t)r * 64 + ch * 8);
    }
    cpa_commit();

    float m0 = -1e30f, m1 = -1e30f, l0 = 0.f, l1 = 0.f;
    float ao[8][4];
#pragma unroll
    for (int nt = 0; nt < 8; nt++)
#pragma unroll
        for (int j = 0; j < 4; j++) ao[nt][j] = 0.f;

    int r0 = lane >> 2, cq = lane & 3;
    int a_row = w * 16 + (lane & 15);
    int a_kb  = (lane >> 4) * 16;
    int b_ro  = ((lane >> 4) << 3) + (lane & 7);
    int b_kb  = ((lane >> 3) & 1) * 16;

    for (int kt = 0; kt <= qt; kt++) {
        int k0 = kt * 64;
#pragma unroll
        for (int it = 0; it < 4; it++) {
            int idx = it * 128 + tid;
            int r = idx >> 3, ch = idx & 7;
            cpa16(smb + AT_KH + r * AT_PITCH + ch * 16, Khp + (size_t)(k0 + r) * 64 + ch * 8);
            cpa16(smb + AT_KL + r * AT_PITCH + ch * 16, Klp + (size_t)(k0 + r) * 64 + ch * 8);
            cpa16(smb + AT_VH + r * AT_PITCH + ch * 16, Vhp + (size_t)r * SEQ + k0 + ch * 8);
            cpa16(smb + AT_VL + r * AT_PITCH + ch * 16, Vlp + (size_t)r * SEQ + k0 + ch * 8);
        }
        cpa_commit();
        asm volatile("cp.async.wait_group 0;" ::: "memory");
        __syncthreads();

        float sc[8][4];
#pragma unroll
        for (int nt = 0; nt < 8; nt++)
#pragma unroll
            for (int j = 0; j < 4; j++) sc[nt][j] = 0.f;

#pragma unroll
        for (int kc = 0; kc < 4; kc++) {
            uint32_t ah4[4], al4[4];
            ldsm4(ah4, smb + AT_QH + a_row * AT_PITCH + kc * 32 + a_kb);
            ldsm4(al4, smb + AT_QL + a_row * AT_PITCH + kc * 32 + a_kb);
#pragma unroll
            for (int gi = 0; gi < 4; gi++) {
                uint32_t kh4[4], kl4[4];
                ldsm4(kh4, smb + AT_KH + (gi * 16 + b_ro) * AT_PITCH + kc * 32 + b_kb);
                ldsm4(kl4, smb + AT_KL + (gi * 16 + b_ro) * AT_PITCH + kc * 32 + b_kb);
#pragma unroll
                for (int t = 0; t < 2; t++) {
                    mma16816(sc[gi * 2 + t], ah4, &kh4[t * 2]);
                    mma16816(sc[gi * 2 + t], ah4, &kl4[t * 2]);
                    mma16816(sc[gi * 2 + t], al4, &kh4[t * 2]);
                }
            }
        }

        if (kt == qt) {
            int qr0 = w * 16 + r0, qr1 = qr0 + 8;
#pragma unroll
            for (int nt = 0; nt < 8; nt++) {
                int col = nt * 8 + cq * 2;
                if (col     > qr0) sc[nt][0] = -1e30f;
                if (col + 1 > qr0) sc[nt][1] = -1e30f;
                if (col     > qr1) sc[nt][2] = -1e30f;
                if (col + 1 > qr1) sc[nt][3] = -1e30f;
            }
        }

        float tm0 = -1e30f, tm1 = -1e30f;
#pragma unroll
        for (int nt = 0; nt < 8; nt++) {
            tm0 = fmaxf(tm0, fmaxf(sc[nt][0], sc[nt][1]));
            tm1 = fmaxf(tm1, fmaxf(sc[nt][2], sc[nt][3]));
        }
        tm0 = fmaxf(tm0, __shfl_xor_sync(0xffffffffu, tm0, 1));
        tm0 = fmaxf(tm0, __shfl_xor_sync(0xffffffffu, tm0, 2));
        tm1 = fmaxf(tm1, __shfl_xor_sync(0xffffffffu, tm1, 1));
        tm1 = fmaxf(tm1, __shfl_xor_sync(0xffffffffu, tm1, 2));
        float mn0 = fmaxf(m0, tm0), mn1 = fmaxf(m1, tm1);
        float cr0 = fexp2((m0 - mn0) * L2E);
        float cr1 = fexp2((m1 - mn1) * L2E);
        float rs0 = 0.f, rs1 = 0.f;
#pragma unroll
        for (int nt = 0; nt < 8; nt++) {
            sc[nt][0] = fexp2((sc[nt][0] - mn0) * L2E);
            sc[nt][1] = fexp2((sc[nt][1] - mn0) * L2E);
            sc[nt][2] = fexp2((sc[nt][2] - mn1) * L2E);
            sc[nt][3] = fexp2((sc[nt][3] - mn1) * L2E);
            rs0 += sc[nt][0] + sc[nt][1];
            rs1 += sc[nt][2] + sc[nt][3];
        }
        rs0 += __shfl_xor_sync(0xffffffffu, rs0, 1);
        rs0 += __shfl_xor_sync(0xffffffffu, rs0, 2);
        rs1 += __shfl_xor_sync(0xffffffffu, rs1, 1);
        rs1 += __shfl_xor_sync(0xffffffffu, rs1, 2);
        l0 = l0 * cr0 + rs0;
        l1 = l1 * cr1 + rs1;
        m0 = mn0; m1 = mn1;
#pragma unroll
        for (int nt = 0; nt < 8; nt++) {
            ao[nt][0] *= cr0; ao[nt][1] *= cr0;
            ao[nt][2] *= cr1; ao[nt][3] *= cr1;
        }

#pragma unroll
        for (int j = 0; j < 4; j++) {
            uint32_t pah[4], pal[4];
#pragma unroll
            for (int u = 0; u < 2; u++) {
                __nv_bfloat162 H, L;
                split2(sc[2 * j + u][0], sc[2 * j + u][1], &H, &L);
                pah[2 * u + 0] = *(uint32_t*)&H; pal[2 * u + 0] = *(uint32_t*)&L;
                split2(sc[2 * j + u][2], sc[2 * j + u][3], &H, &L);
                pah[2 * u + 1] = *(uint32_t*)&H; pal[2 * u + 1] = *(uint32_t*)&L;
            }
#pragma unroll
            for (int gi = 0; gi < 4; gi++) {
                uint32_t vh4[4], vl4[4];
                ldsm4(vh4, smb + AT_VH + (gi * 16 + b_ro) * AT_PITCH + j * 32 + b_kb);
                ldsm4(vl4, smb + AT_VL + (gi * 16 + b_ro) * AT_PITCH + j * 32 + b_kb);
#pragma unroll
                for (int t = 0; t < 2; t++) {
                    mma16816(ao[gi * 2 + t], pah, &vh4[t * 2]);
                    mma16816(ao[gi * 2 + t], pah, &vl4[t * 2]);
                    mma16816(ao[gi * 2 + t], pal, &vh4[t * 2]);
                }
            }
        }
        __syncthreads();
    }

    float i0 = 1.f / l0, i1 = 1.f / l1;
    int rowA = q0 + w * 16 + r0;
    int rowB = rowA + 8;
#pragma unroll
    for (int nt = 0; nt < 8; nt++) {
        int col = h * 64 + nt * 8 + cq * 2;
        size_t oA = ((size_t)(b * SEQ) + rowA) * 2048 + col;
        size_t oB = ((size_t)(b * SEQ) + rowB) * 2048 + col;
        __nv_bfloat162 H, L;
        split2(ao[nt][0] * i0, ao[nt][1] * i0, &H, &L);
        *(__nv_bfloat162*)(OH + oA) = H;
        *(__nv_bfloat162*)(OL + oA) = L;
        split2(ao[nt][2] * i1, ao[nt][3] * i1, &H, &L);
        *(__nv_bfloat162*)(OH + oB) = H;
        *(__nv_bfloat162*)(OL + oB) = L;
    }
}

// ---------------- host launch ----------------
extern "C" void kernel_launch(void* const* d_in, const int* in_sizes, int n_in,
                              void* d_out, int out_size)
{
    const float* hidden  = (const float*)d_in[0];
    const float* norm1_w = (const float*)d_in[2];
    const float* wq      = (const float*)d_in[3];
    const float* wk      = (const float*)d_in[4];
    const float* wv      = (const float*)d_in[5];
    const float* wo      = (const float*)d_in[6];
    const float* norm2_w = (const float*)d_in[7];
    const float* w_gate  = (const float*)d_in[8];
    const float* w_up    = (const float*)d_in[9];
    const float* w_down  = (const float*)d_in[10];
    float* out = (float*)d_out;

    float *res2, *gate, *upb;
    __nv_bfloat16 *a_hi, *a_lo, *w_hi, *w_lo;
    __nv_bfloat16 *qh, *ql, *kh, *kl, *vth, *vtl;
    cudaGetSymbolAddress((void**)&res2, g_res2);
    cudaGetSymbolAddress((void**)&gate, g_gate);
    cudaGetSymbolAddress((void**)&upb,  g_up);
    cudaGetSymbolAddress((void**)&a_hi, g_a_hi);
    cudaGetSymbolAddress((void**)&a_lo, g_a_lo);
    cudaGetSymbolAddress((void**)&w_hi, g_w_hi);
    cudaGetSymbolAddress((void**)&w_lo, g_w_lo);
    cudaGetSymbolAddress((void**)&qh,   g_qh);
    cudaGetSymbolAddress((void**)&ql,   g_ql);
    cudaGetSymbolAddress((void**)&kh,   g_kh);
    cudaGetSymbolAddress((void**)&kl,   g_kl);
    cudaGetSymbolAddress((void**)&vth,  g_vth);
    cudaGetSymbolAddress((void**)&vtl,  g_vtl);

    float* qkv = gate;                                   // fp32 [ROWS][3072], freed before MLP
    __nv_bfloat16* m_hi = (__nv_bfloat16*)upb;           // [ROWS*FF]
    __nv_bfloat16* m_lo = m_hi + (size_t)ROWS * FF;

    // weight pool offsets (elements)
    const size_t OQKV = 0;                    // 3072 x 2048
    const size_t OWO  = 6ull * MEG;           // 2048 x 2048
    const size_t OWG  = 10ull * MEG;          // 8192 x 2048
    const size_t OWU  = 26ull * MEG;
    const size_t OWD  = 42ull * MEG;          // 2048 x 8192

    cudaFuncSetAttribute(hmma_gemm_kernel<0>, cudaFuncAttributeMaxDynamicSharedMemorySize, GSMEM);
    cudaFuncSetAttribute(hmma_gemm_kernel<1>, cudaFuncAttributeMaxDynamicSharedMemorySize, GSMEM);
    cudaFuncSetAttribute(hmma_gemm_kernel<2>, cudaFuncAttributeMaxDynamicSharedMemorySize, GSMEM);
    cudaFuncSetAttribute(attn_mma_kernel, cudaFuncAttributeMaxDynamicSharedMemorySize, AT_SMEM);

    // ---- weight transpose + split (QKV concatenated: rows 0..2047 Q, 2048..2559 K, 2560..3071 V) ----
    convT_kernel<<<dim3(64, 64), 256>>>(wq, w_hi + OQKV, w_lo + OQKV, 2048, 2048);
    convT_kernel<<<dim3(16, 64), 256>>>(wk, w_hi + OQKV + 2048ull * 2048, w_lo + OQKV + 2048ull * 2048, 2048, 512);
    convT_kernel<<<dim3(16, 64), 256>>>(wv, w_hi + OQKV + 2560ull * 2048, w_lo + OQKV + 2560ull * 2048, 2048, 512);
    convT_kernel<<<dim3(64, 64), 256>>>(wo,     w_hi + OWO, w_lo + OWO, 2048, 2048);
    convT_kernel<<<dim3(256, 64), 256>>>(w_gate, w_hi + OWG, w_lo + OWG, 2048, 8192);
    convT_kernel<<<dim3(256, 64), 256>>>(w_up,   w_hi + OWU, w_lo + OWU, 2048, 8192);
    convT_kernel<<<dim3(64, 256), 256>>>(w_down, w_hi + OWD, w_lo + OWD, 8192, 2048);

    // ---- 1. rmsnorm1 -> split ----
    rmsnorm_split_kernel<<<ROWS, 256>>>(hidden, norm1_w, a_hi, a_lo, HID);

    // ---- 2. fused QKV GEMM -> qkv fp32 [ROWS][3072] ----
    hmma_gemm_kernel<0><<<dim3(3072 / 256, ROWS / 128), 256, GSMEM>>>(
        a_hi, a_lo, w_hi + OQKV, w_lo + OQKV, nullptr, qkv, nullptr, nullptr, 3072, 2048);

    // ---- 3. RoPE + scale + split; V transpose + split ----
    rope_split_kernel<NH, 1, 0><<<ROWS, NH * 32>>>(qkv, qh, ql);
    rope_split_kernel<NKVH, 0, 2048><<<ROWS, NKVH * 32>>>(qkv, kh, kl);
    vt_split_kernel<<<dim3(SEQ / 32, 2, NB * NKVH), dim3(32, 8)>>>(qkv, vth, vtl);

    // ---- 4. attention -> ctx split (a_hi/a_lo) ----
    attn_mma_kernel<<<dim3(SEQ / 64, NH, NB), 128, AT_SMEM>>>(qh, ql, kh, kl, vth, vtl, a_hi, a_lo);

    // ---- 5. output projection + residual -> res2 fp32 ----
    hmma_gemm_kernel<1><<<dim3(2048 / 256, ROWS / 128), 256, GSMEM>>>(
        a_hi, a_lo, w_hi + OWO, w_lo + OWO, hidden, res2, nullptr, nullptr, 2048, 2048);

    // ---- 6. rmsnorm2 -> split ----
    rmsnorm_split_kernel<<<ROWS, 256>>>(res2, norm2_w, a_hi, a_lo, HID);

    // ---- 7. gate GEMM -> fp32 ----
    hmma_gemm_kernel<0><<<dim3(FF / 256, ROWS / 128), 256, GSMEM>>>(
        a_hi, a_lo, w_hi + OWG, w_lo + OWG, nullptr, gate, nullptr, nullptr, FF, 2048);

    // ---- 8. up GEMM + fused silu(gate)*up -> split (m_hi/m_lo) ----
    hmma_gemm_kernel<2><<<dim3(FF / 256, ROWS / 128), 256, GSMEM>>>(
        a_hi, a_lo, w_hi + OWU, w_lo + OWU, gate, nullptr, m_hi, m_lo, FF, 2048);

    // ---- 9. down projection + residual -> out ----
    hmma_gemm_kernel<1><<<dim3(2048 / 256, ROWS / 128), 256, GSMEM>>>(
        m_hi, m_lo, w_hi + OWD, w_lo + OWD, res2, out, nullptr, nullptr, 2048, 8192);
}

// round 7
// speedup vs baseline: 4.4717x; 1.3774x over previous
#include <cuda_runtime.h>
#include <cuda_bf16.h>
#include <cuda_fp16.h>
#include <math.h>
#include <stdint.h>

// ---------------- problem constants ----------------
#define HID   2048
#define NH    32
#define NKVH  8
#define HD    64
#define FF    8192
#define SEQ   2048
#define NB    2
#define ROWS  4096
#define EPS   1e-6f
#define MEG   (1024*1024)
#define L2E   1.4426950408889634f

// ---------------- scratch (device globals; no allocs allowed) ----------------
__device__ float g_res2[(size_t)ROWS * 2048];
__device__ float g_gate[(size_t)ROWS * FF];          // also holds qkv fp32 [ROWS][3072] early
__device__ float g_up  [(size_t)ROWS * FF];          // reused as fp16 m_hi/m_lo halves

// fp16 activation split + single-fp16 weights
__device__ __half g_a_hi[(size_t)ROWS * HID];
__device__ __half g_a_lo[(size_t)ROWS * HID];
__device__ __half g_w   [(size_t)58 * MEG];

// attention bf16 split operands (3-term path, unchanged)
__device__ __nv_bfloat16 g_qh[(size_t)ROWS * 2048];
__device__ __nv_bfloat16 g_ql[(size_t)ROWS * 2048];
__device__ __nv_bfloat16 g_kh[(size_t)ROWS * 512];
__device__ __nv_bfloat16 g_kl[(size_t)ROWS * 512];
__device__ __nv_bfloat16 g_vth[(size_t)ROWS * 512];
__device__ __nv_bfloat16 g_vtl[(size_t)ROWS * 512];

// ---------------- helpers ----------------
__device__ __forceinline__ uint32_t smem_u32(const void* p) {
    uint32_t a;
    asm("{ .reg .u64 t; cvta.to.shared.u64 t, %1; cvt.u32.u64 %0, t; }" : "=r"(a) : "l"(p));
    return a;
}

__device__ __forceinline__ void cpa16(uint32_t dst, const void* src) {
    asm volatile("cp.async.cg.shared.global [%0], [%1], 16;" :: "r"(dst), "l"(src));
}
__device__ __forceinline__ void cpa_commit() {
    asm volatile("cp.async.commit_group;" ::: "memory");
}

__device__ __forceinline__ void ldsm4(uint32_t* r, uint32_t addr) {
    asm volatile("ldmatrix.sync.aligned.m8n8.x4.shared.b16 {%0,%1,%2,%3}, [%4];"
        : "=r"(r[0]), "=r"(r[1]), "=r"(r[2]), "=r"(r[3]) : "r"(addr));
}

// bf16 mma (attention)
__device__ __forceinline__ void mma_bf16(float* c, const uint32_t* a, const uint32_t* b) {
    asm volatile("mma.sync.aligned.m16n8k16.row.col.f32.bf16.bf16.f32 "
        "{%0,%1,%2,%3}, {%4,%5,%6,%7}, {%8,%9}, {%0,%1,%2,%3};"
        : "+f"(c[0]), "+f"(c[1]), "+f"(c[2]), "+f"(c[3])
        : "r"(a[0]), "r"(a[1]), "r"(a[2]), "r"(a[3]), "r"(b[0]), "r"(b[1]));
}

// fp16 mma (GEMMs)
__device__ __forceinline__ void mma_f16(float* c, const uint32_t* a, const uint32_t* b) {
    asm volatile("mma.sync.aligned.m16n8k16.row.col.f32.f16.f16.f32 "
        "{%0,%1,%2,%3}, {%4,%5,%6,%7}, {%8,%9}, {%0,%1,%2,%3};"
        : "+f"(c[0]), "+f"(c[1]), "+f"(c[2]), "+f"(c[3])
        : "r"(a[0]), "r"(a[1]), "r"(a[2]), "r"(a[3]), "r"(b[0]), "r"(b[1]));
}

__device__ __forceinline__ void split2b(float x0, float x1, __nv_bfloat162* hi, __nv_bfloat162* lo) {
    __nv_bfloat16 h0 = __float2bfloat16(x0);
    __nv_bfloat16 h1 = __float2bfloat16(x1);
    __nv_bfloat16 l0 = __float2bfloat16(x0 - __bfloat162float(h0));
    __nv_bfloat16 l1 = __float2bfloat16(x1 - __bfloat162float(h1));
    hi->x = h0; hi->y = h1; lo->x = l0; lo->y = l1;
}

__device__ __forceinline__ void split2h(float x0, float x1, __half2* hi, __half2* lo) {
    __half h0 = __float2half_rn(x0);
    __half h1 = __float2half_rn(x1);
    __half l0 = __float2half_rn(x0 - __half2float(h0));
    __half l1 = __float2half_rn(x1 - __half2float(h1));
    hi->x = h0; hi->y = h1; lo->x = l0; lo->y = l1;
}

// FMA-only exp2, clamped both sides, |rel err| ~2e-6
__device__ __forceinline__ float fexp2(float z) {
    z = fminf(fmaxf(z, -126.f), 126.f);
    float sh = z + 12582912.f;
    float zi = sh - 12582912.f;
    float f = z - zi;
    float p = 0.0013333558f;
    p = p * f + 0.0096181291f;
    p = p * f + 0.0555041087f;
    p = p * f + 0.2402265070f;
    p = p * f + 0.6931471806f;
    p = p * f + 1.0f;
    int ei = __float_as_int(sh) - 0x4B400000;
    return p * __int_as_float((ei + 127) << 23);
}

__device__ __forceinline__ float fsilu(float x) {
    return x / (1.f + fexp2(-x * L2E));
}

// ---------------- converters ----------------
// W [K,N] fp32 -> Wt [N,K] fp16 (single)
__global__ void convT_kernel(const float* __restrict__ W,
                             __half* __restrict__ wT, int K, int N)
{
    __shared__ float t[32][33];
    int n0 = blockIdx.x * 32, k0 = blockIdx.y * 32;
    int tx = threadIdx.x & 31, ty = threadIdx.x >> 5;
    for (int ky = ty; ky < 32; ky += 8)
        t[ky][tx] = W[(size_t)(k0 + ky) * N + n0 + tx];
    __syncthreads();
    for (int ny = ty; ny < 32; ny += 8) {
        float x = t[tx][ny];
        wT[(size_t)(n0 + ny) * K + k0 + tx] = __float2half_rn(x);
    }
}

// RMSNorm -> fp16 split
__global__ void rmsnorm_split_kernel(const float* __restrict__ x,
                                     const float* __restrict__ w,
                                     __half* __restrict__ hi,
                                     __half* __restrict__ lo, int K)
{
    int row = blockIdx.x;
    const float* xr = x + (size_t)row * K;
    float ss = 0.f;
    int nvec = K / 4;
    const float4* xv = (const float4*)xr;
    for (int c = threadIdx.x; c < nvec; c += blockDim.x) {
        float4 v = xv[c];
        ss += v.x * v.x + v.y * v.y + v.z * v.z + v.w * v.w;
    }
    __shared__ float red[32];
    for (int off = 16; off > 0; off >>= 1) ss += __shfl_xor_sync(0xffffffffu, ss, off);
    int lane = threadIdx.x & 31, wid = threadIdx.x >> 5;
    if (lane == 0) red[wid] = ss;
    __syncthreads();
    int nwarp = blockDim.x >> 5;
    if (wid == 0) {
        float t = (lane < nwarp) ? red[lane] : 0.f;
        for (int off = 16; off > 0; off >>= 1) t += __shfl_xor_sync(0xffffffffu, t, off);
        if (lane == 0) red[0] = t;
    }
    __syncthreads();
    float inv = rsqrtf(red[0] / (float)K + EPS);

    for (int c = threadIdx.x; c < K / 2; c += blockDim.x) {
        int k = 2 * c;
        float x0 = xr[k] * inv * w[k];
        float x1 = xr[k + 1] * inv * w[k + 1];
        __half2 h, l;
        split2h(x0, x1, &h, &l);
        ((__half2*)(hi + (size_t)row * K))[c] = h;
        ((__half2*)(lo + (size_t)row * K))[c] = l;
    }
}

// RoPE + scale + split (bf16, attention path); reads qkv fp32 [row][3072] at col COFF
template<int NHEADS, int SCALE, int COFF>
__global__ void rope_split_kernel(const float* __restrict__ x,
                                  __nv_bfloat16* __restrict__ hi,
                                  __nv_bfloat16* __restrict__ lo)
{
    int row = blockIdx.x;
    int b = row >> 11, s = row & 2047;
    int t = threadIdx.x;
    int h = t >> 5, i = t & 31;
    float inv_freq = powf(10000.0f, -(float)(2 * i) / 64.0f);
    float ang = (float)s * inv_freq;
    float c, sn;
    __sincosf(ang, &sn, &c);
    const float* p = x + (size_t)row * 3072 + COFF + h * HD;
    float x1 = p[i], x2 = p[i + 32];
    float o1 = x1 * c - x2 * sn;
    float o2 = x2 * c + x1 * sn;
    if (SCALE) { o1 *= 0.125f; o2 *= 0.125f; }
    size_t dst = ((size_t)(b * NHEADS + h) * SEQ + s) * 64;
    __nv_bfloat16 h1 = __float2bfloat16(o1);
    __nv_bfloat16 h2 = __float2bfloat16(o2);
    hi[dst + i]      = h1;
    hi[dst + i + 32] = h2;
    lo[dst + i]      = __float2bfloat16(o1 - __bfloat162float(h1));
    lo[dst + i + 32] = __float2bfloat16(o2 - __bfloat162float(h2));
}

// V transpose + split (bf16): qkv fp32 col 2560+ -> vt [b,kvh,d,s]
__global__ void vt_split_kernel(const float* __restrict__ v,
                                __nv_bfloat16* __restrict__ hiT,
                                __nv_bfloat16* __restrict__ loT)
{
    __shared__ float t[32][33];
    int s0 = blockIdx.x * 32, d0 = blockIdx.y * 32;
    int bz = blockIdx.z;
    int b = bz >> 3, kvh = bz & 7;
    int tx = threadIdx.x, ty = threadIdx.y;
    for (int sy = ty; sy < 32; sy += 8)
        t[sy][tx] = v[(size_t)(b * SEQ + s0 + sy) * 3072 + 2560 + kvh * 64 + d0 + tx];
    __syncthreads();
    for (int dy = ty; dy < 32; dy += 8) {
        float x = t[tx][dy];
        __nv_bfloat16 h = __float2bfloat16(x);
        __nv_bfloat16 l = __float2bfloat16(x - __bfloat162float(h));
        size_t o = ((size_t)bz * 64 + d0 + dy) * SEQ + s0 + tx;
        hiT[o] = h; loT[o] = l;
    }
}

// ---------------- HMMA GEMM: 128(M) x 256(N) tile, BK=32, 4-stage, fp16 2-term ----------------
// A split (hi/lo fp16), B single fp16.
// EPI 0: C = A@B^T (fp32)
// EPI 1: C = A@B^T + RES (fp32)
// EPI 2: OH/OL = split(silu(RES) * (A@B^T))   (RES = gate fp32; C unused)
#define APITCH 80
#define A_MAT  10240          // 128 * 80
#define B_MAT  20480          // 256 * 80
#define STG_SZ (2 * A_MAT + B_MAT)       // 40960
#define GSMEM  (4 * STG_SZ)               // 163840

template<int EPI>
__global__ void __launch_bounds__(256, 1)
hmma_gemm_kernel(const __half* __restrict__ Ah, const __half* __restrict__ Al,
                 const __half* __restrict__ B,
                 const float* __restrict__ RES, float* __restrict__ C,
                 __half* __restrict__ OH, __half* __restrict__ OL,
                 int N, int K)
{
    extern __shared__ char sm[];
    uint32_t smb = smem_u32(sm);
    int tid = threadIdx.x, lane = tid & 31, wid = tid >> 5;
    int wm = wid & 3, wn = wid >> 2;          // warp tile 32(M) x 128(N)
    int bm = blockIdx.y, bn = blockIdx.x;
    int NKT = K / 32;

    const __half* gAh = Ah + (size_t)bm * 128 * K;
    const __half* gAl = Al + (size_t)bm * 128 * K;
    const __half* gB  = B  + (size_t)bn * 256 * K;

    int rbase = tid >> 2;      // 0..63
    int ch = tid & 3;          // 16B chunk within 64B row

    auto issue = [&](int st, int kt) {
        uint32_t base = smb + st * STG_SZ;
        int koff = kt * 32 + ch * 8;
#pragma unroll
        for (int u = 0; u < 2; u++) {
            int r = rbase + u * 64;
            cpa16(base + 0 * A_MAT + r * APITCH + ch * 16, gAh + (size_t)r * K + koff);
            cpa16(base + 1 * A_MAT + r * APITCH + ch * 16, gAl + (size_t)r * K + koff);
        }
        uint32_t bB = base + 2 * A_MAT;
#pragma unroll
        for (int u = 0; u < 4; u++) {
            int r = rbase + u * 64;
            cpa16(bB + r * APITCH + ch * 16, gB + (size_t)r * K + koff);
        }
        cpa_commit();
    };

    float acc[2][16][4];
#pragma unroll
    for (int s = 0; s < 2; s++)
#pragma unroll
        for (int t = 0; t < 16; t++)
#pragma unroll
            for (int j = 0; j < 4; j++) acc[s][t][j] = 0.f;

    issue(0, 0);
    issue(1, 1);
    issue(2, 2);

    int a_row = wm * 32 + (lane & 15);
    int a_kb  = (lane >> 4) * 16;
    int b_ro  = ((lane >> 4) << 3) + (lane & 7);
    int b_kb  = ((lane >> 3) & 1) * 16;

    for (int kt = 0; kt < NKT; kt++) {
        int st = kt & 3;
        if (kt + 3 < NKT) issue((kt + 3) & 3, kt + 3);
        else cpa_commit();
        asm volatile("cp.async.wait_group 3;" ::: "memory");
        __syncthreads();

        uint32_t sAh = smb + st * STG_SZ;
        uint32_t sAl = sAh + A_MAT;
        uint32_t sB  = sAl + A_MAT;

#pragma unroll
        for (int ks = 0; ks < 2; ks++) {
            int kB = ks * 32;
            uint32_t ah[2][4], al[2][4];
            ldsm4(ah[0], sAh + (a_row)      * APITCH + kB + a_kb);
            ldsm4(ah[1], sAh + (a_row + 16) * APITCH + kB + a_kb);
            ldsm4(al[0], sAl + (a_row)      * APITCH + kB + a_kb);
            ldsm4(al[1], sAl + (a_row + 16) * APITCH + kB + a_kb);
#pragma unroll
            for (int gi = 0; gi < 8; gi++) {
                int brow = wn * 128 + gi * 16 + b_ro;
                uint32_t b4[4];
                ldsm4(b4, sB + brow * APITCH + kB + b_kb);
#pragma unroll
                for (int t = 0; t < 2; t++) {
                    const uint32_t* bp = &b4[t * 2];
#pragma unroll
                    for (int sub = 0; sub < 2; sub++) {
                        mma_f16(acc[sub][gi * 2 + t], ah[sub], bp);
                        mma_f16(acc[sub][gi * 2 + t], al[sub], bp);
                    }
                }
            }
        }
        __syncthreads();
    }

    // epilogue
#pragma unroll
    for (int sub = 0; sub < 2; sub++) {
        int row0 = bm * 128 + wm * 32 + sub * 16 + (lane >> 2);
#pragma unroll
        for (int t = 0; t < 16; t++) {
            int col = bn * 256 + wn * 128 + t * 8 + (lane & 3) * 2;
            size_t o0 = (size_t)row0 * N + col;
            size_t o1 = o0 + (size_t)8 * N;
            if (EPI == 2) {
                float2 G0 = *(const float2*)(RES + o0);
                float2 G1 = *(const float2*)(RES + o1);
                float x0 = fsilu(G0.x) * acc[sub][t][0];
                float x1 = fsilu(G0.y) * acc[sub][t][1];
                float x2 = fsilu(G1.x) * acc[sub][t][2];
                float x3 = fsilu(G1.y) * acc[sub][t][3];
                __half2 H, L;
                split2h(x0, x1, &H, &L);
                *(__half2*)(OH + o0) = H;
                *(__half2*)(OL + o0) = L;
                split2h(x2, x3, &H, &L);
                *(__half2*)(OH + o1) = H;
                *(__half2*)(OL + o1) = L;
            } else {
                float2 v0 = make_float2(acc[sub][t][0], acc[sub][t][1]);
                float2 v1 = make_float2(acc[sub][t][2], acc[sub][t][3]);
                if (EPI == 1) {
                    float2 r0 = *(const float2*)(RES + o0);
                    float2 r1 = *(const float2*)(RES + o1);
                    v0.x += r0.x; v0.y += r0.y;
                    v1.x += r1.x; v1.y += r1.y;
                }
                *(float2*)(C + o0) = v0;
                *(float2*)(C + o1) = v1;
            }
        }
    }
}

// ---------------- tensor-core causal attention (bf16 3-term; writes fp16 ctx split) ----------------
#define AT_PITCH 144
#define AT_MAT   (64 * AT_PITCH)
#define AT_QH 0
#define AT_QL (AT_MAT)
#define AT_KH (2 * AT_MAT)
#define AT_KL (3 * AT_MAT)
#define AT_VH (4 * AT_MAT)
#define AT_VL (5 * AT_MAT)
#define AT_SMEM (6 * AT_MAT)

__global__ void __launch_bounds__(128)
attn_mma_kernel(const __nv_bfloat16* __restrict__ qh, const __nv_bfloat16* __restrict__ ql,
                const __nv_bfloat16* __restrict__ kh, const __nv_bfloat16* __restrict__ kl,
                const __nv_bfloat16* __restrict__ vth, const __nv_bfloat16* __restrict__ vtl,
                __half* __restrict__ OH, __half* __restrict__ OL)
{
    extern __shared__ char sm[];
    uint32_t smb = smem_u32(sm);
    int qt = blockIdx.x, h = blockIdx.y, b = blockIdx.z;
    int kvh = h >> 2;
    int tid = threadIdx.x, lane = tid & 31, w = tid >> 5;
    int q0 = qt * 64;

    const __nv_bfloat16* Qhp = qh + ((size_t)(b * NH + h) * SEQ + q0) * 64;
    const __nv_bfloat16* Qlp = ql + ((size_t)(b * NH + h) * SEQ + q0) * 64;
    const __nv_bfloat16* Khp = kh + ((size_t)(b * NKVH + kvh) * SEQ) * 64;
    const __nv_bfloat16* Klp = kl + ((size_t)(b * NKVH + kvh) * SEQ) * 64;
    const __nv_bfloat16* Vhp = vth + ((size_t)(b * NKVH + kvh) * 64) * SEQ;
    const __nv_bfloat16* Vlp = vtl + ((size_t)(b * NKVH + kvh) * 64) * SEQ;

#pragma unroll
    for (int it = 0; it < 4; it++) {
        int idx = it * 128 + tid;
        int r = idx >> 3, ch = idx & 7;
        cpa16(smb + AT_QH + r * AT_PITCH + ch * 16, Qhp + (size_t)r * 64 + ch * 8);
        cpa16(smb + AT_QL + r * AT_PITCH + ch * 16, Qlp + (size_t)r * 64 + ch * 8);
    }
    cpa_commit();

    float m0 = -1e30f, m1 = -1e30f, l0 = 0.f, l1 = 0.f;
    float ao[8][4];
#pragma unroll
    for (int nt = 0; nt < 8; nt++)
#pragma unroll
        for (int j = 0; j < 4; j++) ao[nt][j] = 0.f;

    int r0 = lane >> 2, cq = lane & 3;
    int a_row = w * 16 + (lane & 15);
    int a_kb  = (lane >> 4) * 16;
    int b_ro  = ((lane >> 4) << 3) + (lane & 7);
    int b_kb  = ((lane >> 3) & 1) * 16;

    for (int kt = 0; kt <= qt; kt++) {
        int k0 = kt * 64;
#pragma unroll
        for (int it = 0; it < 4; it++) {
            int idx = it * 128 + tid;
            int r = idx >> 3, ch = idx & 7;
            cpa16(smb + AT_KH + r * AT_PITCH + ch * 16, Khp + (size_t)(k0 + r) * 64 + ch * 8);
            cpa16(smb + AT_KL + r * AT_PITCH + ch * 16, Klp + (size_t)(k0 + r) * 64 + ch * 8);
            cpa16(smb + AT_VH + r * AT_PITCH + ch * 16, Vhp + (size_t)r * SEQ + k0 + ch * 8);
            cpa16(smb + AT_VL + r * AT_PITCH + ch * 16, Vlp + (size_t)r * SEQ + k0 + ch * 8);
        }
        cpa_commit();
        asm volatile("cp.async.wait_group 0;" ::: "memory");
        __syncthreads();

        float sc[8][4];
#pragma unroll
        for (int nt = 0; nt < 8; nt++)
#pragma unroll
            for (int j = 0; j < 4; j++) sc[nt][j] = 0.f;

#pragma unroll
        for (int kc = 0; kc < 4; kc++) {
            uint32_t ah4[4], al4[4];
            ldsm4(ah4, smb + AT_QH + a_row * AT_PITCH + kc * 32 + a_kb);
            ldsm4(al4, smb + AT_QL + a_row * AT_PITCH + kc * 32 + a_kb);
#pragma unroll
            for (int gi = 0; gi < 4; gi++) {
                uint32_t kh4[4], kl4[4];
                ldsm4(kh4, smb + AT_KH + (gi * 16 + b_ro) * AT_PITCH + kc * 32 + b_kb);
                ldsm4(kl4, smb + AT_KL + (gi * 16 + b_ro) * AT_PITCH + kc * 32 + b_kb);
#pragma unroll
                for (int t = 0; t < 2; t++) {
                    mma_bf16(sc[gi * 2 + t], ah4, &kh4[t * 2]);
                    mma_bf16(sc[gi * 2 + t], ah4, &kl4[t * 2]);
                    mma_bf16(sc[gi * 2 + t], al4, &kh4[t * 2]);
                }
            }
        }

        if (kt == qt) {
            int qr0 = w * 16 + r0, qr1 = qr0 + 8;
#pragma unroll
            for (int nt = 0; nt < 8; nt++) {
                int col = nt * 8 + cq * 2;
                if (col     > qr0) sc[nt][0] = -1e30f;
                if (col + 1 > qr0) sc[nt][1] = -1e30f;
                if (col     > qr1) sc[nt][2] = -1e30f;
                if (col + 1 > qr1) sc[nt][3] = -1e30f;
            }
        }

        float tm0 = -1e30f, tm1 = -1e30f;
#pragma unroll
        for (int nt = 0; nt < 8; nt++) {
            tm0 = fmaxf(tm0, fmaxf(sc[nt][0], sc[nt][1]));
            tm1 = fmaxf(tm1, fmaxf(sc[nt][2], sc[nt][3]));
        }
        tm0 = fmaxf(tm0, __shfl_xor_sync(0xffffffffu, tm0, 1));
        tm0 = fmaxf(tm0, __shfl_xor_sync(0xffffffffu, tm0, 2));
        tm1 = fmaxf(tm1, __shfl_xor_sync(0xffffffffu, tm1, 1));
        tm1 = fmaxf(tm1, __shfl_xor_sync(0xffffffffu, tm1, 2));
        float mn0 = fmaxf(m0, tm0), mn1 = fmaxf(m1, tm1);
        float cr0 = fexp2((m0 - mn0) * L2E);
        float cr1 = fexp2((m1 - mn1) * L2E);
        float rs0 = 0.f, rs1 = 0.f;
#pragma unroll
        for (int nt = 0; nt < 8; nt++) {
            sc[nt][0] = fexp2((sc[nt][0] - mn0) * L2E);
            sc[nt][1] = fexp2((sc[nt][1] - mn0) * L2E);
            sc[nt][2] = fexp2((sc[nt][2] - mn1) * L2E);
            sc[nt][3] = fexp2((sc[nt][3] - mn1) * L2E);
            rs0 += sc[nt][0] + sc[nt][1];
            rs1 += sc[nt][2] + sc[nt][3];
        }
        rs0 += __shfl_xor_sync(0xffffffffu, rs0, 1);
        rs0 += __shfl_xor_sync(0xffffffffu, rs0, 2);
        rs1 += __shfl_xor_sync(0xffffffffu, rs1, 1);
        rs1 += __shfl_xor_sync(0xffffffffu, rs1, 2);
        l0 = l0 * cr0 + rs0;
        l1 = l1 * cr1 + rs1;
        m0 = mn0; m1 = mn1;
#pragma unroll
        for (int nt = 0; nt < 8; nt++) {
            ao[nt][0] *= cr0; ao[nt][1] *= cr0;
            ao[nt][2] *= cr1; ao[nt][3] *= cr1;
        }

#pragma unroll
        for (int j = 0; j < 4; j++) {
            uint32_t pah[4], pal[4];
#pragma unroll
            for (int u = 0; u < 2; u++) {
                __nv_bfloat162 H, L;
                split2b(sc[2 * j + u][0], sc[2 * j + u][1], &H, &L);
                pah[2 * u + 0] = *(uint32_t*)&H; pal[2 * u + 0] = *(uint32_t*)&L;
                split2b(sc[2 * j + u][2], sc[2 * j + u][3], &H, &L);
                pah[2 * u + 1] = *(uint32_t*)&H; pal[2 * u + 1] = *(uint32_t*)&L;
            }
#pragma unroll
            for (int gi = 0; gi < 4; gi++) {
                uint32_t vh4[4], vl4[4];
                ldsm4(vh4, smb + AT_VH + (gi * 16 + b_ro) * AT_PITCH + j * 32 + b_kb);
                ldsm4(vl4, smb + AT_VL + (gi * 16 + b_ro) * AT_PITCH + j * 32 + b_kb);
#pragma unroll
                for (int t = 0; t < 2; t++) {
                    mma_bf16(ao[gi * 2 + t], pah, &vh4[t * 2]);
                    mma_bf16(ao[gi * 2 + t], pah, &vl4[t * 2]);
                    mma_bf16(ao[gi * 2 + t], pal, &vh4[t * 2]);
                }
            }
        }
        __syncthreads();
    }

    float i0 = 1.f / l0, i1 = 1.f / l1;
    int rowA = q0 + w * 16 + r0;
    int rowB = rowA + 8;
#pragma unroll
    for (int nt = 0; nt < 8; nt++) {
        int col = h * 64 + nt * 8 + cq * 2;
        size_t oA = ((size_t)(b * SEQ) + rowA) * 2048 + col;
        size_t oB = ((size_t)(b * SEQ) + rowB) * 2048 + col;
        __half2 H, L;
        split2h(ao[nt][0] * i0, ao[nt][1] * i0, &H, &L);
        *(__half2*)(OH + oA) = H;
        *(__half2*)(OL + oA) = L;
        split2h(ao[nt][2] * i1, ao[nt][3] * i1, &H, &L);
        *(__half2*)(OH + oB) = H;
        *(__half2*)(OL + oB) = L;
    }
}

// ---------------- host launch ----------------
extern "C" void kernel_launch(void* const* d_in, const int* in_sizes, int n_in,
                              void* d_out, int out_size)
{
    const float* hidden  = (const float*)d_in[0];
    const float* norm1_w = (const float*)d_in[2];
    const float* wq      = (const float*)d_in[3];
    const float* wk      = (const float*)d_in[4];
    const float* wv      = (const float*)d_in[5];
    const float* wo      = (const float*)d_in[6];
    const float* norm2_w = (const float*)d_in[7];
    const float* w_gate  = (const float*)d_in[8];
    const float* w_up    = (const float*)d_in[9];
    const float* w_down  = (const float*)d_in[10];
    float* out = (float*)d_out;

    float *res2, *gate, *upb;
    __half *a_hi, *a_lo, *wpool;
    __nv_bfloat16 *qh, *ql, *kh, *kl, *vth, *vtl;
    cudaGetSymbolAddress((void**)&res2, g_res2);
    cudaGetSymbolAddress((void**)&gate, g_gate);
    cudaGetSymbolAddress((void**)&upb,  g_up);
    cudaGetSymbolAddress((void**)&a_hi, g_a_hi);
    cudaGetSymbolAddress((void**)&a_lo, g_a_lo);
    cudaGetSymbolAddress((void**)&wpool, g_w);
    cudaGetSymbolAddress((void**)&qh,   g_qh);
    cudaGetSymbolAddress((void**)&ql,   g_ql);
    cudaGetSymbolAddress((void**)&kh,   g_kh);
    cudaGetSymbolAddress((void**)&kl,   g_kl);
    cudaGetSymbolAddress((void**)&vth,  g_vth);
    cudaGetSymbolAddress((void**)&vtl,  g_vtl);

    float* qkv = gate;                          // fp32 [ROWS][3072], freed before MLP
    __half* m_hi = (__half*)upb;                // [ROWS*FF]
    __half* m_lo = m_hi + (size_t)ROWS * FF;

    // weight pool offsets (elements)
    const size_t OQKV = 0;                    // 3072 x 2048
    const size_t OWO  = 6ull * MEG;           // 2048 x 2048
    const size_t OWG  = 10ull * MEG;          // 8192 x 2048
    const size_t OWU  = 26ull * MEG;
    const size_t OWD  = 42ull * MEG;          // 2048 x 8192

    cudaFuncSetAttribute(hmma_gemm_kernel<0>, cudaFuncAttributeMaxDynamicSharedMemorySize, GSMEM);
    cudaFuncSetAttribute(hmma_gemm_kernel<1>, cudaFuncAttributeMaxDynamicSharedMemorySize, GSMEM);
    cudaFuncSetAttribute(hmma_gemm_kernel<2>, cudaFuncAttributeMaxDynamicSharedMemorySize, GSMEM);
    cudaFuncSetAttribute(attn_mma_kernel, cudaFuncAttributeMaxDynamicSharedMemorySize, AT_SMEM);

    // ---- weight transpose -> fp16 (QKV concatenated: rows 0..2047 Q, 2048..2559 K, 2560..3071 V) ----
    convT_kernel<<<dim3(64, 64), 256>>>(wq, wpool + OQKV, 2048, 2048);
    convT_kernel<<<dim3(16, 64), 256>>>(wk, wpool + OQKV + 2048ull * 2048, 2048, 512);
    convT_kernel<<<dim3(16, 64), 256>>>(wv, wpool + OQKV + 2560ull * 2048, 2048, 512);
    convT_kernel<<<dim3(64, 64), 256>>>(wo,     wpool + OWO, 2048, 2048);
    convT_kernel<<<dim3(256, 64), 256>>>(w_gate, wpool + OWG, 2048, 8192);
    convT_kernel<<<dim3(256, 64), 256>>>(w_up,   wpool + OWU, 2048, 8192);
    convT_kernel<<<dim3(64, 256), 256>>>(w_down, wpool + OWD, 8192, 2048);

    // ---- 1. rmsnorm1 -> fp16 split ----
    rmsnorm_split_kernel<<<ROWS, 256>>>(hidden, norm1_w, a_hi, a_lo, HID);

    // ---- 2. fused QKV GEMM -> qkv fp32 [ROWS][3072] ----
    hmma_gemm_kernel<0><<<dim3(3072 / 256, ROWS / 128), 256, GSMEM>>>(
        a_hi, a_lo, wpool + OQKV, nullptr, qkv, nullptr, nullptr, 3072, 2048);

    // ---- 3. RoPE + scale + split; V transpose + split (bf16 attention path) ----
    rope_split_kernel<NH, 1, 0><<<ROWS, NH * 32>>>(qkv, qh, ql);
    rope_split_kernel<NKVH, 0, 2048><<<ROWS, NKVH * 32>>>(qkv, kh, kl);
    vt_split_kernel<<<dim3(SEQ / 32, 2, NB * NKVH), dim3(32, 8)>>>(qkv, vth, vtl);

    // ---- 4. attention -> ctx fp16 split (a_hi/a_lo) ----
    attn_mma_kernel<<<dim3(SEQ / 64, NH, NB), 128, AT_SMEM>>>(qh, ql, kh, kl, vth, vtl, a_hi, a_lo);

    // ---- 5. output projection + residual -> res2 fp32 ----
    hmma_gemm_kernel<1><<<dim3(2048 / 256, ROWS / 128), 256, GSMEM>>>(
        a_hi, a_lo, wpool + OWO, hidden, res2, nullptr, nullptr, 2048, 2048);

    // ---- 6. rmsnorm2 -> fp16 split ----
    rmsnorm_split_kernel<<<ROWS, 256>>>(res2, norm2_w, a_hi, a_lo, HID);

    // ---- 7. gate GEMM -> fp32 ----
    hmma_gemm_kernel<0><<<dim3(FF / 256, ROWS / 128), 256, GSMEM>>>(
        a_hi, a_lo, wpool + OWG, nullptr, gate, nullptr, nullptr, FF, 2048);

    // ---- 8. up GEMM + fused silu(gate)*up -> fp16 split (m_hi/m_lo) ----
    hmma_gemm_kernel<2><<<dim3(FF / 256, ROWS / 128), 256, GSMEM>>>(
        a_hi, a_lo, wpool + OWU, gate, nullptr, m_hi, m_lo, FF, 2048);

    // ---- 9. down projection + residual -> out ----
    hmma_gemm_kernel<1><<<dim3(2048 / 256, ROWS / 128), 256, GSMEM>>>(
        m_hi, m_lo, wpool + OWD, res2, out, nullptr, nullptr, 2048, 8192);
}

// round 8
// speedup vs baseline: 6.3101x; 1.4111x over previous
#include <cuda_runtime.h>
#include <cuda_bf16.h>
#include <cuda_fp16.h>
#include <math.h>
#include <stdint.h>

// ---------------- problem constants ----------------
#define HID   2048
#define NH    32
#define NKVH  8
#define HD    64
#define FF    8192
#define SEQ   2048
#define NB    2
#define ROWS  4096
#define EPS   1e-6f
#define MEG   (1024*1024)
#define L2E   1.4426950408889634f

// ---------------- scratch (device globals; no allocs allowed) ----------------
__device__ float g_res2[(size_t)ROWS * 2048];
__device__ float g_gate[(size_t)ROWS * FF];          // also holds qkv fp32 [ROWS][3072] early
__device__ float g_up  [(size_t)ROWS * FF];          // reused as fp16 m buffer

// fp16 single-precision-term operands
__device__ __half g_a  [(size_t)ROWS * HID];
__device__ __half g_w  [(size_t)58 * MEG];

// attention bf16 split operands (3-term path, unchanged)
__device__ __nv_bfloat16 g_qh[(size_t)ROWS * 2048];
__device__ __nv_bfloat16 g_ql[(size_t)ROWS * 2048];
__device__ __nv_bfloat16 g_kh[(size_t)ROWS * 512];
__device__ __nv_bfloat16 g_kl[(size_t)ROWS * 512];
__device__ __nv_bfloat16 g_vth[(size_t)ROWS * 512];
__device__ __nv_bfloat16 g_vtl[(size_t)ROWS * 512];

// ---------------- helpers ----------------
__device__ __forceinline__ uint32_t smem_u32(const void* p) {
    uint32_t a;
    asm("{ .reg .u64 t; cvta.to.shared.u64 t, %1; cvt.u32.u64 %0, t; }" : "=r"(a) : "l"(p));
    return a;
}

__device__ __forceinline__ void cpa16(uint32_t dst, const void* src) {
    asm volatile("cp.async.cg.shared.global [%0], [%1], 16;" :: "r"(dst), "l"(src));
}
__device__ __forceinline__ void cpa_commit() {
    asm volatile("cp.async.commit_group;" ::: "memory");
}

__device__ __forceinline__ void ldsm4(uint32_t* r, uint32_t addr) {
    asm volatile("ldmatrix.sync.aligned.m8n8.x4.shared.b16 {%0,%1,%2,%3}, [%4];"
        : "=r"(r[0]), "=r"(r[1]), "=r"(r[2]), "=r"(r[3]) : "r"(addr));
}

__device__ __forceinline__ void mma_bf16(float* c, const uint32_t* a, const uint32_t* b) {
    asm volatile("mma.sync.aligned.m16n8k16.row.col.f32.bf16.bf16.f32 "
        "{%0,%1,%2,%3}, {%4,%5,%6,%7}, {%8,%9}, {%0,%1,%2,%3};"
        : "+f"(c[0]), "+f"(c[1]), "+f"(c[2]), "+f"(c[3])
        : "r"(a[0]), "r"(a[1]), "r"(a[2]), "r"(a[3]), "r"(b[0]), "r"(b[1]));
}

__device__ __forceinline__ void mma_f16(float* c, const uint32_t* a, const uint32_t* b) {
    asm volatile("mma.sync.aligned.m16n8k16.row.col.f32.f16.f16.f32 "
        "{%0,%1,%2,%3}, {%4,%5,%6,%7}, {%8,%9}, {%0,%1,%2,%3};"
        : "+f"(c[0]), "+f"(c[1]), "+f"(c[2]), "+f"(c[3])
        : "r"(a[0]), "r"(a[1]), "r"(a[2]), "r"(a[3]), "r"(b[0]), "r"(b[1]));
}

__device__ __forceinline__ void split2b(float x0, float x1, __nv_bfloat162* hi, __nv_bfloat162* lo) {
    __nv_bfloat16 h0 = __float2bfloat16(x0);
    __nv_bfloat16 h1 = __float2bfloat16(x1);
    __nv_bfloat16 l0 = __float2bfloat16(x0 - __bfloat162float(h0));
    __nv_bfloat16 l1 = __float2bfloat16(x1 - __bfloat162float(h1));
    hi->x = h0; hi->y = h1; lo->x = l0; lo->y = l1;
}

// FMA-only exp2, clamped both sides, |rel err| ~2e-6
__device__ __forceinline__ float fexp2(float z) {
    z = fminf(fmaxf(z, -126.f), 126.f);
    float sh = z + 12582912.f;
    float zi = sh - 12582912.f;
    float f = z - zi;
    float p = 0.0013333558f;
    p = p * f + 0.0096181291f;
    p = p * f + 0.0555041087f;
    p = p * f + 0.2402265070f;
    p = p * f + 0.6931471806f;
    p = p * f + 1.0f;
    int ei = __float_as_int(sh) - 0x4B400000;
    return p * __int_as_float((ei + 127) << 23);
}

__device__ __forceinline__ float fsilu(float x) {
    return x / (1.f + fexp2(-x * L2E));
}

// ---------------- converters ----------------
// W [K,N] fp32 -> Wt [N,K] fp16
__global__ void convT_kernel(const float* __restrict__ W,
                             __half* __restrict__ wT, int K, int N)
{
    __shared__ float t[32][33];
    int n0 = blockIdx.x * 32, k0 = blockIdx.y * 32;
    int tx = threadIdx.x & 31, ty = threadIdx.x >> 5;
    for (int ky = ty; ky < 32; ky += 8)
        t[ky][tx] = W[(size_t)(k0 + ky) * N + n0 + tx];
    __syncthreads();
    for (int ny = ty; ny < 32; ny += 8) {
        float x = t[tx][ny];
        wT[(size_t)(n0 + ny) * K + k0 + tx] = __float2half_rn(x);
    }
}

// RMSNorm -> fp16
__global__ void rmsnorm_h_kernel(const float* __restrict__ x,
                                 const float* __restrict__ w,
                                 __half* __restrict__ o, int K)
{
    int row = blockIdx.x;
    const float* xr = x + (size_t)row * K;
    float ss = 0.f;
    int nvec = K / 4;
    const float4* xv = (const float4*)xr;
    for (int c = threadIdx.x; c < nvec; c += blockDim.x) {
        float4 v = xv[c];
        ss += v.x * v.x + v.y * v.y + v.z * v.z + v.w * v.w;
    }
    __shared__ float red[32];
    for (int off = 16; off > 0; off >>= 1) ss += __shfl_xor_sync(0xffffffffu, ss, off);
    int lane = threadIdx.x & 31, wid = threadIdx.x >> 5;
    if (lane == 0) red[wid] = ss;
    __syncthreads();
    int nwarp = blockDim.x >> 5;
    if (wid == 0) {
        float t = (lane < nwarp) ? red[lane] : 0.f;
        for (int off = 16; off > 0; off >>= 1) t += __shfl_xor_sync(0xffffffffu, t, off);
        if (lane == 0) red[0] = t;
    }
    __syncthreads();
    float inv = rsqrtf(red[0] / (float)K + EPS);

    for (int c = threadIdx.x; c < K / 2; c += blockDim.x) {
        int k = 2 * c;
        __half2 h;
        h.x = __float2half_rn(xr[k] * inv * w[k]);
        h.y = __float2half_rn(xr[k + 1] * inv * w[k + 1]);
        ((__half2*)(o + (size_t)row * K))[c] = h;
    }
}

// RoPE + scale + split (bf16, attention path); reads qkv fp32 [row][3072] at col COFF
template<int NHEADS, int SCALE, int COFF>
__global__ void rope_split_kernel(const float* __restrict__ x,
                                  __nv_bfloat16* __restrict__ hi,
                                  __nv_bfloat16* __restrict__ lo)
{
    int row = blockIdx.x;
    int b = row >> 11, s = row & 2047;
    int t = threadIdx.x;
    int h = t >> 5, i = t & 31;
    float inv_freq = powf(10000.0f, -(float)(2 * i) / 64.0f);
    float ang = (float)s * inv_freq;
    float c, sn;
    __sincosf(ang, &sn, &c);
    const float* p = x + (size_t)row * 3072 + COFF + h * HD;
    float x1 = p[i], x2 = p[i + 32];
    float o1 = x1 * c - x2 * sn;
    float o2 = x2 * c + x1 * sn;
    if (SCALE) { o1 *= 0.125f; o2 *= 0.125f; }
    size_t dst = ((size_t)(b * NHEADS + h) * SEQ + s) * 64;
    __nv_bfloat16 h1 = __float2bfloat16(o1);
    __nv_bfloat16 h2 = __float2bfloat16(o2);
    hi[dst + i]      = h1;
    hi[dst + i + 32] = h2;
    lo[dst + i]      = __float2bfloat16(o1 - __bfloat162float(h1));
    lo[dst + i + 32] = __float2bfloat16(o2 - __bfloat162float(h2));
}

// V transpose + split (bf16): qkv fp32 col 2560+ -> vt [b,kvh,d,s]
__global__ void vt_split_kernel(const float* __restrict__ v,
                                __nv_bfloat16* __restrict__ hiT,
                                __nv_bfloat16* __restrict__ loT)
{
    __shared__ float t[32][33];
    int s0 = blockIdx.x * 32, d0 = blockIdx.y * 32;
    int bz = blockIdx.z;
    int b = bz >> 3, kvh = bz & 7;
    int tx = threadIdx.x, ty = threadIdx.y;
    for (int sy = ty; sy < 32; sy += 8)
        t[sy][tx] = v[(size_t)(b * SEQ + s0 + sy) * 3072 + 2560 + kvh * 64 + d0 + tx];
    __syncthreads();
    for (int dy = ty; dy < 32; dy += 8) {
        float x = t[tx][dy];
        __nv_bfloat16 h = __float2bfloat16(x);
        __nv_bfloat16 l = __float2bfloat16(x - __bfloat162float(h));
        size_t o = ((size_t)bz * 64 + d0 + dy) * SEQ + s0 + tx;
        hiT[o] = h; loT[o] = l;
    }
}

// ---------------- HMMA GEMM: 128(M) x 256(N) tile, BK=32, 4-stage, fp16 1-term ----------------
// EPI 0: C = A@B^T (fp32)
// EPI 1: C = A@B^T + RES (fp32)
// EPI 2: OH = fp16(silu(RES) * (A@B^T))   (RES = gate fp32; C unused)
#define APITCH 80
#define A_MAT  10240          // 128 * 80
#define B_MAT  20480          // 256 * 80
#define STG_SZ (A_MAT + B_MAT)           // 30720
#define GSMEM  (4 * STG_SZ)               // 122880

template<int EPI>
__global__ void __launch_bounds__(256, 1)
hmma_gemm_kernel(const __half* __restrict__ A, const __half* __restrict__ B,
                 const float* __restrict__ RES, float* __restrict__ C,
                 __half* __restrict__ OH, int N, int K)
{
    extern __shared__ char sm[];
    uint32_t smb = smem_u32(sm);
    int tid = threadIdx.x, lane = tid & 31, wid = tid >> 5;
    int wm = wid & 3, wn = wid >> 2;          // warp tile 32(M) x 128(N)
    int bm = blockIdx.y, bn = blockIdx.x;
    int NKT = K / 32;

    const __half* gA = A + (size_t)bm * 128 * K;
    const __half* gB = B + (size_t)bn * 256 * K;

    int rbase = tid >> 2;      // 0..63
    int ch = tid & 3;          // 16B chunk within 64B row

    auto issue = [&](int st, int kt) {
        uint32_t base = smb + st * STG_SZ;
        int koff = kt * 32 + ch * 8;
#pragma unroll
        for (int u = 0; u < 2; u++) {
            int r = rbase + u * 64;
            cpa16(base + r * APITCH + ch * 16, gA + (size_t)r * K + koff);
        }
        uint32_t bB = base + A_MAT;
#pragma unroll
        for (int u = 0; u < 4; u++) {
            int r = rbase + u * 64;
            cpa16(bB + r * APITCH + ch * 16, gB + (size_t)r * K + koff);
        }
        cpa_commit();
    };

    float acc[2][16][4];
#pragma unroll
    for (int s = 0; s < 2; s++)
#pragma unroll
        for (int t = 0; t < 16; t++)
#pragma unroll
            for (int j = 0; j < 4; j++) acc[s][t][j] = 0.f;

    issue(0, 0);
    issue(1, 1);
    issue(2, 2);

    int a_row = wm * 32 + (lane & 15);
    int a_kb  = (lane >> 4) * 16;
    int b_ro  = ((lane >> 4) << 3) + (lane & 7);
    int b_kb  = ((lane >> 3) & 1) * 16;

    for (int kt = 0; kt < NKT; kt++) {
        int st = kt & 3;
        if (kt + 3 < NKT) issue((kt + 3) & 3, kt + 3);
        else cpa_commit();
        asm volatile("cp.async.wait_group 3;" ::: "memory");
        __syncthreads();

        uint32_t sA = smb + st * STG_SZ;
        uint32_t sB = sA + A_MAT;

#pragma unroll
        for (int ks = 0; ks < 2; ks++) {
            int kB = ks * 32;
            uint32_t a4[2][4];
            ldsm4(a4[0], sA + (a_row)      * APITCH + kB + a_kb);
            ldsm4(a4[1], sA + (a_row + 16) * APITCH + kB + a_kb);
#pragma unroll
            for (int gi = 0; gi < 8; gi++) {
                int brow = wn * 128 + gi * 16 + b_ro;
                uint32_t b4[4];
                ldsm4(b4, sB + brow * APITCH + kB + b_kb);
#pragma unroll
                for (int t = 0; t < 2; t++) {
                    const uint32_t* bp = &b4[t * 2];
#pragma unroll
                    for (int sub = 0; sub < 2; sub++)
                        mma_f16(acc[sub][gi * 2 + t], a4[sub], bp);
                }
            }
        }
        __syncthreads();
    }

    // epilogue
#pragma unroll
    for (int sub = 0; sub < 2; sub++) {
        int row0 = bm * 128 + wm * 32 + sub * 16 + (lane >> 2);
#pragma unroll
        for (int t = 0; t < 16; t++) {
            int col = bn * 256 + wn * 128 + t * 8 + (lane & 3) * 2;
            size_t o0 = (size_t)row0 * N + col;
            size_t o1 = o0 + (size_t)8 * N;
            if (EPI == 2) {
                float2 G0 = *(const float2*)(RES + o0);
                float2 G1 = *(const float2*)(RES + o1);
                __half2 H0, H1;
                H0.x = __float2half_rn(fsilu(G0.x) * acc[sub][t][0]);
                H0.y = __float2half_rn(fsilu(G0.y) * acc[sub][t][1]);
                H1.x = __float2half_rn(fsilu(G1.x) * acc[sub][t][2]);
                H1.y = __float2half_rn(fsilu(G1.y) * acc[sub][t][3]);
                *(__half2*)(OH + o0) = H0;
                *(__half2*)(OH + o1) = H1;
            } else {
                float2 v0 = make_float2(acc[sub][t][0], acc[sub][t][1]);
                float2 v1 = make_float2(acc[sub][t][2], acc[sub][t][3]);
                if (EPI == 1) {
                    float2 r0 = *(const float2*)(RES + o0);
                    float2 r1 = *(const float2*)(RES + o1);
                    v0.x += r0.x; v0.y += r0.y;
                    v1.x += r1.x; v1.y += r1.y;
                }
                *(float2*)(C + o0) = v0;
                *(float2*)(C + o1) = v1;
            }
        }
    }
}

// ---------------- tensor-core causal attention (bf16 3-term; writes fp16 ctx) ----------------
#define AT_PITCH 144
#define AT_MAT   (64 * AT_PITCH)
#define AT_QH 0
#define AT_QL (AT_MAT)
#define AT_KH (2 * AT_MAT)
#define AT_KL (3 * AT_MAT)
#define AT_VH (4 * AT_MAT)
#define AT_VL (5 * AT_MAT)
#define AT_SMEM (6 * AT_MAT)

__global__ void __launch_bounds__(128)
attn_mma_kernel(const __nv_bfloat16* __restrict__ qh, const __nv_bfloat16* __restrict__ ql,
                const __nv_bfloat16* __restrict__ kh, const __nv_bfloat16* __restrict__ kl,
                const __nv_bfloat16* __restrict__ vth, const __nv_bfloat16* __restrict__ vtl,
                __half* __restrict__ OH)
{
    extern __shared__ char sm[];
    uint32_t smb = smem_u32(sm);
    int qt = blockIdx.x, h = blockIdx.y, b = blockIdx.z;
    int kvh = h >> 2;
    int tid = threadIdx.x, lane = tid & 31, w = tid >> 5;
    int q0 = qt * 64;

    const __nv_bfloat16* Qhp = qh + ((size_t)(b * NH + h) * SEQ + q0) * 64;
    const __nv_bfloat16* Qlp = ql + ((size_t)(b * NH + h) * SEQ + q0) * 64;
    const __nv_bfloat16* Khp = kh + ((size_t)(b * NKVH + kvh) * SEQ) * 64;
    const __nv_bfloat16* Klp = kl + ((size_t)(b * NKVH + kvh) * SEQ) * 64;
    const __nv_bfloat16* Vhp = vth + ((size_t)(b * NKVH + kvh) * 64) * SEQ;
    const __nv_bfloat16* Vlp = vtl + ((size_t)(b * NKVH + kvh) * 64) * SEQ;

#pragma unroll
    for (int it = 0; it < 4; it++) {
        int idx = it * 128 + tid;
        int r = idx >> 3, ch = idx & 7;
        cpa16(smb + AT_QH + r * AT_PITCH + ch * 16, Qhp + (size_t)r * 64 + ch * 8);
        cpa16(smb + AT_QL + r * AT_PITCH + ch * 16, Qlp + (size_t)r * 64 + ch * 8);
    }
    cpa_commit();

    float m0 = -1e30f, m1 = -1e30f, l0 = 0.f, l1 = 0.f;
    float ao[8][4];
#pragma unroll
    for (int nt = 0; nt < 8; nt++)
#pragma unroll
        for (int j = 0; j < 4; j++) ao[nt][j] = 0.f;

    int r0 = lane >> 2, cq = lane & 3;
    int a_row = w * 16 + (lane & 15);
    int a_kb  = (lane >> 4) * 16;
    int b_ro  = ((lane >> 4) << 3) + (lane & 7);
    int b_kb  = ((lane >> 3) & 1) * 16;

    for (int kt = 0; kt <= qt; kt++) {
        int k0 = kt * 64;
#pragma unroll
        for (int it = 0; it < 4; it++) {
            int idx = it * 128 + tid;
            int r = idx >> 3, ch = idx & 7;
            cpa16(smb + AT_KH + r * AT_PITCH + ch * 16, Khp + (size_t)(k0 + r) * 64 + ch * 8);
            cpa16(smb + AT_KL + r * AT_PITCH + ch * 16, Klp + (size_t)(k0 + r) * 64 + ch * 8);
            cpa16(smb + AT_VH + r * AT_PITCH + ch * 16, Vhp + (size_t)r * SEQ + k0 + ch * 8);
            cpa16(smb + AT_VL + r * AT_PITCH + ch * 16, Vlp + (size_t)r * SEQ + k0 + ch * 8);
        }
        cpa_commit();
        asm volatile("cp.async.wait_group 0;" ::: "memory");
        __syncthreads();

        float sc[8][4];
#pragma unroll
        for (int nt = 0; nt < 8; nt++)
#pragma unroll
            for (int j = 0; j < 4; j++) sc[nt][j] = 0.f;

#pragma unroll
        for (int kc = 0; kc < 4; kc++) {
            uint32_t ah4[4], al4[4];
            ldsm4(ah4, smb + AT_QH + a_row * AT_PITCH + kc * 32 + a_kb);
            ldsm4(al4, smb + AT_QL + a_row * AT_PITCH + kc * 32 + a_kb);
#pragma unroll
            for (int gi = 0; gi < 4; gi++) {
                uint32_t kh4[4], kl4[4];
                ldsm4(kh4, smb + AT_KH + (gi * 16 + b_ro) * AT_PITCH + kc * 32 + b_kb);
                ldsm4(kl4, smb + AT_KL + (gi * 16 + b_ro) * AT_PITCH + kc * 32 + b_kb);
#pragma unroll
                for (int t = 0; t < 2; t++) {
                    mma_bf16(sc[gi * 2 + t], ah4, &kh4[t * 2]);
                    mma_bf16(sc[gi * 2 + t], ah4, &kl4[t * 2]);
                    mma_bf16(sc[gi * 2 + t], al4, &kh4[t * 2]);
                }
            }
        }

        if (kt == qt) {
            int qr0 = w * 16 + r0, qr1 = qr0 + 8;
#pragma unroll
            for (int nt = 0; nt < 8; nt++) {
                int col = nt * 8 + cq * 2;
                if (col     > qr0) sc[nt][0] = -1e30f;
                if (col + 1 > qr0) sc[nt][1] = -1e30f;
                if (col     > qr1) sc[nt][2] = -1e30f;
                if (col + 1 > qr1) sc[nt][3] = -1e30f;
            }
        }

        float tm0 = -1e30f, tm1 = -1e30f;
#pragma unroll
        for (int nt = 0; nt < 8; nt++) {
            tm0 = fmaxf(tm0, fmaxf(sc[nt][0], sc[nt][1]));
            tm1 = fmaxf(tm1, fmaxf(sc[nt][2], sc[nt][3]));
        }
        tm0 = fmaxf(tm0, __shfl_xor_sync(0xffffffffu, tm0, 1));
        tm0 = fmaxf(tm0, __shfl_xor_sync(0xffffffffu, tm0, 2));
        tm1 = fmaxf(tm1, __shfl_xor_sync(0xffffffffu, tm1, 1));
        tm1 = fmaxf(tm1, __shfl_xor_sync(0xffffffffu, tm1, 2));
        float mn0 = fmaxf(m0, tm0), mn1 = fmaxf(m1, tm1);
        float cr0 = fexp2((m0 - mn0) * L2E);
        float cr1 = fexp2((m1 - mn1) * L2E);
        float rs0 = 0.f, rs1 = 0.f;
#pragma unroll
        for (int nt = 0; nt < 8; nt++) {
            sc[nt][0] = fexp2((sc[nt][0] - mn0) * L2E);
            sc[nt][1] = fexp2((sc[nt][1] - mn0) * L2E);
            sc[nt][2] = fexp2((sc[nt][2] - mn1) * L2E);
            sc[nt][3] = fexp2((sc[nt][3] - mn1) * L2E);
            rs0 += sc[nt][0] + sc[nt][1];
            rs1 += sc[nt][2] + sc[nt][3];
        }
        rs0 += __shfl_xor_sync(0xffffffffu, rs0, 1);
        rs0 += __shfl_xor_sync(0xffffffffu, rs0, 2);
        rs1 += __shfl_xor_sync(0xffffffffu, rs1, 1);
        rs1 += __shfl_xor_sync(0xffffffffu, rs1, 2);
        l0 = l0 * cr0 + rs0;
        l1 = l1 * cr1 + rs1;
        m0 = mn0; m1 = mn1;
#pragma unroll
        for (int nt = 0; nt < 8; nt++) {
            ao[nt][0] *= cr0; ao[nt][1] *= cr0;
            ao[nt][2] *= cr1; ao[nt][3] *= cr1;
        }

#pragma unroll
        for (int j = 0; j < 4; j++) {
            uint32_t pah[4], pal[4];
#pragma unroll
            for (int u = 0; u < 2; u++) {
                __nv_bfloat162 H, L;
                split2b(sc[2 * j + u][0], sc[2 * j + u][1], &H, &L);
                pah[2 * u + 0] = *(uint32_t*)&H; pal[2 * u + 0] = *(uint32_t*)&L;
                split2b(sc[2 * j + u][2], sc[2 * j + u][3], &H, &L);
                pah[2 * u + 1] = *(uint32_t*)&H; pal[2 * u + 1] = *(uint32_t*)&L;
            }
#pragma unroll
            for (int gi = 0; gi < 4; gi++) {
                uint32_t vh4[4], vl4[4];
                ldsm4(vh4, smb + AT_VH + (gi * 16 + b_ro) * AT_PITCH + j * 32 + b_kb);
                ldsm4(vl4, smb + AT_VL + (gi * 16 + b_ro) * AT_PITCH + j * 32 + b_kb);
#pragma unroll
                for (int t = 0; t < 2; t++) {
                    mma_bf16(ao[gi * 2 + t], pah, &vh4[t * 2]);
                    mma_bf16(ao[gi * 2 + t], pah, &vl4[t * 2]);
                    mma_bf16(ao[gi * 2 + t], pal, &vh4[t * 2]);
                }
            }
        }
        __syncthreads();
    }

    float i0 = 1.f / l0, i1 = 1.f / l1;
    int rowA = q0 + w * 16 + r0;
    int rowB = rowA + 8;
#pragma unroll
    for (int nt = 0; nt < 8; nt++) {
        int col = h * 64 + nt * 8 + cq * 2;
        size_t oA = ((size_t)(b * SEQ) + rowA) * 2048 + col;
        size_t oB = ((size_t)(b * SEQ) + rowB) * 2048 + col;
        __half2 H;
        H.x = __float2half_rn(ao[nt][0] * i0);
        H.y = __float2half_rn(ao[nt][1] * i0);
        *(__half2*)(OH + oA) = H;
        H.x = __float2half_rn(ao[nt][2] * i1);
        H.y = __float2half_rn(ao[nt][3] * i1);
        *(__half2*)(OH + oB) = H;
    }
}

// ---------------- host launch ----------------
extern "C" void kernel_launch(void* const* d_in, const int* in_sizes, int n_in,
                              void* d_out, int out_size)
{
    const float* hidden  = (const float*)d_in[0];
    const float* norm1_w = (const float*)d_in[2];
    const float* wq      = (const float*)d_in[3];
    const float* wk      = (const float*)d_in[4];
    const float* wv      = (const float*)d_in[5];
    const float* wo      = (const float*)d_in[6];
    const float* norm2_w = (const float*)d_in[7];
    const float* w_gate  = (const float*)d_in[8];
    const float* w_up    = (const float*)d_in[9];
    const float* w_down  = (const float*)d_in[10];
    float* out = (float*)d_out;

    float *res2, *gate, *upb;
    __half *ab, *wpool;
    __nv_bfloat16 *qh, *ql, *kh, *kl, *vth, *vtl;
    cudaGetSymbolAddress((void**)&res2, g_res2);
    cudaGetSymbolAddress((void**)&gate, g_gate);
    cudaGetSymbolAddress((void**)&upb,  g_up);
    cudaGetSymbolAddress((void**)&ab,   g_a);
    cudaGetSymbolAddress((void**)&wpool, g_w);
    cudaGetSymbolAddress((void**)&qh,   g_qh);
    cudaGetSymbolAddress((void**)&ql,   g_ql);
    cudaGetSymbolAddress((void**)&kh,   g_kh);
    cudaGetSymbolAddress((void**)&kl,   g_kl);
    cudaGetSymbolAddress((void**)&vth,  g_vth);
    cudaGetSymbolAddress((void**)&vtl,  g_vtl);

    float* qkv = gate;                          // fp32 [ROWS][3072], freed before MLP
    __half* mbuf = (__half*)upb;                // [ROWS*FF] fp16

    // weight pool offsets (elements)
    const size_t OQKV = 0;                    // 3072 x 2048
    const size_t OWO  = 6ull * MEG;           // 2048 x 2048
    const size_t OWG  = 10ull * MEG;          // 8192 x 2048
    const size_t OWU  = 26ull * MEG;
    const size_t OWD  = 42ull * MEG;          // 2048 x 8192

    cudaFuncSetAttribute(hmma_gemm_kernel<0>, cudaFuncAttributeMaxDynamicSharedMemorySize, GSMEM);
    cudaFuncSetAttribute(hmma_gemm_kernel<1>, cudaFuncAttributeMaxDynamicSharedMemorySize, GSMEM);
    cudaFuncSetAttribute(hmma_gemm_kernel<2>, cudaFuncAttributeMaxDynamicSharedMemorySize, GSMEM);
    cudaFuncSetAttribute(attn_mma_kernel, cudaFuncAttributeMaxDynamicSharedMemorySize, AT_SMEM);

    // ---- weight transpose -> fp16 (QKV concatenated) ----
    convT_kernel<<<dim3(64, 64), 256>>>(wq, wpool + OQKV, 2048, 2048);
    convT_kernel<<<dim3(16, 64), 256>>>(wk, wpool + OQKV + 2048ull * 2048, 2048, 512);
    convT_kernel<<<dim3(16, 64), 256>>>(wv, wpool + OQKV + 2560ull * 2048, 2048, 512);
    convT_kernel<<<dim3(64, 64), 256>>>(wo,     wpool + OWO, 2048, 2048);
    convT_kernel<<<dim3(256, 64), 256>>>(w_gate, wpool + OWG, 2048, 8192);
    convT_kernel<<<dim3(256, 64), 256>>>(w_up,   wpool + OWU, 2048, 8192);
    convT_kernel<<<dim3(64, 256), 256>>>(w_down, wpool + OWD, 8192, 2048);

    // ---- 1. rmsnorm1 -> fp16 ----
    rmsnorm_h_kernel<<<ROWS, 256>>>(hidden, norm1_w, ab, HID);

    // ---- 2. fused QKV GEMM -> qkv fp32 [ROWS][3072] ----
    hmma_gemm_kernel<0><<<dim3(3072 / 256, ROWS / 128), 256, GSMEM>>>(
        ab, wpool + OQKV, nullptr, qkv, nullptr, 3072, 2048);

    // ---- 3. RoPE + scale + split; V transpose + split (bf16 attention path) ----
    rope_split_kernel<NH, 1, 0><<<ROWS, NH * 32>>>(qkv, qh, ql);
    rope_split_kernel<NKVH, 0, 2048><<<ROWS, NKVH * 32>>>(qkv, kh, kl);
    vt_split_kernel<<<dim3(SEQ / 32, 2, NB * NKVH), dim3(32, 8)>>>(qkv, vth, vtl);

    // ---- 4. attention -> ctx fp16 (ab) ----
    attn_mma_kernel<<<dim3(SEQ / 64, NH, NB), 128, AT_SMEM>>>(qh, ql, kh, kl, vth, vtl, ab);

    // ---- 5. output projection + residual -> res2 fp32 ----
    hmma_gemm_kernel<1><<<dim3(2048 / 256, ROWS / 128), 256, GSMEM>>>(
        ab, wpool + OWO, hidden, res2, nullptr, 2048, 2048);

    // ---- 6. rmsnorm2 -> fp16 ----
    rmsnorm_h_kernel<<<ROWS, 256>>>(res2, norm2_w, ab, HID);

    // ---- 7. gate GEMM -> fp32 ----
    hmma_gemm_kernel<0><<<dim3(FF / 256, ROWS / 128), 256, GSMEM>>>(
        ab, wpool + OWG, nullptr, gate, nullptr, FF, 2048);

    // ---- 8. up GEMM + fused silu(gate)*up -> fp16 (mbuf) ----
    hmma_gemm_kernel<2><<<dim3(FF / 256, ROWS / 128), 256, GSMEM>>>(
        ab, wpool + OWU, gate, nullptr, mbuf, FF, 2048);

    // ---- 9. down projection + residual -> out ----
    hmma_gemm_kernel<1><<<dim3(2048 / 256, ROWS / 128), 256, GSMEM>>>(
        mbuf, wpool + OWD, res2, out, nullptr, 2048, 8192);
}

// round 9
// speedup vs baseline: 6.8259x; 1.0817x over previous
#include <cuda_runtime.h>
#include <cuda_bf16.h>
#include <cuda_fp16.h>
#include <math.h>
#include <stdint.h>

// ---------------- problem constants ----------------
#define HID   2048
#define NH    32
#define NKVH  8
#define HD    64
#define FF    8192
#define SEQ   2048
#define NB    2
#define ROWS  4096
#define EPS   1e-6f
#define MEG   (1024*1024)
#define L2E   1.4426950408889634f

// ---------------- scratch (device globals; no allocs allowed) ----------------
__device__ float g_res2[(size_t)ROWS * 2048];
__device__ float g_gate[(size_t)ROWS * FF];          // holds qkv fp32 early, then gate fp16
__device__ float g_up  [(size_t)ROWS * FF];          // reused as fp16 m buffer

// fp16 operands
__device__ __half g_a  [(size_t)ROWS * HID];
__device__ __half g_w  [(size_t)58 * MEG];

// attention fp16 operands
__device__ __half g_qh[(size_t)ROWS * 2048];
__device__ __half g_ql[(size_t)ROWS * 2048];
__device__ __half g_k [(size_t)ROWS * 512];
__device__ __half g_vt[(size_t)ROWS * 512];

// ---------------- helpers ----------------
__device__ __forceinline__ uint32_t smem_u32(const void* p) {
    uint32_t a;
    asm("{ .reg .u64 t; cvta.to.shared.u64 t, %1; cvt.u32.u64 %0, t; }" : "=r"(a) : "l"(p));
    return a;
}

__device__ __forceinline__ void cpa16(uint32_t dst, const void* src) {
    asm volatile("cp.async.cg.shared.global [%0], [%1], 16;" :: "r"(dst), "l"(src));
}
__device__ __forceinline__ void cpa_commit() {
    asm volatile("cp.async.commit_group;" ::: "memory");
}

__device__ __forceinline__ void ldsm4(uint32_t* r, uint32_t addr) {
    asm volatile("ldmatrix.sync.aligned.m8n8.x4.shared.b16 {%0,%1,%2,%3}, [%4];"
        : "=r"(r[0]), "=r"(r[1]), "=r"(r[2]), "=r"(r[3]) : "r"(addr));
}

__device__ __forceinline__ void mma_f16(float* c, const uint32_t* a, const uint32_t* b) {
    asm volatile("mma.sync.aligned.m16n8k16.row.col.f32.f16.f16.f32 "
        "{%0,%1,%2,%3}, {%4,%5,%6,%7}, {%8,%9}, {%0,%1,%2,%3};"
        : "+f"(c[0]), "+f"(c[1]), "+f"(c[2]), "+f"(c[3])
        : "r"(a[0]), "r"(a[1]), "r"(a[2]), "r"(a[3]), "r"(b[0]), "r"(b[1]));
}

// FMA-only exp2, clamped both sides, |rel err| ~2e-6
__device__ __forceinline__ float fexp2(float z) {
    z = fminf(fmaxf(z, -126.f), 126.f);
    float sh = z + 12582912.f;
    float zi = sh - 12582912.f;
    float f = z - zi;
    float p = 0.0013333558f;
    p = p * f + 0.0096181291f;
    p = p * f + 0.0555041087f;
    p = p * f + 0.2402265070f;
    p = p * f + 0.6931471806f;
    p = p * f + 1.0f;
    int ei = __float_as_int(sh) - 0x4B400000;
    return p * __int_as_float((ei + 127) << 23);
}

__device__ __forceinline__ float fsilu(float x) {
    return x / (1.f + fexp2(-x * L2E));
}

// ---------------- converters ----------------
// W [K,N] fp32 -> Wt [N,K] fp16
__global__ void convT_kernel(const float* __restrict__ W,
                             __half* __restrict__ wT, int K, int N)
{
    __shared__ float t[32][33];
    int n0 = blockIdx.x * 32, k0 = blockIdx.y * 32;
    int tx = threadIdx.x & 31, ty = threadIdx.x >> 5;
    for (int ky = ty; ky < 32; ky += 8)
        t[ky][tx] = W[(size_t)(k0 + ky) * N + n0 + tx];
    __syncthreads();
    for (int ny = ty; ny < 32; ny += 8) {
        float x = t[tx][ny];
        wT[(size_t)(n0 + ny) * K + k0 + tx] = __float2half_rn(x);
    }
}

// RMSNorm -> fp16
__global__ void rmsnorm_h_kernel(const float* __restrict__ x,
                                 const float* __restrict__ w,
                                 __half* __restrict__ o, int K)
{
    int row = blockIdx.x;
    const float* xr = x + (size_t)row * K;
    float ss = 0.f;
    int nvec = K / 4;
    const float4* xv = (const float4*)xr;
    for (int c = threadIdx.x; c < nvec; c += blockDim.x) {
        float4 v = xv[c];
        ss += v.x * v.x + v.y * v.y + v.z * v.z + v.w * v.w;
    }
    __shared__ float red[32];
    for (int off = 16; off > 0; off >>= 1) ss += __shfl_xor_sync(0xffffffffu, ss, off);
    int lane = threadIdx.x & 31, wid = threadIdx.x >> 5;
    if (lane == 0) red[wid] = ss;
    __syncthreads();
    int nwarp = blockDim.x >> 5;
    if (wid == 0) {
        float t = (lane < nwarp) ? red[lane] : 0.f;
        for (int off = 16; off > 0; off >>= 1) t += __shfl_xor_sync(0xffffffffu, t, off);
        if (lane == 0) red[0] = t;
    }
    __syncthreads();
    float inv = rsqrtf(red[0] / (float)K + EPS);

    for (int c = threadIdx.x; c < K / 2; c += blockDim.x) {
        int k = 2 * c;
        __half2 h;
        h.x = __float2half_rn(xr[k] * inv * w[k]);
        h.y = __float2half_rn(xr[k + 1] * inv * w[k + 1]);
        ((__half2*)(o + (size_t)row * K))[c] = h;
    }
}

// RoPE Q: fp32 qkv col 0+ -> qh/ql [b,h,s,d] fp16 split, scaled by 1/8
__global__ void rope_q_kernel(const float* __restrict__ x,
                              __half* __restrict__ hi, __half* __restrict__ lo)
{
    int row = blockIdx.x;
    int b = row >> 11, s = row & 2047;
    int t = threadIdx.x;                 // 32*32 threads
    int h = t >> 5, i = t & 31;
    float inv_freq = powf(10000.0f, -(float)(2 * i) / 64.0f);
    float ang = (float)s * inv_freq;
    float c, sn;
    __sincosf(ang, &sn, &c);
    const float* p = x + (size_t)row * 3072 + h * HD;
    float x1 = p[i], x2 = p[i + 32];
    float o1 = (x1 * c - x2 * sn) * 0.125f;
    float o2 = (x2 * c + x1 * sn) * 0.125f;
    size_t dst = ((size_t)(b * NH + h) * SEQ + s) * 64;
    __half h1 = __float2half_rn(o1);
    __half h2 = __float2half_rn(o2);
    hi[dst + i]      = h1;
    hi[dst + i + 32] = h2;
    lo[dst + i]      = __float2half_rn(o1 - __half2float(h1));
    lo[dst + i + 32] = __float2half_rn(o2 - __half2float(h2));
}

// RoPE K: fp32 qkv col 2048+ -> k [b,kvh,s,d] fp16 single
__global__ void rope_k_kernel(const float* __restrict__ x, __half* __restrict__ o)
{
    int row = blockIdx.x;
    int b = row >> 11, s = row & 2047;
    int t = threadIdx.x;                 // 8*32 threads
    int h = t >> 5, i = t & 31;
    float inv_freq = powf(10000.0f, -(float)(2 * i) / 64.0f);
    float ang = (float)s * inv_freq;
    float c, sn;
    __sincosf(ang, &sn, &c);
    const float* p = x + (size_t)row * 3072 + 2048 + h * HD;
    float x1 = p[i], x2 = p[i + 32];
    size_t dst = ((size_t)(b * NKVH + h) * SEQ + s) * 64;
    o[dst + i]      = __float2half_rn(x1 * c - x2 * sn);
    o[dst + i + 32] = __float2half_rn(x2 * c + x1 * sn);
}

// V transpose: qkv fp32 col 2560+ -> vt [b,kvh,d,s] fp16 single
__global__ void vt_kernel(const float* __restrict__ v, __half* __restrict__ oT)
{
    __shared__ float t[32][33];
    int s0 = blockIdx.x * 32, d0 = blockIdx.y * 32;
    int bz = blockIdx.z;
    int b = bz >> 3, kvh = bz & 7;
    int tx = threadIdx.x, ty = threadIdx.y;
    for (int sy = ty; sy < 32; sy += 8)
        t[sy][tx] = v[(size_t)(b * SEQ + s0 + sy) * 3072 + 2560 + kvh * 64 + d0 + tx];
    __syncthreads();
    for (int dy = ty; dy < 32; dy += 8)
        oT[((size_t)bz * 64 + d0 + dy) * SEQ + s0 + tx] = __float2half_rn(t[tx][dy]);
}

// ---------------- HMMA GEMM: 128(M) x 256(N) tile, BK=32, 4-stage, fp16 ----------------
// EPI 0: C = A@B^T (fp32)
// EPI 1: C = A@B^T + RES (fp32)
// EPI 2: OH = fp16(silu(RESH) * (A@B^T))   (RESH fp16)
// EPI 3: OH = fp16(A@B^T)
#define APITCH 80
#define A_MAT  10240
#define B_MAT  20480
#define STG_SZ (A_MAT + B_MAT)           // 30720
#define GSMEM  (4 * STG_SZ)               // 122880

template<int EPI>
__global__ void __launch_bounds__(256, 1)
hmma_gemm_kernel(const __half* __restrict__ A, const __half* __restrict__ B,
                 const float* __restrict__ RES, const __half* __restrict__ RESH,
                 float* __restrict__ C, __half* __restrict__ OH, int N, int K)
{
    extern __shared__ char sm[];
    uint32_t smb = smem_u32(sm);
    int tid = threadIdx.x, lane = tid & 31, wid = tid >> 5;
    int wm = wid & 3, wn = wid >> 2;
    int bm = blockIdx.y, bn = blockIdx.x;
    int NKT = K / 32;

    const __half* gA = A + (size_t)bm * 128 * K;
    const __half* gB = B + (size_t)bn * 256 * K;

    int rbase = tid >> 2;
    int ch = tid & 3;

    auto issue = [&](int st, int kt) {
        uint32_t base = smb + st * STG_SZ;
        int koff = kt * 32 + ch * 8;
#pragma unroll
        for (int u = 0; u < 2; u++) {
            int r = rbase + u * 64;
            cpa16(base + r * APITCH + ch * 16, gA + (size_t)r * K + koff);
        }
        uint32_t bB = base + A_MAT;
#pragma unroll
        for (int u = 0; u < 4; u++) {
            int r = rbase + u * 64;
            cpa16(bB + r * APITCH + ch * 16, gB + (size_t)r * K + koff);
        }
        cpa_commit();
    };

    float acc[2][16][4];
#pragma unroll
    for (int s = 0; s < 2; s++)
#pragma unroll
        for (int t = 0; t < 16; t++)
#pragma unroll
            for (int j = 0; j < 4; j++) acc[s][t][j] = 0.f;

    issue(0, 0);
    issue(1, 1);
    issue(2, 2);

    int a_row = wm * 32 + (lane & 15);
    int a_kb  = (lane >> 4) * 16;
    int b_ro  = ((lane >> 4) << 3) + (lane & 7);
    int b_kb  = ((lane >> 3) & 1) * 16;

    for (int kt = 0; kt < NKT; kt++) {
        int st = kt & 3;
        if (kt + 3 < NKT) issue((kt + 3) & 3, kt + 3);
        else cpa_commit();
        asm volatile("cp.async.wait_group 3;" ::: "memory");
        __syncthreads();

        uint32_t sA = smb + st * STG_SZ;
        uint32_t sB = sA + A_MAT;

#pragma unroll
        for (int ks = 0; ks < 2; ks++) {
            int kB = ks * 32;
            uint32_t a4[2][4];
            ldsm4(a4[0], sA + (a_row)      * APITCH + kB + a_kb);
            ldsm4(a4[1], sA + (a_row + 16) * APITCH + kB + a_kb);
#pragma unroll
            for (int gi = 0; gi < 8; gi++) {
                int brow = wn * 128 + gi * 16 + b_ro;
                uint32_t b4[4];
                ldsm4(b4, sB + brow * APITCH + kB + b_kb);
#pragma unroll
                for (int t = 0; t < 2; t++) {
                    const uint32_t* bp = &b4[t * 2];
#pragma unroll
                    for (int sub = 0; sub < 2; sub++)
                        mma_f16(acc[sub][gi * 2 + t], a4[sub], bp);
                }
            }
        }
        __syncthreads();
    }

    // epilogue
#pragma unroll
    for (int sub = 0; sub < 2; sub++) {
        int row0 = bm * 128 + wm * 32 + sub * 16 + (lane >> 2);
#pragma unroll
        for (int t = 0; t < 16; t++) {
            int col = bn * 256 + wn * 128 + t * 8 + (lane & 3) * 2;
            size_t o0 = (size_t)row0 * N + col;
            size_t o1 = o0 + (size_t)8 * N;
            if (EPI == 2) {
                float2 G0 = __half22float2(*(const __half2*)(RESH + o0));
                float2 G1 = __half22float2(*(const __half2*)(RESH + o1));
                __half2 H0, H1;
                H0.x = __float2half_rn(fsilu(G0.x) * acc[sub][t][0]);
                H0.y = __float2half_rn(fsilu(G0.y) * acc[sub][t][1]);
                H1.x = __float2half_rn(fsilu(G1.x) * acc[sub][t][2]);
                H1.y = __float2half_rn(fsilu(G1.y) * acc[sub][t][3]);
                *(__half2*)(OH + o0) = H0;
                *(__half2*)(OH + o1) = H1;
            } else if (EPI == 3) {
                __half2 H0, H1;
                H0.x = __float2half_rn(acc[sub][t][0]);
                H0.y = __float2half_rn(acc[sub][t][1]);
                H1.x = __float2half_rn(acc[sub][t][2]);
                H1.y = __float2half_rn(acc[sub][t][3]);
                *(__half2*)(OH + o0) = H0;
                *(__half2*)(OH + o1) = H1;
            } else {
                float2 v0 = make_float2(acc[sub][t][0], acc[sub][t][1]);
                float2 v1 = make_float2(acc[sub][t][2], acc[sub][t][3]);
                if (EPI == 1) {
                    float2 r0 = *(const float2*)(RES + o0);
                    float2 r1 = *(const float2*)(RES + o1);
                    v0.x += r0.x; v0.y += r0.y;
                    v1.x += r1.x; v1.y += r1.y;
                }
                *(float2*)(C + o0) = v0;
                *(float2*)(C + o1) = v1;
            }
        }
    }
}

// ---------------- tensor-core causal attention (fp16: Q split, K/P/V single) ----------------
#define AT_PITCH 144
#define AT_MAT   (64 * AT_PITCH)
#define AT_QH 0
#define AT_QL (AT_MAT)
#define AT_K  (2 * AT_MAT)
#define AT_V  (3 * AT_MAT)
#define AT_SMEM (4 * AT_MAT)     // 36864

__global__ void __launch_bounds__(128)
attn_mma_kernel(const __half* __restrict__ qh, const __half* __restrict__ ql,
                const __half* __restrict__ kk, const __half* __restrict__ vt,
                __half* __restrict__ OH)
{
    extern __shared__ char sm[];
    uint32_t smb = smem_u32(sm);
    int qt = blockIdx.x, h = blockIdx.y, b = blockIdx.z;
    int kvh = h >> 2;
    int tid = threadIdx.x, lane = tid & 31, w = tid >> 5;
    int q0 = qt * 64;

    const __half* Qhp = qh + ((size_t)(b * NH + h) * SEQ + q0) * 64;
    const __half* Qlp = ql + ((size_t)(b * NH + h) * SEQ + q0) * 64;
    const __half* Kp  = kk + ((size_t)(b * NKVH + kvh) * SEQ) * 64;
    const __half* Vp  = vt + ((size_t)(b * NKVH + kvh) * 64) * SEQ;

    // load Q tiles, then hoist fragments to registers
#pragma unroll
    for (int it = 0; it < 4; it++) {
        int idx = it * 128 + tid;
        int r = idx >> 3, ch = idx & 7;
        cpa16(smb + AT_QH + r * AT_PITCH + ch * 16, Qhp + (size_t)r * 64 + ch * 8);
        cpa16(smb + AT_QL + r * AT_PITCH + ch * 16, Qlp + (size_t)r * 64 + ch * 8);
    }
    cpa_commit();
    asm volatile("cp.async.wait_group 0;" ::: "memory");
    __syncthreads();

    int r0 = lane >> 2, cq = lane & 3;
    int a_row = w * 16 + (lane & 15);
    int a_kb  = (lane >> 4) * 16;
    int b_ro  = ((lane >> 4) << 3) + (lane & 7);
    int b_kb  = ((lane >> 3) & 1) * 16;

    uint32_t qfh[4][4], qfl[4][4];
#pragma unroll
    for (int kc = 0; kc < 4; kc++) {
        ldsm4(qfh[kc], smb + AT_QH + a_row * AT_PITCH + kc * 32 + a_kb);
        ldsm4(qfl[kc], smb + AT_QL + a_row * AT_PITCH + kc * 32 + a_kb);
    }
    __syncthreads();

    float m0 = -1e30f, m1 = -1e30f, l0 = 0.f, l1 = 0.f;
    float ao[8][4];
#pragma unroll
    for (int nt = 0; nt < 8; nt++)
#pragma unroll
        for (int j = 0; j < 4; j++) ao[nt][j] = 0.f;

    for (int kt = 0; kt <= qt; kt++) {
        int k0 = kt * 64;
#pragma unroll
        for (int it = 0; it < 4; it++) {
            int idx = it * 128 + tid;
            int r = idx >> 3, ch = idx & 7;
            cpa16(smb + AT_K + r * AT_PITCH + ch * 16, Kp + (size_t)(k0 + r) * 64 + ch * 8);
            cpa16(smb + AT_V + r * AT_PITCH + ch * 16, Vp + (size_t)r * SEQ + k0 + ch * 8);
        }
        cpa_commit();
        asm volatile("cp.async.wait_group 0;" ::: "memory");
        __syncthreads();

        float sc[8][4];
#pragma unroll
        for (int nt = 0; nt < 8; nt++)
#pragma unroll
            for (int j = 0; j < 4; j++) sc[nt][j] = 0.f;

#pragma unroll
        for (int kc = 0; kc < 4; kc++) {
#pragma unroll
            for (int gi = 0; gi < 4; gi++) {
                uint32_t k4[4];
                ldsm4(k4, smb + AT_K + (gi * 16 + b_ro) * AT_PITCH + kc * 32 + b_kb);
#pragma unroll
                for (int t = 0; t < 2; t++) {
                    mma_f16(sc[gi * 2 + t], qfh[kc], &k4[t * 2]);
                    mma_f16(sc[gi * 2 + t], qfl[kc], &k4[t * 2]);
                }
            }
        }

        if (kt == qt) {
            int qr0 = w * 16 + r0, qr1 = qr0 + 8;
#pragma unroll
            for (int nt = 0; nt < 8; nt++) {
                int col = nt * 8 + cq * 2;
                if (col     > qr0) sc[nt][0] = -1e30f;
                if (col + 1 > qr0) sc[nt][1] = -1e30f;
                if (col     > qr1) sc[nt][2] = -1e30f;
                if (col + 1 > qr1) sc[nt][3] = -1e30f;
            }
        }

        float tm0 = -1e30f, tm1 = -1e30f;
#pragma unroll
        for (int nt = 0; nt < 8; nt++) {
            tm0 = fmaxf(tm0, fmaxf(sc[nt][0], sc[nt][1]));
            tm1 = fmaxf(tm1, fmaxf(sc[nt][2], sc[nt][3]));
        }
        tm0 = fmaxf(tm0, __shfl_xor_sync(0xffffffffu, tm0, 1));
        tm0 = fmaxf(tm0, __shfl_xor_sync(0xffffffffu, tm0, 2));
        tm1 = fmaxf(tm1, __shfl_xor_sync(0xffffffffu, tm1, 1));
        tm1 = fmaxf(tm1, __shfl_xor_sync(0xffffffffu, tm1, 2));
        float mn0 = fmaxf(m0, tm0), mn1 = fmaxf(m1, tm1);
        float cr0 = fexp2((m0 - mn0) * L2E);
        float cr1 = fexp2((m1 - mn1) * L2E);
        float rs0 = 0.f, rs1 = 0.f;
#pragma unroll
        for (int nt = 0; nt < 8; nt++) {
            sc[nt][0] = fexp2((sc[nt][0] - mn0) * L2E);
            sc[nt][1] = fexp2((sc[nt][1] - mn0) * L2E);
            sc[nt][2] = fexp2((sc[nt][2] - mn1) * L2E);
            sc[nt][3] = fexp2((sc[nt][3] - mn1) * L2E);
            rs0 += sc[nt][0] + sc[nt][1];
            rs1 += sc[nt][2] + sc[nt][3];
        }
        rs0 += __shfl_xor_sync(0xffffffffu, rs0, 1);
        rs0 += __shfl_xor_sync(0xffffffffu, rs0, 2);
        rs1 += __shfl_xor_sync(0xffffffffu, rs1, 1);
        rs1 += __shfl_xor_sync(0xffffffffu, rs1, 2);
        l0 = l0 * cr0 + rs0;
        l1 = l1 * cr1 + rs1;
        m0 = mn0; m1 = mn1;
#pragma unroll
        for (int nt = 0; nt < 8; nt++) {
            ao[nt][0] *= cr0; ao[nt][1] *= cr0;
            ao[nt][2] *= cr1; ao[nt][3] *= cr1;
        }

        // P (single fp16) @ V (single fp16)
#pragma unroll
        for (int j = 0; j < 4; j++) {
            uint32_t pa[4];
#pragma unroll
            for (int u = 0; u < 2; u++) {
                __half2 H0 = __floats2half2_rn(sc[2 * j + u][0], sc[2 * j + u][1]);
                __half2 H1 = __floats2half2_rn(sc[2 * j + u][2], sc[2 * j + u][3]);
                pa[2 * u + 0] = *(uint32_t*)&H0;
                pa[2 * u + 1] = *(uint32_t*)&H1;
            }
#pragma unroll
            for (int gi = 0; gi < 4; gi++) {
                uint32_t v4[4];
                ldsm4(v4, smb + AT_V + (gi * 16 + b_ro) * AT_PITCH + j * 32 + b_kb);
#pragma unroll
                for (int t = 0; t < 2; t++)
                    mma_f16(ao[gi * 2 + t], pa, &v4[t * 2]);
            }
        }
        __syncthreads();
    }

    float i0 = 1.f / l0, i1 = 1.f / l1;
    int rowA = q0 + w * 16 + r0;
    int rowB = rowA + 8;
#pragma unroll
    for (int nt = 0; nt < 8; nt++) {
        int col = h * 64 + nt * 8 + cq * 2;
        size_t oA = ((size_t)(b * SEQ) + rowA) * 2048 + col;
        size_t oB = ((size_t)(b * SEQ) + rowB) * 2048 + col;
        *(__half2*)(OH + oA) = __floats2half2_rn(ao[nt][0] * i0, ao[nt][1] * i0);
        *(__half2*)(OH + oB) = __floats2half2_rn(ao[nt][2] * i1, ao[nt][3] * i1);
    }
}

// ---------------- host launch ----------------
extern "C" void kernel_launch(void* const* d_in, const int* in_sizes, int n_in,
                              void* d_out, int out_size)
{
    const float* hidden  = (const float*)d_in[0];
    const float* norm1_w = (const float*)d_in[2];
    const float* wq      = (const float*)d_in[3];
    const float* wk      = (const float*)d_in[4];
    const float* wv      = (const float*)d_in[5];
    const float* wo      = (const float*)d_in[6];
    const float* norm2_w = (const float*)d_in[7];
    const float* w_gate  = (const float*)d_in[8];
    const float* w_up    = (const float*)d_in[9];
    const float* w_down  = (const float*)d_in[10];
    float* out = (float*)d_out;

    float *res2, *gatef, *upb;
    __half *ab, *wpool, *qh, *ql, *kbuf, *vtb;
    cudaGetSymbolAddress((void**)&res2, g_res2);
    cudaGetSymbolAddress((void**)&gatef, g_gate);
    cudaGetSymbolAddress((void**)&upb,  g_up);
    cudaGetSymbolAddress((void**)&ab,   g_a);
    cudaGetSymbolAddress((void**)&wpool, g_w);
    cudaGetSymbolAddress((void**)&qh,   g_qh);
    cudaGetSymbolAddress((void**)&ql,   g_ql);
    cudaGetSymbolAddress((void**)&kbuf, g_k);
    cudaGetSymbolAddress((void**)&vtb,  g_vt);

    float* qkv = gatef;                         // fp32 [ROWS][3072], dead before gate GEMM
    __half* gateh = (__half*)gatef;             // fp16 gate [ROWS][FF] (after qkv dead)
    __half* mbuf = (__half*)upb;                // fp16 [ROWS*FF]

    // weight pool offsets (elements)
    const size_t OQKV = 0;
    const size_t OWO  = 6ull * MEG;
    const size_t OWG  = 10ull * MEG;
    const size_t OWU  = 26ull * MEG;
    const size_t OWD  = 42ull * MEG;

    cudaFuncSetAttribute(hmma_gemm_kernel<0>, cudaFuncAttributeMaxDynamicSharedMemorySize, GSMEM);
    cudaFuncSetAttribute(hmma_gemm_kernel<1>, cudaFuncAttributeMaxDynamicSharedMemorySize, GSMEM);
    cudaFuncSetAttribute(hmma_gemm_kernel<2>, cudaFuncAttributeMaxDynamicSharedMemorySize, GSMEM);
    cudaFuncSetAttribute(hmma_gemm_kernel<3>, cudaFuncAttributeMaxDynamicSharedMemorySize, GSMEM);
    cudaFuncSetAttribute(attn_mma_kernel, cudaFuncAttributeMaxDynamicSharedMemorySize, AT_SMEM);

    // ---- weight transpose -> fp16 (QKV concatenated) ----
    convT_kernel<<<dim3(64, 64), 256>>>(wq, wpool + OQKV, 2048, 2048);
    convT_kernel<<<dim3(16, 64), 256>>>(wk, wpool + OQKV + 2048ull * 2048, 2048, 512);
    convT_kernel<<<dim3(16, 64), 256>>>(wv, wpool + OQKV + 2560ull * 2048, 2048, 512);
    convT_kernel<<<dim3(64, 64), 256>>>(wo,     wpool + OWO, 2048, 2048);
    convT_kernel<<<dim3(256, 64), 256>>>(w_gate, wpool + OWG, 2048, 8192);
    convT_kernel<<<dim3(256, 64), 256>>>(w_up,   wpool + OWU, 2048, 8192);
    convT_kernel<<<dim3(64, 256), 256>>>(w_down, wpool + OWD, 8192, 2048);

    // ---- 1. rmsnorm1 -> fp16 ----
    rmsnorm_h_kernel<<<ROWS, 256>>>(hidden, norm1_w, ab, HID);

    // ---- 2. fused QKV GEMM -> qkv fp32 [ROWS][3072] ----
    hmma_gemm_kernel<0><<<dim3(3072 / 256, ROWS / 128), 256, GSMEM>>>(
        ab, wpool + OQKV, nullptr, nullptr, qkv, nullptr, 3072, 2048);

    // ---- 3. RoPE Q/K + V transpose (fp16 attention operands) ----
    rope_q_kernel<<<ROWS, NH * 32>>>(qkv, qh, ql);
    rope_k_kernel<<<ROWS, NKVH * 32>>>(qkv, kbuf);
    vt_kernel<<<dim3(SEQ / 32, 2, NB * NKVH), dim3(32, 8)>>>(qkv, vtb);

    // ---- 4. attention -> ctx fp16 (ab) ----
    attn_mma_kernel<<<dim3(SEQ / 64, NH, NB), 128, AT_SMEM>>>(qh, ql, kbuf, vtb, ab);

    // ---- 5. output projection + residual -> res2 fp32 ----
    hmma_gemm_kernel<1><<<dim3(2048 / 256, ROWS / 128), 256, GSMEM>>>(
        ab, wpool + OWO, hidden, nullptr, res2, nullptr, 2048, 2048);

    // ---- 6. rmsnorm2 -> fp16 ----
    rmsnorm_h_kernel<<<ROWS, 256>>>(res2, norm2_w, ab, HID);

    // ---- 7. gate GEMM -> fp16 (gateh; qkv dead now) ----
    hmma_gemm_kernel<3><<<dim3(FF / 256, ROWS / 128), 256, GSMEM>>>(
        ab, wpool + OWG, nullptr, nullptr, nullptr, gateh, FF, 2048);

    // ---- 8. up GEMM + fused silu(gate)*up -> fp16 (mbuf) ----
    hmma_gemm_kernel<2><<<dim3(FF / 256, ROWS / 128), 256, GSMEM>>>(
        ab, wpool + OWU, nullptr, gateh, nullptr, mbuf, FF, 2048);

    // ---- 9. down projection + residual -> out ----
    hmma_gemm_kernel<1><<<dim3(2048 / 256, ROWS / 128), 256, GSMEM>>>(
        mbuf, wpool + OWD, res2, nullptr, out, nullptr, 2048, 8192);
}

// round 10
// speedup vs baseline: 7.1705x; 1.0505x over previous
#include <cuda_runtime.h>
#include <cuda_bf16.h>
#include <cuda_fp16.h>
#include <math.h>
#include <stdint.h>

// ---------------- problem constants ----------------
#define HID   2048
#define NH    32
#define NKVH  8
#define HD    64
#define FF    8192
#define SEQ   2048
#define NB    2
#define ROWS  4096
#define EPS   1e-6f
#define MEG   (1024*1024)
#define L2E   1.4426950408889634f

// ---------------- scratch (device globals; no allocs allowed) ----------------
__device__ float g_res2[(size_t)ROWS * 2048];
__device__ float g_qkv [(size_t)ROWS * 3072];
__device__ __half g_m  [(size_t)ROWS * FF];          // silu(gate)*up fp16

// fp16 operands
__device__ __half g_a  [(size_t)ROWS * HID];
__device__ __half g_w  [(size_t)58 * MEG];

// attention fp16 operands
__device__ __half g_q  [(size_t)ROWS * 2048];
__device__ __half g_k  [(size_t)ROWS * 512];
__device__ __half g_vt [(size_t)ROWS * 512];

// ---------------- helpers ----------------
__device__ __forceinline__ uint32_t smem_u32(const void* p) {
    uint32_t a;
    asm("{ .reg .u64 t; cvta.to.shared.u64 t, %1; cvt.u32.u64 %0, t; }" : "=r"(a) : "l"(p));
    return a;
}

__device__ __forceinline__ void cpa16(uint32_t dst, const void* src) {
    asm volatile("cp.async.cg.shared.global [%0], [%1], 16;" :: "r"(dst), "l"(src));
}
__device__ __forceinline__ void cpa_commit() {
    asm volatile("cp.async.commit_group;" ::: "memory");
}

__device__ __forceinline__ void ldsm4(uint32_t* r, uint32_t addr) {
    asm volatile("ldmatrix.sync.aligned.m8n8.x4.shared.b16 {%0,%1,%2,%3}, [%4];"
        : "=r"(r[0]), "=r"(r[1]), "=r"(r[2]), "=r"(r[3]) : "r"(addr));
}

__device__ __forceinline__ void mma_f16(float* c, const uint32_t* a, const uint32_t* b) {
    asm volatile("mma.sync.aligned.m16n8k16.row.col.f32.f16.f16.f32 "
        "{%0,%1,%2,%3}, {%4,%5,%6,%7}, {%8,%9}, {%0,%1,%2,%3};"
        : "+f"(c[0]), "+f"(c[1]), "+f"(c[2]), "+f"(c[3])
        : "r"(a[0]), "r"(a[1]), "r"(a[2]), "r"(a[3]), "r"(b[0]), "r"(b[1]));
}

// FMA-only exp2, clamped both sides, |rel err| ~2e-6
__device__ __forceinline__ float fexp2(float z) {
    z = fminf(fmaxf(z, -126.f), 126.f);
    float sh = z + 12582912.f;
    float zi = sh - 12582912.f;
    float f = z - zi;
    float p = 0.0013333558f;
    p = p * f + 0.0096181291f;
    p = p * f + 0.0555041087f;
    p = p * f + 0.2402265070f;
    p = p * f + 0.6931471806f;
    p = p * f + 1.0f;
    int ei = __float_as_int(sh) - 0x4B400000;
    return p * __int_as_float((ei + 127) << 23);
}

__device__ __forceinline__ float fsilu(float x) {
    return x / (1.f + fexp2(-x * L2E));
}

// ---------------- converters ----------------
// W [K,N] fp32 -> Wt [N,K] fp16; 64k x 32n tiles, half2 stores (128B/warp-row)
__global__ void convT_kernel(const float* __restrict__ W,
                             __half* __restrict__ wT, int K, int N)
{
    __shared__ float t[64][33];
    int n0 = blockIdx.x * 32, k0 = blockIdx.y * 64;
    int tx = threadIdx.x & 31, ty = threadIdx.x >> 5;   // 8 rows of 32
    for (int ky = ty; ky < 64; ky += 8)
        t[ky][tx] = W[(size_t)(k0 + ky) * N + n0 + tx];
    __syncthreads();
    for (int ny = ty; ny < 32; ny += 8) {
        __half2 h;
        h.x = __float2half_rn(t[2 * tx][ny]);
        h.y = __float2half_rn(t[2 * tx + 1][ny]);
        *(__half2*)(wT + (size_t)(n0 + ny) * K + k0 + 2 * tx) = h;
    }
}

// gate/up interleaved conversion: G,U [K,8192] fp32 -> pool [16384,K] fp16
// gate col n -> row (n>>7)*256 + ((n>>6)&1)*128 + ((n>>3)&7)*16 + (n&7); up -> +8
__global__ void convT_gu_kernel(const float* __restrict__ G,
                                const float* __restrict__ U,
                                __half* __restrict__ wT, int K)
{
    __shared__ float tg[64][33];
    __shared__ float tu[64][33];
    int n0 = blockIdx.x * 32, k0 = blockIdx.y * 64;
    int tx = threadIdx.x & 31, ty = threadIdx.x >> 5;
    for (int ky = ty; ky < 64; ky += 8) {
        tg[ky][tx] = G[(size_t)(k0 + ky) * FF + n0 + tx];
        tu[ky][tx] = U[(size_t)(k0 + ky) * FF + n0 + tx];
    }
    __syncthreads();
    for (int ny = ty; ny < 32; ny += 8) {
        int n = n0 + ny;
        size_t rowG = (size_t)((n >> 7) * 256 + ((n >> 6) & 1) * 128 + ((n >> 3) & 7) * 16 + (n & 7));
        __half2 h;
        h.x = __float2half_rn(tg[2 * tx][ny]);
        h.y = __float2half_rn(tg[2 * tx + 1][ny]);
        *(__half2*)(wT + rowG * K + k0 + 2 * tx) = h;
        h.x = __float2half_rn(tu[2 * tx][ny]);
        h.y = __float2half_rn(tu[2 * tx + 1][ny]);
        *(__half2*)(wT + (rowG + 8) * K + k0 + 2 * tx) = h;
    }
}

// RMSNorm -> fp16
__global__ void rmsnorm_h_kernel(const float* __restrict__ x,
                                 const float* __restrict__ w,
                                 __half* __restrict__ o, int K)
{
    int row = blockIdx.x;
    const float* xr = x + (size_t)row * K;
    float ss = 0.f;
    int nvec = K / 4;
    const float4* xv = (const float4*)xr;
    for (int c = threadIdx.x; c < nvec; c += blockDim.x) {
        float4 v = xv[c];
        ss += v.x * v.x + v.y * v.y + v.z * v.z + v.w * v.w;
    }
    __shared__ float red[32];
    for (int off = 16; off > 0; off >>= 1) ss += __shfl_xor_sync(0xffffffffu, ss, off);
    int lane = threadIdx.x & 31, wid = threadIdx.x >> 5;
    if (lane == 0) red[wid] = ss;
    __syncthreads();
    int nwarp = blockDim.x >> 5;
    if (wid == 0) {
        float t = (lane < nwarp) ? red[lane] : 0.f;
        for (int off = 16; off > 0; off >>= 1) t += __shfl_xor_sync(0xffffffffu, t, off);
        if (lane == 0) red[0] = t;
    }
    __syncthreads();
    float inv = rsqrtf(red[0] / (float)K + EPS);

    for (int c = threadIdx.x; c < K / 2; c += blockDim.x) {
        int k = 2 * c;
        __half2 h;
        h.x = __float2half_rn(xr[k] * inv * w[k]);
        h.y = __float2half_rn(xr[k + 1] * inv * w[k + 1]);
        ((__half2*)(o + (size_t)row * K))[c] = h;
    }
}

// RoPE Q: fp32 qkv col 0+ -> q [b,h,s,d] fp16 single, scaled by 1/8
__global__ void rope_q_kernel(const float* __restrict__ x, __half* __restrict__ o)
{
    int row = blockIdx.x;
    int b = row >> 11, s = row & 2047;
    int t = threadIdx.x;
    int h = t >> 5, i = t & 31;
    float inv_freq = powf(10000.0f, -(float)(2 * i) / 64.0f);
    float ang = (float)s * inv_freq;
    float c, sn;
    __sincosf(ang, &sn, &c);
    const float* p = x + (size_t)row * 3072 + h * HD;
    float x1 = p[i], x2 = p[i + 32];
    size_t dst = ((size_t)(b * NH + h) * SEQ + s) * 64;
    o[dst + i]      = __float2half_rn((x1 * c - x2 * sn) * 0.125f);
    o[dst + i + 32] = __float2half_rn((x2 * c + x1 * sn) * 0.125f);
}

// RoPE K: fp32 qkv col 2048+ -> k [b,kvh,s,d] fp16 single
__global__ void rope_k_kernel(const float* __restrict__ x, __half* __restrict__ o)
{
    int row = blockIdx.x;
    int b = row >> 11, s = row & 2047;
    int t = threadIdx.x;
    int h = t >> 5, i = t & 31;
    float inv_freq = powf(10000.0f, -(float)(2 * i) / 64.0f);
    float ang = (float)s * inv_freq;
    float c, sn;
    __sincosf(ang, &sn, &c);
    const float* p = x + (size_t)row * 3072 + 2048 + h * HD;
    float x1 = p[i], x2 = p[i + 32];
    size_t dst = ((size_t)(b * NKVH + h) * SEQ + s) * 64;
    o[dst + i]      = __float2half_rn(x1 * c - x2 * sn);
    o[dst + i + 32] = __float2half_rn(x2 * c + x1 * sn);
}

// V transpose: qkv fp32 col 2560+ -> vt [b,kvh,d,s] fp16 single
__global__ void vt_kernel(const float* __restrict__ v, __half* __restrict__ oT)
{
    __shared__ float t[32][33];
    int s0 = blockIdx.x * 32, d0 = blockIdx.y * 32;
    int bz = blockIdx.z;
    int b = bz >> 3, kvh = bz & 7;
    int tx = threadIdx.x, ty = threadIdx.y;
    for (int sy = ty; sy < 32; sy += 8)
        t[sy][tx] = v[(size_t)(b * SEQ + s0 + sy) * 3072 + 2560 + kvh * 64 + d0 + tx];
    __syncthreads();
    for (int dy = ty; dy < 32; dy += 8)
        oT[((size_t)bz * 64 + d0 + dy) * SEQ + s0 + tx] = __float2half_rn(t[tx][dy]);
}

// ---------------- HMMA GEMM: 128(M) x 256(N) tile, BK=32, 4-stage, fp16 ----------------
// EPI 0: C = A@B^T (fp32)
// EPI 1: C = A@B^T + RES (fp32)
// EPI 4: gate/up interleaved: OH = fp16(silu(acc_even) * acc_odd), output pitch FF
#define APITCH 80
#define A_MAT  10240
#define B_MAT  20480
#define STG_SZ (A_MAT + B_MAT)
#define GSMEM  (4 * STG_SZ)

template<int EPI>
__global__ void __launch_bounds__(256, 1)
hmma_gemm_kernel(const __half* __restrict__ A, const __half* __restrict__ B,
                 const float* __restrict__ RES,
                 float* __restrict__ C, __half* __restrict__ OH, int N, int K)
{
    extern __shared__ char sm[];
    uint32_t smb = smem_u32(sm);
    int tid = threadIdx.x, lane = tid & 31, wid = tid >> 5;
    int wm = wid & 3, wn = wid >> 2;
    int bm = blockIdx.y, bn = blockIdx.x;
    int NKT = K / 32;

    const __half* gA = A + (size_t)bm * 128 * K;
    const __half* gB = B + (size_t)bn * 256 * K;

    int rbase = tid >> 2;
    int ch = tid & 3;

    auto issue = [&](int st, int kt) {
        uint32_t base = smb + st * STG_SZ;
        int koff = kt * 32 + ch * 8;
#pragma unroll
        for (int u = 0; u < 2; u++) {
            int r = rbase + u * 64;
            cpa16(base + r * APITCH + ch * 16, gA + (size_t)r * K + koff);
        }
        uint32_t bB = base + A_MAT;
#pragma unroll
        for (int u = 0; u < 4; u++) {
            int r = rbase + u * 64;
            cpa16(bB + r * APITCH + ch * 16, gB + (size_t)r * K + koff);
        }
        cpa_commit();
    };

    float acc[2][16][4];
#pragma unroll
    for (int s = 0; s < 2; s++)
#pragma unroll
        for (int t = 0; t < 16; t++)
#pragma unroll
            for (int j = 0; j < 4; j++) acc[s][t][j] = 0.f;

    issue(0, 0);
    issue(1, 1);
    issue(2, 2);

    int a_row = wm * 32 + (lane & 15);
    int a_kb  = (lane >> 4) * 16;
    int b_ro  = ((lane >> 4) << 3) + (lane & 7);
    int b_kb  = ((lane >> 3) & 1) * 16;

    for (int kt = 0; kt < NKT; kt++) {
        int st = kt & 3;
        if (kt + 3 < NKT) issue((kt + 3) & 3, kt + 3);
        else cpa_commit();
        asm volatile("cp.async.wait_group 3;" ::: "memory");
        __syncthreads();

        uint32_t sA = smb + st * STG_SZ;
        uint32_t sB = sA + A_MAT;

#pragma unroll
        for (int ks = 0; ks < 2; ks++) {
            int kB = ks * 32;
            uint32_t a4[2][4];
            ldsm4(a4[0], sA + (a_row)      * APITCH + kB + a_kb);
            ldsm4(a4[1], sA + (a_row + 16) * APITCH + kB + a_kb);
#pragma unroll
            for (int gi = 0; gi < 8; gi++) {
                int brow = wn * 128 + gi * 16 + b_ro;
                uint32_t b4[4];
                ldsm4(b4, sB + brow * APITCH + kB + b_kb);
#pragma unroll
                for (int t = 0; t < 2; t++) {
                    const uint32_t* bp = &b4[t * 2];
#pragma unroll
                    for (int sub = 0; sub < 2; sub++)
                        mma_f16(acc[sub][gi * 2 + t], a4[sub], bp);
                }
            }
        }
        __syncthreads();
    }

    // epilogue
#pragma unroll
    for (int sub = 0; sub < 2; sub++) {
        int row0 = bm * 128 + wm * 32 + sub * 16 + (lane >> 2);
        if (EPI == 4) {
#pragma unroll
            for (int j = 0; j < 8; j++) {
                int col = bn * 128 + wn * 64 + j * 8 + (lane & 3) * 2;
                size_t o0 = (size_t)row0 * FF + col;
                size_t o1 = o0 + (size_t)8 * FF;
                float* g = acc[sub][2 * j];
                float* u = acc[sub][2 * j + 1];
                __half2 H0, H1;
                H0.x = __float2half_rn(fsilu(g[0]) * u[0]);
                H0.y = __float2half_rn(fsilu(g[1]) * u[1]);
                H1.x = __float2half_rn(fsilu(g[2]) * u[2]);
                H1.y = __float2half_rn(fsilu(g[3]) * u[3]);
                *(__half2*)(OH + o0) = H0;
                *(__half2*)(OH + o1) = H1;
            }
        } else {
#pragma unroll
            for (int t = 0; t < 16; t++) {
                int col = bn * 256 + wn * 128 + t * 8 + (lane & 3) * 2;
                size_t o0 = (size_t)row0 * N + col;
                size_t o1 = o0 + (size_t)8 * N;
                float2 v0 = make_float2(acc[sub][t][0], acc[sub][t][1]);
                float2 v1 = make_float2(acc[sub][t][2], acc[sub][t][3]);
                if (EPI == 1) {
                    float2 r0 = *(const float2*)(RES + o0);
                    float2 r1 = *(const float2*)(RES + o1);
                    v0.x += r0.x; v0.y += r0.y;
                    v1.x += r1.x; v1.y += r1.y;
                }
                *(float2*)(C + o0) = v0;
                *(float2*)(C + o1) = v1;
            }
        }
    }
}

// ---------------- tensor-core causal attention (fp16 single Q/K/P/V) ----------------
#define AT_PITCH 144
#define AT_MAT   (64 * AT_PITCH)
#define AT_Q  0
#define AT_K  (AT_MAT)
#define AT_V  (2 * AT_MAT)
#define AT_SMEM (3 * AT_MAT)     // 27648

__global__ void __launch_bounds__(128)
attn_mma_kernel(const __half* __restrict__ qq, const __half* __restrict__ kk,
                const __half* __restrict__ vt, __half* __restrict__ OH)
{
    extern __shared__ char sm[];
    uint32_t smb = smem_u32(sm);
    int qt = blockIdx.x, h = blockIdx.y, b = blockIdx.z;
    int kvh = h >> 2;
    int tid = threadIdx.x, lane = tid & 31, w = tid >> 5;
    int q0 = qt * 64;

    const __half* Qp = qq + ((size_t)(b * NH + h) * SEQ + q0) * 64;
    const __half* Kp = kk + ((size_t)(b * NKVH + kvh) * SEQ) * 64;
    const __half* Vp = vt + ((size_t)(b * NKVH + kvh) * 64) * SEQ;

#pragma unroll
    for (int it = 0; it < 4; it++) {
        int idx = it * 128 + tid;
        int r = idx >> 3, ch = idx & 7;
        cpa16(smb + AT_Q + r * AT_PITCH + ch * 16, Qp + (size_t)r * 64 + ch * 8);
    }
    cpa_commit();
    asm volatile("cp.async.wait_group 0;" ::: "memory");
    __syncthreads();

    int r0 = lane >> 2, cq = lane & 3;
    int a_row = w * 16 + (lane & 15);
    int a_kb  = (lane >> 4) * 16;
    int b_ro  = ((lane >> 4) << 3) + (lane & 7);
    int b_kb  = ((lane >> 3) & 1) * 16;

    uint32_t qf[4][4];
#pragma unroll
    for (int kc = 0; kc < 4; kc++)
        ldsm4(qf[kc], smb + AT_Q + a_row * AT_PITCH + kc * 32 + a_kb);
    __syncthreads();

    float m0 = -1e30f, m1 = -1e30f, l0 = 0.f, l1 = 0.f;
    float ao[8][4];
#pragma unroll
    for (int nt = 0; nt < 8; nt++)
#pragma unroll
        for (int j = 0; j < 4; j++) ao[nt][j] = 0.f;

    for (int kt = 0; kt <= qt; kt++) {
        int k0 = kt * 64;
#pragma unroll
        for (int it = 0; it < 4; it++) {
            int idx = it * 128 + tid;
            int r = idx >> 3, ch = idx & 7;
            cpa16(smb + AT_K + r * AT_PITCH + ch * 16, Kp + (size_t)(k0 + r) * 64 + ch * 8);
            cpa16(smb + AT_V + r * AT_PITCH + ch * 16, Vp + (size_t)r * SEQ + k0 + ch * 8);
        }
        cpa_commit();
        asm volatile("cp.async.wait_group 0;" ::: "memory");
        __syncthreads();

        float sc[8][4];
#pragma unroll
        for (int nt = 0; nt < 8; nt++)
#pragma unroll
            for (int j = 0; j < 4; j++) sc[nt][j] = 0.f;

#pragma unroll
        for (int kc = 0; kc < 4; kc++) {
#pragma unroll
            for (int gi = 0; gi < 4; gi++) {
                uint32_t k4[4];
                ldsm4(k4, smb + AT_K + (gi * 16 + b_ro) * AT_PITCH + kc * 32 + b_kb);
#pragma unroll
                for (int t = 0; t < 2; t++)
                    mma_f16(sc[gi * 2 + t], qf[kc], &k4[t * 2]);
            }
        }

        if (kt == qt) {
            int qr0 = w * 16 + r0, qr1 = qr0 + 8;
#pragma unroll
            for (int nt = 0; nt < 8; nt++) {
                int col = nt * 8 + cq * 2;
                if (col     > qr0) sc[nt][0] = -1e30f;
                if (col + 1 > qr0) sc[nt][1] = -1e30f;
                if (col     > qr1) sc[nt][2] = -1e30f;
                if (col + 1 > qr1) sc[nt][3] = -1e30f;
            }
        }

        float tm0 = -1e30f, tm1 = -1e30f;
#pragma unroll
        for (int nt = 0; nt < 8; nt++) {
            tm0 = fmaxf(tm0, fmaxf(sc[nt][0], sc[nt][1]));
            tm1 = fmaxf(tm1, fmaxf(sc[nt][2], sc[nt][3]));
        }
        tm0 = fmaxf(tm0, __shfl_xor_sync(0xffffffffu, tm0, 1));
        tm0 = fmaxf(tm0, __shfl_xor_sync(0xffffffffu, tm0, 2));
        tm1 = fmaxf(tm1, __shfl_xor_sync(0xffffffffu, tm1, 1));
        tm1 = fmaxf(tm1, __shfl_xor_sync(0xffffffffu, tm1, 2));
        float mn0 = fmaxf(m0, tm0), mn1 = fmaxf(m1, tm1);
        float cr0 = fexp2((m0 - mn0) * L2E);
        float cr1 = fexp2((m1 - mn1) * L2E);
        float rs0 = 0.f, rs1 = 0.f;
#pragma unroll
        for (int nt = 0; nt < 8; nt++) {
            sc[nt][0] = fexp2((sc[nt][0] - mn0) * L2E);
            sc[nt][1] = fexp2((sc[nt][1] - mn0) * L2E);
            sc[nt][2] = fexp2((sc[nt][2] - mn1) * L2E);
            sc[nt][3] = fexp2((sc[nt][3] - mn1) * L2E);
            rs0 += sc[nt][0] + sc[nt][1];
            rs1 += sc[nt][2] + sc[nt][3];
        }
        rs0 += __shfl_xor_sync(0xffffffffu, rs0, 1);
        rs0 += __shfl_xor_sync(0xffffffffu, rs0, 2);
        rs1 += __shfl_xor_sync(0xffffffffu, rs1, 1);
        rs1 += __shfl_xor_sync(0xffffffffu, rs1, 2);
        l0 = l0 * cr0 + rs0;
        l1 = l1 * cr1 + rs1;
        m0 = mn0; m1 = mn1;
#pragma unroll
        for (int nt = 0; nt < 8; nt++) {
            ao[nt][0] *= cr0; ao[nt][1] *= cr0;
            ao[nt][2] *= cr1; ao[nt][3] *= cr1;
        }

#pragma unroll
        for (int j = 0; j < 4; j++) {
            uint32_t pa[4];
#pragma unroll
            for (int u = 0; u < 2; u++) {
                __half2 H0 = __floats2half2_rn(sc[2 * j + u][0], sc[2 * j + u][1]);
                __half2 H1 = __floats2half2_rn(sc[2 * j + u][2], sc[2 * j + u][3]);
                pa[2 * u + 0] = *(uint32_t*)&H0;
                pa[2 * u + 1] = *(uint32_t*)&H1;
            }
#pragma unroll
            for (int gi = 0; gi < 4; gi++) {
                uint32_t v4[4];
                ldsm4(v4, smb + AT_V + (gi * 16 + b_ro) * AT_PITCH + j * 32 + b_kb);
#pragma unroll
                for (int t = 0; t < 2; t++)
                    mma_f16(ao[gi * 2 + t], pa, &v4[t * 2]);
            }
        }
        __syncthreads();
    }

    float i0 = 1.f / l0, i1 = 1.f / l1;
    int rowA = q0 + w * 16 + r0;
    int rowB = rowA + 8;
#pragma unroll
    for (int nt = 0; nt < 8; nt++) {
        int col = h * 64 + nt * 8 + cq * 2;
        size_t oA = ((size_t)(b * SEQ) + rowA) * 2048 + col;
        size_t oB = ((size_t)(b * SEQ) + rowB) * 2048 + col;
        *(__half2*)(OH + oA) = __floats2half2_rn(ao[nt][0] * i0, ao[nt][1] * i0);
        *(__half2*)(OH + oB) = __floats2half2_rn(ao[nt][2] * i1, ao[nt][3] * i1);
    }
}

// ---------------- host launch ----------------
extern "C" void kernel_launch(void* const* d_in, const int* in_sizes, int n_in,
                              void* d_out, int out_size)
{
    const float* hidden  = (const float*)d_in[0];
    const float* norm1_w = (const float*)d_in[2];
    const float* wq      = (const float*)d_in[3];
    const float* wk      = (const float*)d_in[4];
    const float* wv      = (const float*)d_in[5];
    const float* wo      = (const float*)d_in[6];
    const float* norm2_w = (const float*)d_in[7];
    const float* w_gate  = (const float*)d_in[8];
    const float* w_up    = (const float*)d_in[9];
    const float* w_down  = (const float*)d_in[10];
    float* out = (float*)d_out;

    float *res2, *qkv;
    __half *ab, *wpool, *qb, *kbuf, *vtb, *mbuf;
    cudaGetSymbolAddress((void**)&res2, g_res2);
    cudaGetSymbolAddress((void**)&qkv,  g_qkv);
    cudaGetSymbolAddress((void**)&mbuf, g_m);
    cudaGetSymbolAddress((void**)&ab,   g_a);
    cudaGetSymbolAddress((void**)&wpool, g_w);
    cudaGetSymbolAddress((void**)&qb,   g_q);
    cudaGetSymbolAddress((void**)&kbuf, g_k);
    cudaGetSymbolAddress((void**)&vtb,  g_vt);

    // weight pool offsets (elements)
    const size_t OQKV = 0;                     // 3072 x 2048
    const size_t OWO  = 6ull * MEG;            // 2048 x 2048
    const size_t OGU  = 10ull * MEG;           // 16384 x 2048 (interleaved gate/up)
    const size_t OWD  = 42ull * MEG;           // 2048 x 8192

    cudaFuncSetAttribute(hmma_gemm_kernel<0>, cudaFuncAttributeMaxDynamicSharedMemorySize, GSMEM);
    cudaFuncSetAttribute(hmma_gemm_kernel<1>, cudaFuncAttributeMaxDynamicSharedMemorySize, GSMEM);
    cudaFuncSetAttribute(hmma_gemm_kernel<4>, cudaFuncAttributeMaxDynamicSharedMemorySize, GSMEM);
    cudaFuncSetAttribute(attn_mma_kernel, cudaFuncAttributeMaxDynamicSharedMemorySize, AT_SMEM);

    // ---- weight conversions ----
    convT_kernel<<<dim3(64, 32), 256>>>(wq, wpool + OQKV, 2048, 2048);
    convT_kernel<<<dim3(16, 32), 256>>>(wk, wpool + OQKV + 2048ull * 2048, 2048, 512);
    convT_kernel<<<dim3(16, 32), 256>>>(wv, wpool + OQKV + 2560ull * 2048, 2048, 512);
    convT_kernel<<<dim3(64, 32), 256>>>(wo, wpool + OWO, 2048, 2048);
    convT_gu_kernel<<<dim3(256, 32), 256>>>(w_gate, w_up, wpool + OGU, 2048);
    convT_kernel<<<dim3(64, 128), 256>>>(w_down, wpool + OWD, 8192, 2048);

    // ---- 1. rmsnorm1 -> fp16 ----
    rmsnorm_h_kernel<<<ROWS, 256>>>(hidden, norm1_w, ab, HID);

    // ---- 2. fused QKV GEMM -> qkv fp32 ----
    hmma_gemm_kernel<0><<<dim3(3072 / 256, ROWS / 128), 256, GSMEM>>>(
        ab, wpool + OQKV, nullptr, qkv, nullptr, 3072, 2048);

    // ---- 3. RoPE Q/K + V transpose ----
    rope_q_kernel<<<ROWS, NH * 32>>>(qkv, qb);
    rope_k_kernel<<<ROWS, NKVH * 32>>>(qkv, kbuf);
    vt_kernel<<<dim3(SEQ / 32, 2, NB * NKVH), dim3(32, 8)>>>(qkv, vtb);

    // ---- 4. attention -> ctx fp16 (ab) ----
    attn_mma_kernel<<<dim3(SEQ / 64, NH, NB), 128, AT_SMEM>>>(qb, kbuf, vtb, ab);

    // ---- 5. output projection + residual -> res2 fp32 ----
    hmma_gemm_kernel<1><<<dim3(2048 / 256, ROWS / 128), 256, GSMEM>>>(
        ab, wpool + OWO, hidden, res2, nullptr, 2048, 2048);

    // ---- 6. rmsnorm2 -> fp16 ----
    rmsnorm_h_kernel<<<ROWS, 256>>>(res2, norm2_w, ab, HID);

    // ---- 7. fused gate+up GEMM + silu-mul -> fp16 (mbuf) ----
    hmma_gemm_kernel<4><<<dim3(2 * FF / 256, ROWS / 128), 256, GSMEM>>>(
        ab, wpool + OGU, nullptr, nullptr, mbuf, FF, 2048);

    // ---- 8. down projection + residual -> out ----
    hmma_gemm_kernel<1><<<dim3(2048 / 256, ROWS / 128), 256, GSMEM>>>(
        mbuf, wpool + OWD, res2, out, nullptr, 2048, 8192);
}

// round 11
// speedup vs baseline: 7.4487x; 1.0388x over previous
#include <cuda_runtime.h>
#include <cuda_bf16.h>
#include <cuda_fp16.h>
#include <math.h>
#include <stdint.h>

// ---------------- problem constants ----------------
#define HID   2048
#define NH    32
#define NKVH  8
#define HD    64
#define FF    8192
#define SEQ   2048
#define NB    2
#define ROWS  4096
#define EPS   1e-6f
#define MEG   (1024*1024)
#define L2E   1.4426950408889634f

// ---------------- scratch (device globals; no allocs allowed) ----------------
__device__ float g_res2[(size_t)ROWS * 2048];
__device__ float g_qkv [(size_t)ROWS * 3072];
__device__ __half g_m  [(size_t)ROWS * FF];

__device__ __half g_a  [(size_t)ROWS * HID];
__device__ __half g_w  [(size_t)58 * MEG];

__device__ __half g_q  [(size_t)ROWS * 2048];
__device__ __half g_k  [(size_t)ROWS * 512];
__device__ __half g_vt [(size_t)ROWS * 512];

// ---------------- helpers ----------------
__device__ __forceinline__ uint32_t smem_u32(const void* p) {
    uint32_t a;
    asm("{ .reg .u64 t; cvta.to.shared.u64 t, %1; cvt.u32.u64 %0, t; }" : "=r"(a) : "l"(p));
    return a;
}

__device__ __forceinline__ void cpa16(uint32_t dst, const void* src) {
    asm volatile("cp.async.cg.shared.global [%0], [%1], 16;" :: "r"(dst), "l"(src));
}
__device__ __forceinline__ void cpa_commit() {
    asm volatile("cp.async.commit_group;" ::: "memory");
}

__device__ __forceinline__ void ldsm4(uint32_t* r, uint32_t addr) {
    asm volatile("ldmatrix.sync.aligned.m8n8.x4.shared.b16 {%0,%1,%2,%3}, [%4];"
        : "=r"(r[0]), "=r"(r[1]), "=r"(r[2]), "=r"(r[3]) : "r"(addr));
}

__device__ __forceinline__ void mma_f16(float* c, const uint32_t* a, const uint32_t* b) {
    asm volatile("mma.sync.aligned.m16n8k16.row.col.f32.f16.f16.f32 "
        "{%0,%1,%2,%3}, {%4,%5,%6,%7}, {%8,%9}, {%0,%1,%2,%3};"
        : "+f"(c[0]), "+f"(c[1]), "+f"(c[2]), "+f"(c[3])
        : "r"(a[0]), "r"(a[1]), "r"(a[2]), "r"(a[3]), "r"(b[0]), "r"(b[1]));
}

__device__ __forceinline__ float fexp2(float z) {
    z = fminf(fmaxf(z, -126.f), 126.f);
    float sh = z + 12582912.f;
    float zi = sh - 12582912.f;
    float f = z - zi;
    float p = 0.0013333558f;
    p = p * f + 0.0096181291f;
    p = p * f + 0.0555041087f;
    p = p * f + 0.2402265070f;
    p = p * f + 0.6931471806f;
    p = p * f + 1.0f;
    int ei = __float_as_int(sh) - 0x4B400000;
    return p * __int_as_float((ei + 127) << 23);
}

__device__ __forceinline__ float fsilu(float x) {
    return x / (1.f + fexp2(-x * L2E));
}

// ---------------- converters ----------------
// W [K,N] fp32 -> Wt [N,K] fp16; 64k x 64n tiles, float4 loads, half2 stores
__global__ void convT_kernel(const float* __restrict__ W,
                             __half* __restrict__ wT, int K, int N)
{
    __shared__ float t[64][67];
    int n0 = blockIdx.x * 64, k0 = blockIdx.y * 64;
    int tx = threadIdx.x & 31, ty = threadIdx.x >> 5;
    // load 64 rows x 64 floats, float4
    int cx = threadIdx.x & 15;          // 16 float4 per row
    int ry = threadIdx.x >> 4;          // 16 rows per pass
    for (int ky = ry; ky < 64; ky += 16) {
        float4 v = *(const float4*)(W + (size_t)(k0 + ky) * N + n0 + cx * 4);
        t[ky][cx * 4 + 0] = v.x; t[ky][cx * 4 + 1] = v.y;
        t[ky][cx * 4 + 2] = v.z; t[ky][cx * 4 + 3] = v.w;
    }
    __syncthreads();
    for (int ny = ty; ny < 64; ny += 8) {
        __half2 h;
        h.x = __float2half_rn(t[2 * tx][ny]);
        h.y = __float2half_rn(t[2 * tx + 1][ny]);
        *(__half2*)(wT + (size_t)(n0 + ny) * K + k0 + 2 * tx) = h;
    }
}

// gate/up interleaved: G,U [K,8192] fp32 -> pool [16384,K] fp16, 64x64 tiles
__global__ void convT_gu_kernel(const float* __restrict__ G,
                                const float* __restrict__ U,
                                __half* __restrict__ wT, int K)
{
    __shared__ float tg[64][67];
    __shared__ float tu[64][67];
    int n0 = blockIdx.x * 64, k0 = blockIdx.y * 64;
    int tx = threadIdx.x & 31, ty = threadIdx.x >> 5;
    int cx = threadIdx.x & 15;
    int ry = threadIdx.x >> 4;
    for (int ky = ry; ky < 64; ky += 16) {
        float4 v = *(const float4*)(G + (size_t)(k0 + ky) * FF + n0 + cx * 4);
        tg[ky][cx * 4 + 0] = v.x; tg[ky][cx * 4 + 1] = v.y;
        tg[ky][cx * 4 + 2] = v.z; tg[ky][cx * 4 + 3] = v.w;
        float4 u = *(const float4*)(U + (size_t)(k0 + ky) * FF + n0 + cx * 4);
        tu[ky][cx * 4 + 0] = u.x; tu[ky][cx * 4 + 1] = u.y;
        tu[ky][cx * 4 + 2] = u.z; tu[ky][cx * 4 + 3] = u.w;
    }
    __syncthreads();
    for (int ny = ty; ny < 64; ny += 8) {
        int n = n0 + ny;
        size_t rowG = (size_t)((n >> 7) * 256 + ((n >> 6) & 1) * 128 + ((n >> 3) & 7) * 16 + (n & 7));
        __half2 h;
        h.x = __float2half_rn(tg[2 * tx][ny]);
        h.y = __float2half_rn(tg[2 * tx + 1][ny]);
        *(__half2*)(wT + rowG * K + k0 + 2 * tx) = h;
        h.x = __float2half_rn(tu[2 * tx][ny]);
        h.y = __float2half_rn(tu[2 * tx + 1][ny]);
        *(__half2*)(wT + (rowG + 8) * K + k0 + 2 * tx) = h;
    }
}

// RMSNorm -> fp16
__global__ void rmsnorm_h_kernel(const float* __restrict__ x,
                                 const float* __restrict__ w,
                                 __half* __restrict__ o, int K)
{
    int row = blockIdx.x;
    const float* xr = x + (size_t)row * K;
    float ss = 0.f;
    int nvec = K / 4;
    const float4* xv = (const float4*)xr;
    for (int c = threadIdx.x; c < nvec; c += blockDim.x) {
        float4 v = xv[c];
        ss += v.x * v.x + v.y * v.y + v.z * v.z + v.w * v.w;
    }
    __shared__ float red[32];
    for (int off = 16; off > 0; off >>= 1) ss += __shfl_xor_sync(0xffffffffu, ss, off);
    int lane = threadIdx.x & 31, wid = threadIdx.x >> 5;
    if (lane == 0) red[wid] = ss;
    __syncthreads();
    int nwarp = blockDim.x >> 5;
    if (wid == 0) {
        float t = (lane < nwarp) ? red[lane] : 0.f;
        for (int off = 16; off > 0; off >>= 1) t += __shfl_xor_sync(0xffffffffu, t, off);
        if (lane == 0) red[0] = t;
    }
    __syncthreads();
    float inv = rsqrtf(red[0] / (float)K + EPS);

    for (int c = threadIdx.x; c < K / 2; c += blockDim.x) {
        int k = 2 * c;
        __half2 h;
        h.x = __float2half_rn(xr[k] * inv * w[k]);
        h.y = __float2half_rn(xr[k + 1] * inv * w[k + 1]);
        ((__half2*)(o + (size_t)row * K))[c] = h;
    }
}

// RoPE Q
__global__ void rope_q_kernel(const float* __restrict__ x, __half* __restrict__ o)
{
    int row = blockIdx.x;
    int b = row >> 11, s = row & 2047;
    int t = threadIdx.x;
    int h = t >> 5, i = t & 31;
    float inv_freq = powf(10000.0f, -(float)(2 * i) / 64.0f);
    float ang = (float)s * inv_freq;
    float c, sn;
    __sincosf(ang, &sn, &c);
    const float* p = x + (size_t)row * 3072 + h * HD;
    float x1 = p[i], x2 = p[i + 32];
    size_t dst = ((size_t)(b * NH + h) * SEQ + s) * 64;
    o[dst + i]      = __float2half_rn((x1 * c - x2 * sn) * 0.125f);
    o[dst + i + 32] = __float2half_rn((x2 * c + x1 * sn) * 0.125f);
}

// RoPE K
__global__ void rope_k_kernel(const float* __restrict__ x, __half* __restrict__ o)
{
    int row = blockIdx.x;
    int b = row >> 11, s = row & 2047;
    int t = threadIdx.x;
    int h = t >> 5, i = t & 31;
    float inv_freq = powf(10000.0f, -(float)(2 * i) / 64.0f);
    float ang = (float)s * inv_freq;
    float c, sn;
    __sincosf(ang, &sn, &c);
    const float* p = x + (size_t)row * 3072 + 2048 + h * HD;
    float x1 = p[i], x2 = p[i + 32];
    size_t dst = ((size_t)(b * NKVH + h) * SEQ + s) * 64;
    o[dst + i]      = __float2half_rn(x1 * c - x2 * sn);
    o[dst + i + 32] = __float2half_rn(x2 * c + x1 * sn);
}

// V transpose
__global__ void vt_kernel(const float* __restrict__ v, __half* __restrict__ oT)
{
    __shared__ float t[32][33];
    int s0 = blockIdx.x * 32, d0 = blockIdx.y * 32;
    int bz = blockIdx.z;
    int b = bz >> 3, kvh = bz & 7;
    int tx = threadIdx.x, ty = threadIdx.y;
    for (int sy = ty; sy < 32; sy += 8)
        t[sy][tx] = v[(size_t)(b * SEQ + s0 + sy) * 3072 + 2560 + kvh * 64 + d0 + tx];
    __syncthreads();
    for (int dy = ty; dy < 32; dy += 8)
        oT[((size_t)bz * 64 + d0 + dy) * SEQ + s0 + tx] = __float2half_rn(t[tx][dy]);
}

// ---------------- HMMA GEMM: 128x256 tile, BK=32, 4-stage, single sync/iter ----------------
#define APITCH 80
#define A_MAT  10240
#define B_MAT  20480
#define STG_SZ (A_MAT + B_MAT)
#define GSMEM  (4 * STG_SZ)

template<int EPI>
__global__ void __launch_bounds__(256, 1)
hmma_gemm_kernel(const __half* __restrict__ A, const __half* __restrict__ B,
                 const float* __restrict__ RES,
                 float* __restrict__ C, __half* __restrict__ OH, int N, int K)
{
    extern __shared__ char sm[];
    uint32_t smb = smem_u32(sm);
    int tid = threadIdx.x, lane = tid & 31, wid = tid >> 5;
    int wm = wid & 3, wn = wid >> 2;
    int bm = blockIdx.y, bn = blockIdx.x;
    int NKT = K / 32;

    const __half* gA = A + (size_t)bm * 128 * K;
    const __half* gB = B + (size_t)bn * 256 * K;

    int rbase = tid >> 2;
    int ch = tid & 3;

    auto issue = [&](int st, int kt) {
        uint32_t base = smb + st * STG_SZ;
        int koff = kt * 32 + ch * 8;
#pragma unroll
        for (int u = 0; u < 2; u++) {
            int r = rbase + u * 64;
            cpa16(base + r * APITCH + ch * 16, gA + (size_t)r * K + koff);
        }
        uint32_t bB = base + A_MAT;
#pragma unroll
        for (int u = 0; u < 4; u++) {
            int r = rbase + u * 64;
            cpa16(bB + r * APITCH + ch * 16, gB + (size_t)r * K + koff);
        }
        cpa_commit();
    };

    float acc[2][16][4];
#pragma unroll
    for (int s = 0; s < 2; s++)
#pragma unroll
        for (int t = 0; t < 16; t++)
#pragma unroll
            for (int j = 0; j < 4; j++) acc[s][t][j] = 0.f;

    issue(0, 0);
    issue(1, 1);
    issue(2, 2);

    int a_row = wm * 32 + (lane & 15);
    int a_kb  = (lane >> 4) * 16;
    int b_ro  = ((lane >> 4) << 3) + (lane & 7);
    int b_kb  = ((lane >> 3) & 1) * 16;

    // invariant: 3 groups pending before each wait; wait<=2 drains group kt
    for (int kt = 0; kt < NKT; kt++) {
        int st = kt & 3;
        asm volatile("cp.async.wait_group 2;" ::: "memory");
        __syncthreads();
        if (kt + 3 < NKT) issue((kt + 3) & 3, kt + 3);
        else cpa_commit();                 // empty group keeps accounting

        uint32_t sA = smb + st * STG_SZ;
        uint32_t sB = sA + A_MAT;

#pragma unroll
        for (int ks = 0; ks < 2; ks++) {
            int kB = ks * 32;
            uint32_t a4[2][4];
            ldsm4(a4[0], sA + (a_row)      * APITCH + kB + a_kb);
            ldsm4(a4[1], sA + (a_row + 16) * APITCH + kB + a_kb);
#pragma unroll
            for (int gi = 0; gi < 8; gi++) {
                int brow = wn * 128 + gi * 16 + b_ro;
                uint32_t b4[4];
                ldsm4(b4, sB + brow * APITCH + kB + b_kb);
#pragma unroll
                for (int t = 0; t < 2; t++) {
                    const uint32_t* bp = &b4[t * 2];
#pragma unroll
                    for (int sub = 0; sub < 2; sub++)
                        mma_f16(acc[sub][gi * 2 + t], a4[sub], bp);
                }
            }
        }
    }

    // epilogue
#pragma unroll
    for (int sub = 0; sub < 2; sub++) {
        int row0 = bm * 128 + wm * 32 + sub * 16 + (lane >> 2);
        if (EPI == 4) {
#pragma unroll
            for (int j = 0; j < 8; j++) {
                int col = bn * 128 + wn * 64 + j * 8 + (lane & 3) * 2;
                size_t o0 = (size_t)row0 * FF + col;
                size_t o1 = o0 + (size_t)8 * FF;
                float* g = acc[sub][2 * j];
                float* u = acc[sub][2 * j + 1];
                __half2 H0, H1;
                H0.x = __float2half_rn(fsilu(g[0]) * u[0]);
                H0.y = __float2half_rn(fsilu(g[1]) * u[1]);
                H1.x = __float2half_rn(fsilu(g[2]) * u[2]);
                H1.y = __float2half_rn(fsilu(g[3]) * u[3]);
                *(__half2*)(OH + o0) = H0;
                *(__half2*)(OH + o1) = H1;
            }
        } else {
#pragma unroll
            for (int t = 0; t < 16; t++) {
                int col = bn * 256 + wn * 128 + t * 8 + (lane & 3) * 2;
                size_t o0 = (size_t)row0 * N + col;
                size_t o1 = o0 + (size_t)8 * N;
                float2 v0 = make_float2(acc[sub][t][0], acc[sub][t][1]);
                float2 v1 = make_float2(acc[sub][t][2], acc[sub][t][3]);
                if (EPI == 1) {
                    float2 r0 = *(const float2*)(RES + o0);
                    float2 r1 = *(const float2*)(RES + o1);
                    v0.x += r0.x; v0.y += r0.y;
                    v1.x += r1.x; v1.y += r1.y;
                }
                *(float2*)(C + o0) = v0;
                *(float2*)(C + o1) = v1;
            }
        }
    }
}

// ---------------- tensor-core causal attention (2-stage K/V pipeline) ----------------
#define AT_PITCH 144
#define AT_MAT   (64 * AT_PITCH)
#define AT_Q   0
#define AT_KV  (AT_MAT)               // 2 stages x (K + V)
#define AT_SMEM (AT_MAT + 2 * 2 * AT_MAT)   // Q + 2*(K,V) = 46080

__global__ void __launch_bounds__(128)
attn_mma_kernel(const __half* __restrict__ qq, const __half* __restrict__ kk,
                const __half* __restrict__ vt, __half* __restrict__ OH)
{
    extern __shared__ char sm[];
    uint32_t smb = smem_u32(sm);
    int qt = blockIdx.x, h = blockIdx.y, b = blockIdx.z;
    int kvh = h >> 2;
    int tid = threadIdx.x, lane = tid & 31, w = tid >> 5;
    int q0 = qt * 64;

    const __half* Qp = qq + ((size_t)(b * NH + h) * SEQ + q0) * 64;
    const __half* Kp = kk + ((size_t)(b * NKVH + kvh) * SEQ) * 64;
    const __half* Vp = vt + ((size_t)(b * NKVH + kvh) * 64) * SEQ;

    auto issue_kv = [&](int st, int kt) {
        int k0 = kt * 64;
        uint32_t base = smb + AT_KV + st * (2 * AT_MAT);
#pragma unroll
        for (int it = 0; it < 4; it++) {
            int idx = it * 128 + tid;
            int r = idx >> 3, ch = idx & 7;
            cpa16(base + r * AT_PITCH + ch * 16,            Kp + (size_t)(k0 + r) * 64 + ch * 8);
            cpa16(base + AT_MAT + r * AT_PITCH + ch * 16,   Vp + (size_t)r * SEQ + k0 + ch * 8);
        }
        cpa_commit();
    };

    // load Q
#pragma unroll
    for (int it = 0; it < 4; it++) {
        int idx = it * 128 + tid;
        int r = idx >> 3, ch = idx & 7;
        cpa16(smb + AT_Q + r * AT_PITCH + ch * 16, Qp + (size_t)r * 64 + ch * 8);
    }
    cpa_commit();
    asm volatile("cp.async.wait_group 0;" ::: "memory");
    __syncthreads();

    int r0 = lane >> 2, cq = lane & 3;
    int a_row = w * 16 + (lane & 15);
    int a_kb  = (lane >> 4) * 16;
    int b_ro  = ((lane >> 4) << 3) + (lane & 7);
    int b_kb  = ((lane >> 3) & 1) * 16;

    uint32_t qf[4][4];
#pragma unroll
    for (int kc = 0; kc < 4; kc++)
        ldsm4(qf[kc], smb + AT_Q + a_row * AT_PITCH + kc * 32 + a_kb);

    issue_kv(0, 0);

    float m0 = -1e30f, m1 = -1e30f, l0 = 0.f, l1 = 0.f;
    float ao[8][4];
#pragma unroll
    for (int nt = 0; nt < 8; nt++)
#pragma unroll
        for (int j = 0; j < 4; j++) ao[nt][j] = 0.f;

    for (int kt = 0; kt <= qt; kt++) {
        int st = kt & 1;
        asm volatile("cp.async.wait_group 0;" ::: "memory");
        __syncthreads();
        if (kt < qt) issue_kv((kt + 1) & 1, kt + 1);

        uint32_t sK = smb + AT_KV + st * (2 * AT_MAT);
        uint32_t sV = sK + AT_MAT;

        float sc[8][4];
#pragma unroll
        for (int nt = 0; nt < 8; nt++)
#pragma unroll
            for (int j = 0; j < 4; j++) sc[nt][j] = 0.f;

#pragma unroll
        for (int kc = 0; kc < 4; kc++) {
#pragma unroll
            for (int gi = 0; gi < 4; gi++) {
                uint32_t k4[4];
                ldsm4(k4, sK + (gi * 16 + b_ro) * AT_PITCH + kc * 32 + b_kb);
#pragma unroll
                for (int t = 0; t < 2; t++)
                    mma_f16(sc[gi * 2 + t], qf[kc], &k4[t * 2]);
            }
        }

        if (kt == qt) {
            int qr0 = w * 16 + r0, qr1 = qr0 + 8;
#pragma unroll
            for (int nt = 0; nt < 8; nt++) {
                int col = nt * 8 + cq * 2;
                if (col     > qr0) sc[nt][0] = -1e30f;
                if (col + 1 > qr0) sc[nt][1] = -1e30f;
                if (col     > qr1) sc[nt][2] = -1e30f;
                if (col + 1 > qr1) sc[nt][3] = -1e30f;
            }
        }

        float tm0 = -1e30f, tm1 = -1e30f;
#pragma unroll
        for (int nt = 0; nt < 8; nt++) {
            tm0 = fmaxf(tm0, fmaxf(sc[nt][0], sc[nt][1]));
            tm1 = fmaxf(tm1, fmaxf(sc[nt][2], sc[nt][3]));
        }
        tm0 = fmaxf(tm0, __shfl_xor_sync(0xffffffffu, tm0, 1));
        tm0 = fmaxf(tm0, __shfl_xor_sync(0xffffffffu, tm0, 2));
        tm1 = fmaxf(tm1, __shfl_xor_sync(0xffffffffu, tm1, 1));
        tm1 = fmaxf(tm1, __shfl_xor_sync(0xffffffffu, tm1, 2));
        float mn0 = fmaxf(m0, tm0), mn1 = fmaxf(m1, tm1);
        float cr0 = fexp2((m0 - mn0) * L2E);
        float cr1 = fexp2((m1 - mn1) * L2E);
        float rs0 = 0.f, rs1 = 0.f;
#pragma unroll
        for (int nt = 0; nt < 8; nt++) {
            sc[nt][0] = fexp2((sc[nt][0] - mn0) * L2E);
            sc[nt][1] = fexp2((sc[nt][1] - mn0) * L2E);
            sc[nt][2] = fexp2((sc[nt][2] - mn1) * L2E);
            sc[nt][3] = fexp2((sc[nt][3] - mn1) * L2E);
            rs0 += sc[nt][0] + sc[nt][1];
            rs1 += sc[nt][2] + sc[nt][3];
        }
        rs0 += __shfl_xor_sync(0xffffffffu, rs0, 1);
        rs0 += __shfl_xor_sync(0xffffffffu, rs0, 2);
        rs1 += __shfl_xor_sync(0xffffffffu, rs1, 1);
        rs1 += __shfl_xor_sync(0xffffffffu, rs1, 2);
        l0 = l0 * cr0 + rs0;
        l1 = l1 * cr1 + rs1;
        m0 = mn0; m1 = mn1;
#pragma unroll
        for (int nt = 0; nt < 8; nt++) {
            ao[nt][0] *= cr0; ao[nt][1] *= cr0;
            ao[nt][2] *= cr1; ao[nt][3] *= cr1;
        }

#pragma unroll
        for (int j = 0; j < 4; j++) {
            uint32_t pa[4];
#pragma unroll
            for (int u = 0; u < 2; u++) {
                __half2 H0 = __floats2half2_rn(sc[2 * j + u][0], sc[2 * j + u][1]);
                __half2 H1 = __floats2half2_rn(sc[2 * j + u][2], sc[2 * j + u][3]);
                pa[2 * u + 0] = *(uint32_t*)&H0;
                pa[2 * u + 1] = *(uint32_t*)&H1;
            }
#pragma unroll
            for (int gi = 0; gi < 4; gi++) {
                uint32_t v4[4];
                ldsm4(v4, sV + (gi * 16 + b_ro) * AT_PITCH + j * 32 + b_kb);
#pragma unroll
                for (int t = 0; t < 2; t++)
                    mma_f16(ao[gi * 2 + t], pa, &v4[t * 2]);
            }
        }
    }

    float i0 = 1.f / l0, i1 = 1.f / l1;
    int rowA = q0 + w * 16 + r0;
    int rowB = rowA + 8;
#pragma unroll
    for (int nt = 0; nt < 8; nt++) {
        int col = h * 64 + nt * 8 + cq * 2;
        size_t oA = ((size_t)(b * SEQ) + rowA) * 2048 + col;
        size_t oB = ((size_t)(b * SEQ) + rowB) * 2048 + col;
        *(__half2*)(OH + oA) = __floats2half2_rn(ao[nt][0] * i0, ao[nt][1] * i0);
        *(__half2*)(OH + oB) = __floats2half2_rn(ao[nt][2] * i1, ao[nt][3] * i1);
    }
}

// ---------------- host launch ----------------
extern "C" void kernel_launch(void* const* d_in, const int* in_sizes, int n_in,
                              void* d_out, int out_size)
{
    const float* hidden  = (const float*)d_in[0];
    const float* norm1_w = (const float*)d_in[2];
    const float* wq      = (const float*)d_in[3];
    const float* wk      = (const float*)d_in[4];
    const float* wv      = (const float*)d_in[5];
    const float* wo      = (const float*)d_in[6];
    const float* norm2_w = (const float*)d_in[7];
    const float* w_gate  = (const float*)d_in[8];
    const float* w_up    = (const float*)d_in[9];
    const float* w_down  = (const float*)d_in[10];
    float* out = (float*)d_out;

    float *res2, *qkv;
    __half *ab, *wpool, *qb, *kbuf, *vtb, *mbuf;
    cudaGetSymbolAddress((void**)&res2, g_res2);
    cudaGetSymbolAddress((void**)&qkv,  g_qkv);
    cudaGetSymbolAddress((void**)&mbuf, g_m);
    cudaGetSymbolAddress((void**)&ab,   g_a);
    cudaGetSymbolAddress((void**)&wpool, g_w);
    cudaGetSymbolAddress((void**)&qb,   g_q);
    cudaGetSymbolAddress((void**)&kbuf, g_k);
    cudaGetSymbolAddress((void**)&vtb,  g_vt);

    const size_t OQKV = 0;
    const size_t OWO  = 6ull * MEG;
    const size_t OGU  = 10ull * MEG;
    const size_t OWD  = 42ull * MEG;

    cudaFuncSetAttribute(hmma_gemm_kernel<0>, cudaFuncAttributeMaxDynamicSharedMemorySize, GSMEM);
    cudaFuncSetAttribute(hmma_gemm_kernel<1>, cudaFuncAttributeMaxDynamicSharedMemorySize, GSMEM);
    cudaFuncSetAttribute(hmma_gemm_kernel<4>, cudaFuncAttributeMaxDynamicSharedMemorySize, GSMEM);
    cudaFuncSetAttribute(attn_mma_kernel, cudaFuncAttributeMaxDynamicSharedMemorySize, AT_SMEM);

    // ---- weight conversions ----
    convT_kernel<<<dim3(32, 32), 256>>>(wq, wpool + OQKV, 2048, 2048);
    convT_kernel<<<dim3(8, 32), 256>>>(wk, wpool + OQKV + 2048ull * 2048, 2048, 512);
    convT_kernel<<<dim3(8, 32), 256>>>(wv, wpool + OQKV + 2560ull * 2048, 2048, 512);
    convT_kernel<<<dim3(32, 32), 256>>>(wo, wpool + OWO, 2048, 2048);
    convT_gu_kernel<<<dim3(128, 32), 256>>>(w_gate, w_up, wpool + OGU, 2048);
    convT_kernel<<<dim3(32, 128), 256>>>(w_down, wpool + OWD, 8192, 2048);

    // ---- 1. rmsnorm1 -> fp16 ----
    rmsnorm_h_kernel<<<ROWS, 256>>>(hidden, norm1_w, ab, HID);

    // ---- 2. fused QKV GEMM -> qkv fp32 ----
    hmma_gemm_kernel<0><<<dim3(3072 / 256, ROWS / 128), 256, GSMEM>>>(
        ab, wpool + OQKV, nullptr, qkv, nullptr, 3072, 2048);

    // ---- 3. RoPE Q/K + V transpose ----
    rope_q_kernel<<<ROWS, NH * 32>>>(qkv, qb);
    rope_k_kernel<<<ROWS, NKVH * 32>>>(qkv, kbuf);
    vt_kernel<<<dim3(SEQ / 32, 2, NB * NKVH), dim3(32, 8)>>>(qkv, vtb);

    // ---- 4. attention -> ctx fp16 (ab) ----
    attn_mma_kernel<<<dim3(SEQ / 64, NH, NB), 128, AT_SMEM>>>(qb, kbuf, vtb, ab);

    // ---- 5. output projection + residual -> res2 fp32 ----
    hmma_gemm_kernel<1><<<dim3(2048 / 256, ROWS / 128), 256, GSMEM>>>(
        ab, wpool + OWO, hidden, res2, nullptr, 2048, 2048);

    // ---- 6. rmsnorm2 -> fp16 ----
    rmsnorm_h_kernel<<<ROWS, 256>>>(res2, norm2_w, ab, HID);

    // ---- 7. fused gate+up GEMM + silu-mul -> fp16 (mbuf) ----
    hmma_gemm_kernel<4><<<dim3(2 * FF / 256, ROWS / 128), 256, GSMEM>>>(
        ab, wpool + OGU, nullptr, nullptr, mbuf, FF, 2048);

    // ---- 8. down projection + residual -> out ----
    hmma_gemm_kernel<1><<<dim3(2048 / 256, ROWS / 128), 256, GSMEM>>>(
        mbuf, wpool + OWD, res2, out, nullptr, 2048, 8192);
}